// round 4
// baseline (speedup 1.0000x reference)
#include <cuda_runtime.h>
#include <math.h>

#define T 1024
#define H 1280
#define NH 10
#define HD 128
#define EI 896
#define NEXP 64
#define TOPK 6
#define SHF 1792
#define NPAIR (T*TOPK)

// ---------------- device scratch ----------------
static __device__ float g_h1[T*H];
static __device__ float g_q[T*H];
static __device__ float g_k[T*H];
static __device__ float g_v[T*H];
static __device__ float g_scores[NH*T*T];
static __device__ float g_attnout[T*H];
static __device__ float g_hres[T*H];
static __device__ float g_h2[T*H];
static __device__ float g_sg[T*SHF];
static __device__ float g_su[T*SHF];
static __device__ float g_shared[T*H];
static __device__ float g_gpeT[(size_t)NEXP*H*EI];
static __device__ float g_upeT[(size_t)NEXP*H*EI];
static __device__ float g_dpeT[(size_t)NEXP*EI*H];
static __device__ float g_act[(size_t)(NPAIR+128)*EI];
static __device__ float g_pairout[(size_t)NPAIR*H];
static __device__ int   g_cnt[NEXP];
static __device__ int   g_off[NEXP];
static __device__ int   g_cur[NEXP];
static __device__ int   g_tokE[NPAIR];
static __device__ float g_tokW[NPAIR];
static __device__ int   g_pairTok[NPAIR];
static __device__ float g_pairW[NPAIR];
static __device__ int   g_pairPos[NPAIR];

// ---------------- helpers ----------------
__device__ __forceinline__ void mma_tf32(float4& c, const unsigned a[4], const unsigned b[2]) {
    asm volatile("mma.sync.aligned.m16n8k8.row.col.f32.tf32.tf32.f32 "
        "{%0,%1,%2,%3}, {%4,%5,%6,%7}, {%8,%9}, {%0,%1,%2,%3};"
        : "+f"(c.x), "+f"(c.y), "+f"(c.z), "+f"(c.w)
        : "r"(a[0]), "r"(a[1]), "r"(a[2]), "r"(a[3]), "r"(b[0]), "r"(b[1]));
}
__device__ __forceinline__ unsigned ldtf(const float* p) {
    unsigned r; asm("cvt.rna.tf32.f32 %0, %1;" : "=r"(r) : "f"(*p)); return r;
}
__device__ __forceinline__ void cp16(const void* smem, const void* gmem) {
    unsigned sa = (unsigned)__cvta_generic_to_shared(smem);
    asm volatile("cp.async.cg.shared.global [%0], [%1], 16;" :: "r"(sa), "l"(gmem));
}
#define CP_COMMIT asm volatile("cp.async.commit_group;")
#define CP_WAIT1  asm volatile("cp.async.wait_group 1;")

#define AST 20    // 16-k row stride (+4 pad): (20g+tig)%32 all-distinct
#define BST 72    // 64-n row stride (+8 pad): (8tig+g)%32 all-distinct

// ---------------- RMSNorm ----------------
__global__ void rms_kernel(const float* __restrict__ x, const float* __restrict__ w,
                           float* __restrict__ out) {
    int t = blockIdx.x;
    const float* xr = x + (long)t*H;
    __shared__ float red[256];
    float s = 0.f;
    for (int i = threadIdx.x; i < H; i += 256) { float v = xr[i]; s += v*v; }
    red[threadIdx.x] = s; __syncthreads();
    for (int k = 128; k > 0; k >>= 1) {
        if (threadIdx.x < k) red[threadIdx.x] += red[threadIdx.x + k];
        __syncthreads();
    }
    float r = rsqrtf(red[0]/(float)H + 1e-6f);
    for (int i = threadIdx.x; i < H; i += 256) out[(long)t*H + i] = w[i]*xr[i]*r;
}

// ---------------- tf32 GEMM v2: CTA 128x64, 128 thr, warp tile 64x32 ----------------
// 3-stage cp.async, BK=16, one barrier per k-iter. Frags rounded via cvt.rna.
// mode: 0 none, 1 causal block skip, 2 K capped at m0+128.
// If Bb != null: z in {0,1,2} selects (B,C)/(Bb,Cb)/(Bc,Cc); else batch via strides.
__global__ void __launch_bounds__(128)
gemm_tc(const float* __restrict__ A, int lda, long sA,
        const float* __restrict__ B, const float* __restrict__ Bb, const float* __restrict__ Bc,
        int ldb, long sB, int transB,
        float* __restrict__ C, float* __restrict__ Cb, float* __restrict__ Cc,
        int ldc, long sC,
        const float* __restrict__ res, long sR,
        int K, float alpha, int mode) {
    int m0 = blockIdx.y*128, n0 = blockIdx.x*64;
    if (mode == 1 && n0 >= m0 + 128) return;
    int bz = blockIdx.z;
    A += (long)bz*sA;
    if (Bb) {
        if (bz == 1) { B = Bb; C = Cb; }
        else if (bz == 2) { B = Bc; C = Cc; }
    } else {
        B += (long)bz*sB; C += (long)bz*sC; if (res) res += (long)bz*sR;
    }
    int Klim = (mode == 2) ? (m0 + 128 < K ? m0 + 128 : K) : K;

    __shared__ float As[3][128*AST];
    __shared__ float Bs[3][1280];
    int tid = threadIdx.x;
    int lane = tid & 31, warpId = tid >> 5;
    int g = lane >> 2, tig = lane & 3;
    int warp_m = (warpId & 1) * 64, warp_n = (warpId >> 1) * 32;
    float4 acc[4][4];
    #pragma unroll
    for (int i = 0; i < 4; i++)
        #pragma unroll
        for (int j = 0; j < 4; j++) acc[i][j] = make_float4(0.f,0.f,0.f,0.f);

#define G_LOAD(sidx, k0v) do { int _k0 = (k0v); if (_k0 < Klim) { \
    _Pragma("unroll") for (int i = 0; i < 4; i++) { int idx = tid + i*128; int r = idx >> 2, c4 = (idx & 3) << 2; \
        cp16(&As[sidx][r*AST + c4], &A[(long)(m0+r)*lda + _k0 + c4]); } \
    if (!transB) { \
        _Pragma("unroll") for (int i = 0; i < 2; i++) { int idx = tid + i*128; int r = idx >> 4, c4 = (idx & 15) << 2; \
            cp16(&Bs[sidx][r*BST + c4], &B[(long)(_k0+r)*ldb + n0 + c4]); } \
    } else { \
        _Pragma("unroll") for (int i = 0; i < 2; i++) { int idx = tid + i*128; int r = idx >> 2, c4 = (idx & 3) << 2; \
            cp16(&Bs[sidx][r*AST + c4], &B[(long)(n0+r)*ldb + _k0 + c4]); } \
    } } CP_COMMIT; } while(0)

    int nIter = Klim >> 4;
    G_LOAD(0, 0);
    G_LOAD(1, 16);
    int st = 0;
    for (int it = 0; it < nIter; it++) {
        CP_WAIT1;
        __syncthreads();
        #pragma unroll
        for (int kk = 0; kk < 16; kk += 8) {
            unsigned a[4][4], b[4][2];
            #pragma unroll
            for (int mi = 0; mi < 4; mi++) {
                const float* ap = &As[st][(warp_m + mi*16 + g)*AST + kk + tig];
                a[mi][0] = ldtf(ap);
                a[mi][1] = ldtf(ap + 8*AST);
                a[mi][2] = ldtf(ap + 4);
                a[mi][3] = ldtf(ap + 8*AST + 4);
            }
            if (!transB) {
                #pragma unroll
                for (int ni = 0; ni < 4; ni++) {
                    int col = warp_n + ni*8 + g;
                    b[ni][0] = ldtf(&Bs[st][(kk+tig)*BST + col]);
                    b[ni][1] = ldtf(&Bs[st][(kk+tig+4)*BST + col]);
                }
            } else {
                #pragma unroll
                for (int ni = 0; ni < 4; ni++) {
                    const float* bp = &Bs[st][(warp_n + ni*8 + g)*AST + kk + tig];
                    b[ni][0] = ldtf(bp);
                    b[ni][1] = ldtf(bp + 4);
                }
            }
            #pragma unroll
            for (int mi = 0; mi < 4; mi++)
                #pragma unroll
                for (int ni = 0; ni < 4; ni++) mma_tf32(acc[mi][ni], a[mi], b[ni]);
        }
        int wst = st + 2; if (wst >= 3) wst -= 3;
        G_LOAD(wst, (it + 2) << 4);
        if (++st == 3) st = 0;
    }
#undef G_LOAD
    #pragma unroll
    for (int mi = 0; mi < 4; mi++) {
        #pragma unroll
        for (int ni = 0; ni < 4; ni++) {
            int row = m0 + warp_m + mi*16 + g;
            int col = n0 + warp_n + ni*8 + 2*tig;
            float4 c = acc[mi][ni];
            float2 v0 = { alpha*c.x, alpha*c.y };
            float2 v1 = { alpha*c.z, alpha*c.w };
            if (res) {
                float2 r0 = *(const float2*)&res[(long)row*ldc + col];
                float2 r1 = *(const float2*)&res[(long)(row+8)*ldc + col];
                v0.x += r0.x; v0.y += r0.y; v1.x += r1.x; v1.y += r1.y;
            }
            *(float2*)&C[(long)row*ldc + col] = v0;
            *(float2*)&C[(long)(row+8)*ldc + col] = v1;
        }
    }
}

// ---------------- RoPE ----------------
__global__ void rope_kernel() {
    int t = blockIdx.x, tid = threadIdx.x;
    __shared__ float cs[64], sn[64];
    if (tid < 64) {
        float inv = powf(10000.0f, -(float)tid / 64.0f);
        float fr = (float)t * inv;
        cs[tid] = cosf(fr); sn[tid] = sinf(fr);
    }
    __syncthreads();
    for (int idx = tid; idx < NH*64; idx += 256) {
        int hh = idx >> 6, j = idx & 63;
        long b = (long)t*H + hh*HD;
        float c = cs[j], s = sn[j];
        float q1 = g_q[b+j], q2 = g_q[b+j+64];
        g_q[b+j]    = q1*c - q2*s;
        g_q[b+j+64] = q2*c + q1*s;
        float k1 = g_k[b+j], k2 = g_k[b+j+64];
        g_k[b+j]    = k1*c - k2*s;
        g_k[b+j+64] = k2*c + k1*s;
    }
}

// ---------------- causal softmax (zero to next 128-boundary to match PV K-cap) --------
__global__ void attn_softmax() {
    int t = blockIdx.x, hh = blockIdx.y, tid = threadIdx.x;
    float* row = g_scores + ((long)hh*T + t)*(long)T;
    int len = t + 1;
    int zend = ((t >> 7) + 1) << 7;
    __shared__ float red[256];
    float mx = -3.0e38f;
    for (int i = tid; i < len; i += 256) mx = fmaxf(mx, row[i]);
    red[tid] = mx; __syncthreads();
    for (int s = 128; s > 0; s >>= 1) { if (tid < s) red[tid] = fmaxf(red[tid], red[tid+s]); __syncthreads(); }
    mx = red[0]; __syncthreads();
    float sum = 0.f;
    for (int i = tid; i < len; i += 256) { float e = __expf(row[i]-mx); row[i] = e; sum += e; }
    red[tid] = sum; __syncthreads();
    for (int s = 128; s > 0; s >>= 1) { if (tid < s) red[tid] += red[tid+s]; __syncthreads(); }
    float inv = 1.0f / red[0];
    for (int i = tid; i < len; i += 256) row[i] *= inv;
    for (int i = len + tid; i < zend; i += 256) row[i] = 0.f;
}

// ---------------- expert-last transpose: in[R][C][64] -> out[64][R][C] ----------------
__global__ void transpose_e(const float* __restrict__ in, float* __restrict__ out, int R, int C) {
    int r = blockIdx.y;
    int c0 = blockIdx.x * 32;
    __shared__ float tile[64*33];
    const float* src = in + ((long)r*C + c0)*64;
    for (int i = threadIdx.x; i < 2048; i += 256) {
        int ci = i >> 6, e = i & 63;
        tile[e*33 + ci] = src[i];
    }
    __syncthreads();
    for (int i = threadIdx.x; i < 2048; i += 256) {
        int e = i >> 5, ci = i & 31;
        out[(long)e*R*C + (long)r*C + c0 + ci] = tile[e*33 + ci];
    }
}

// ---------------- router ----------------
__global__ void zero_cnt_kernel() { if (threadIdx.x < NEXP) g_cnt[threadIdx.x] = 0; }

__global__ void router_kernel(const float* __restrict__ gw) {
    int t = blockIdx.x, e = threadIdx.x;
    const float* hr = g_h2 + (long)t*H;
    float s = 0.f;
    for (int h = 0; h < H; h++) s += hr[h] * gw[h*NEXP + e];
    __shared__ float probs[NEXP];
    probs[e] = s;
    __syncthreads();
    if (e == 0) {
        float mx = -3e38f;
        for (int i = 0; i < NEXP; i++) mx = fmaxf(mx, probs[i]);
        float sum = 0.f;
        for (int i = 0; i < NEXP; i++) { probs[i] = __expf(probs[i]-mx); sum += probs[i]; }
        float inv = 1.f/sum;
        for (int i = 0; i < NEXP; i++) probs[i] *= inv;
        int ti[TOPK]; float tw[TOPK]; float ws = 0.f;
        for (int j = 0; j < TOPK; j++) {
            int bi = 0; float bv = -1.f;
            for (int i = 0; i < NEXP; i++) if (probs[i] > bv) { bv = probs[i]; bi = i; }
            ti[j] = bi; tw[j] = bv; ws += bv; probs[bi] = -2.f;
        }
        float wi = 1.f/ws;
        for (int j = 0; j < TOPK; j++) {
            g_tokE[t*TOPK+j] = ti[j];
            g_tokW[t*TOPK+j] = tw[j]*wi;
            atomicAdd(&g_cnt[ti[j]], 1);
        }
    }
}

__global__ void prefix_kernel() {
    if (threadIdx.x == 0) {
        int s = 0;
        for (int e = 0; e < NEXP; e++) { g_off[e] = s; g_cur[e] = s; s += g_cnt[e]; }
    }
}

__global__ void scatter_kernel() {
    int i = blockIdx.x*256 + threadIdx.x;
    if (i < NPAIR) {
        int e = g_tokE[i];
        int pos = atomicAdd(&g_cur[e], 1);
        g_pairTok[pos] = i / TOPK;
        g_pairW[pos]   = g_tokW[i];
        g_pairPos[i]   = pos;
    }
}

// ---------------- MoE pass 1: CTA 128x64, 256 thr, warp 32x32, dual-B, 2-stage -------
__global__ void __launch_bounds__(256) moe_pass1() {
    int e = blockIdx.z;
    int cnt = g_cnt[e];
    int m0 = blockIdx.y * 128;
    if (m0 >= cnt) return;
    int n0 = blockIdx.x * 64;
    int base = g_off[e];
    const float* Bg = g_gpeT + (size_t)e*H*EI;
    const float* Bu = g_upeT + (size_t)e*H*EI;
    __shared__ int stok[128];
    __shared__ float As[2][128*AST];
    __shared__ float Bs1[2][16*BST];
    __shared__ float Bs2[2][16*BST];
    int tid = threadIdx.x;
    int lane = tid & 31, warpId = tid >> 5;
    int g = lane >> 2, tig = lane & 3;
    int warp_m = (warpId & 3) * 32, warp_n = (warpId >> 2) * 32;
    if (tid < 128) stok[tid] = (m0 + tid < cnt) ? g_pairTok[base + m0 + tid] : 0;
    __syncthreads();
    float4 accG[2][4], accU[2][4];
    #pragma unroll
    for (int i = 0; i < 2; i++)
        #pragma unroll
        for (int j = 0; j < 4; j++) { accG[i][j] = make_float4(0,0,0,0); accU[i][j] = make_float4(0,0,0,0); }

#define P1_LOAD(sidx, k0v) do { int _k0 = (k0v); if (_k0 < H) { \
    _Pragma("unroll") for (int i = 0; i < 2; i++) { int idx = tid + i*256; int r = idx >> 2, c4 = (idx & 3) << 2; \
        cp16(&As[sidx][r*AST + c4], &g_h2[(long)stok[r]*H + _k0 + c4]); } \
    { int r = tid >> 4, c4 = (tid & 15) << 2; \
        cp16(&Bs1[sidx][r*BST + c4], &Bg[(long)(_k0+r)*EI + n0 + c4]); \
        cp16(&Bs2[sidx][r*BST + c4], &Bu[(long)(_k0+r)*EI + n0 + c4]); } \
    } CP_COMMIT; } while(0)

    P1_LOAD(0, 0);
    const int nIter = H / 16;
    for (int it = 0; it < nIter; it++) {
        int s = it & 1;
        P1_LOAD(s ^ 1, (it + 1) << 4);
        CP_WAIT1;
        __syncthreads();
        #pragma unroll
        for (int kk = 0; kk < 16; kk += 8) {
            unsigned a[2][4], b1[4][2], b2[4][2];
            #pragma unroll
            for (int mi = 0; mi < 2; mi++) {
                const float* ap = &As[s][(warp_m + mi*16 + g)*AST + kk + tig];
                a[mi][0] = ldtf(ap);
                a[mi][1] = ldtf(ap + 8*AST);
                a[mi][2] = ldtf(ap + 4);
                a[mi][3] = ldtf(ap + 8*AST + 4);
            }
            #pragma unroll
            for (int ni = 0; ni < 4; ni++) {
                int col = warp_n + ni*8 + g;
                b1[ni][0] = ldtf(&Bs1[s][(kk+tig)*BST + col]);
                b1[ni][1] = ldtf(&Bs1[s][(kk+tig+4)*BST + col]);
                b2[ni][0] = ldtf(&Bs2[s][(kk+tig)*BST + col]);
                b2[ni][1] = ldtf(&Bs2[s][(kk+tig+4)*BST + col]);
            }
            #pragma unroll
            for (int mi = 0; mi < 2; mi++)
                #pragma unroll
                for (int ni = 0; ni < 4; ni++) {
                    mma_tf32(accG[mi][ni], a[mi], b1[ni]);
                    mma_tf32(accU[mi][ni], a[mi], b2[ni]);
                }
        }
        __syncthreads();
    }
#undef P1_LOAD
    #pragma unroll
    for (int mi = 0; mi < 2; mi++) {
        #pragma unroll
        for (int ni = 0; ni < 4; ni++) {
            int mrow = warp_m + mi*16 + g;
            int col = n0 + warp_n + ni*8 + 2*tig;
            float4 cg = accG[mi][ni], cu = accU[mi][ni];
            if (m0 + mrow < cnt) {
                float g0 = cg.x, g1 = cg.y;
                float2 v = { (g0/(1.f+__expf(-g0)))*cu.x, (g1/(1.f+__expf(-g1)))*cu.y };
                *(float2*)&g_act[(long)(base+m0+mrow)*EI + col] = v;
            }
            if (m0 + mrow + 8 < cnt) {
                float g0 = cg.z, g1 = cg.w;
                float2 v = { (g0/(1.f+__expf(-g0)))*cu.z, (g1/(1.f+__expf(-g1)))*cu.w };
                *(float2*)&g_act[(long)(base+m0+mrow+8)*EI + col] = v;
            }
        }
    }
}

// ---------------- MoE pass 2: CTA 128x64, 128 thr, warp 64x32, 3-stage ----------------
__global__ void __launch_bounds__(128) moe_pass2() {
    int e = blockIdx.z;
    int cnt = g_cnt[e];
    int m0 = blockIdx.y * 128;
    if (m0 >= cnt) return;
    int n0 = blockIdx.x * 64;
    int base = g_off[e];
    const float* Bm = g_dpeT + (size_t)e*EI*H;
    __shared__ float As[3][128*AST];
    __shared__ float Bs[3][16*BST];
    int tid = threadIdx.x;
    int lane = tid & 31, warpId = tid >> 5;
    int g = lane >> 2, tig = lane & 3;
    int warp_m = (warpId & 1) * 64, warp_n = (warpId >> 1) * 32;
    float4 acc[4][4];
    #pragma unroll
    for (int i = 0; i < 4; i++)
        #pragma unroll
        for (int j = 0; j < 4; j++) acc[i][j] = make_float4(0,0,0,0);

#define P2_LOAD(sidx, k0v) do { int _k0 = (k0v); if (_k0 < EI) { \
    _Pragma("unroll") for (int i = 0; i < 4; i++) { int idx = tid + i*128; int r = idx >> 2, c4 = (idx & 3) << 2; \
        int rr = m0 + r; if (rr >= cnt) rr = cnt - 1; \
        cp16(&As[sidx][r*AST + c4], &g_act[(long)(base+rr)*EI + _k0 + c4]); } \
    _Pragma("unroll") for (int i = 0; i < 2; i++) { int idx = tid + i*128; int r = idx >> 4, c4 = (idx & 15) << 2; \
        cp16(&Bs[sidx][r*BST + c4], &Bm[(long)(_k0+r)*H + n0 + c4]); } \
    } CP_COMMIT; } while(0)

    const int nIter = EI / 16;
    P2_LOAD(0, 0);
    P2_LOAD(1, 16);
    int st = 0;
    for (int it = 0; it < nIter; it++) {
        CP_WAIT1;
        __syncthreads();
        #pragma unroll
        for (int kk = 0; kk < 16; kk += 8) {
            unsigned a[4][4], b[4][2];
            #pragma unroll
            for (int mi = 0; mi < 4; mi++) {
                const float* ap = &As[st][(warp_m + mi*16 + g)*AST + kk + tig];
                a[mi][0] = ldtf(ap);
                a[mi][1] = ldtf(ap + 8*AST);
                a[mi][2] = ldtf(ap + 4);
                a[mi][3] = ldtf(ap + 8*AST + 4);
            }
            #pragma unroll
            for (int ni = 0; ni < 4; ni++) {
                int col = warp_n + ni*8 + g;
                b[ni][0] = ldtf(&Bs[st][(kk+tig)*BST + col]);
                b[ni][1] = ldtf(&Bs[st][(kk+tig+4)*BST + col]);
            }
            #pragma unroll
            for (int mi = 0; mi < 4; mi++)
                #pragma unroll
                for (int ni = 0; ni < 4; ni++) mma_tf32(acc[mi][ni], a[mi], b[ni]);
        }
        int wst = st + 2; if (wst >= 3) wst -= 3;
        P2_LOAD(wst, (it + 2) << 4);
        if (++st == 3) st = 0;
    }
#undef P2_LOAD
    #pragma unroll
    for (int mi = 0; mi < 4; mi++) {
        #pragma unroll
        for (int ni = 0; ni < 4; ni++) {
            int mrow = warp_m + mi*16 + g;
            int col = n0 + warp_n + ni*8 + 2*tig;
            float4 c = acc[mi][ni];
            if (m0 + mrow < cnt)
                *(float2*)&g_pairout[(long)(base+m0+mrow)*H + col] = make_float2(c.x, c.y);
            if (m0 + mrow + 8 < cnt)
                *(float2*)&g_pairout[(long)(base+m0+mrow+8)*H + col] = make_float2(c.z, c.w);
        }
    }
}

// ---------------- shared-FFN activation ----------------
__global__ void silumul_kernel(float* __restrict__ g, const float* __restrict__ u, int n) {
    int i = blockIdx.x*256 + threadIdx.x;
    if (i < n) {
        float x = g[i];
        g[i] = (x / (1.f + __expf(-x))) * u[i];
    }
}

// ---------------- final combine ----------------
__global__ void combine_kernel(float* __restrict__ out) {
    int t = blockIdx.x;
    int pos[TOPK]; float w[TOPK];
    #pragma unroll
    for (int j = 0; j < TOPK; j++) {
        pos[j] = g_pairPos[t*TOPK + j];
        w[j]   = g_pairW[pos[j]];
    }
    for (int h = threadIdx.x; h < H; h += 256) {
        float s = g_hres[(long)t*H + h] + g_shared[(long)t*H + h];
        #pragma unroll
        for (int j = 0; j < TOPK; j++)
            s += w[j] * g_pairout[(long)pos[j]*H + h];
        out[(long)t*H + h] = s;
    }
}

// ---------------- launch ----------------
extern "C" void kernel_launch(void* const* d_in, const int* in_sizes, int n_in,
                              void* d_out, int out_size) {
    (void)in_sizes; (void)n_in; (void)out_size;
    const float* x       = (const float*)d_in[0];
    const float* ln1     = (const float*)d_in[1];
    const float* ln2     = (const float*)d_in[2];
    const float* Wq      = (const float*)d_in[3];
    const float* Wk      = (const float*)d_in[4];
    const float* Wv      = (const float*)d_in[5];
    const float* Wo      = (const float*)d_in[6];
    const float* gate_w  = (const float*)d_in[7];
    const float* gpe     = (const float*)d_in[8];
    const float* upe     = (const float*)d_in[9];
    const float* dpe     = (const float*)d_in[10];
    const float* sh_gate = (const float*)d_in[11];
    const float* sh_up   = (const float*)d_in[12];
    const float* sh_down = (const float*)d_in[13];
    float* out = (float*)d_out;

    float *h1p,*qp,*kp,*vp,*scoresp,*attnp,*hresp,*h2p,*sgp,*sup,*sharedp,*gpeTp,*upeTp,*dpeTp;
    cudaGetSymbolAddress((void**)&h1p,     g_h1);
    cudaGetSymbolAddress((void**)&qp,      g_q);
    cudaGetSymbolAddress((void**)&kp,      g_k);
    cudaGetSymbolAddress((void**)&vp,      g_v);
    cudaGetSymbolAddress((void**)&scoresp, g_scores);
    cudaGetSymbolAddress((void**)&attnp,   g_attnout);
    cudaGetSymbolAddress((void**)&hresp,   g_hres);
    cudaGetSymbolAddress((void**)&h2p,     g_h2);
    cudaGetSymbolAddress((void**)&sgp,     g_sg);
    cudaGetSymbolAddress((void**)&sup,     g_su);
    cudaGetSymbolAddress((void**)&sharedp, g_shared);
    cudaGetSymbolAddress((void**)&gpeTp,   g_gpeT);
    cudaGetSymbolAddress((void**)&upeTp,   g_upeT);
    cudaGetSymbolAddress((void**)&dpeTp,   g_dpeT);

    const float inv_sqrt_hd = 0.08838834764831845f;

    // attention branch
    rms_kernel<<<T, 256>>>(x, ln1, h1p);
    gemm_tc<<<dim3(H/64, T/128, 3), 128>>>(h1p, H, 0, Wq, Wk, Wv, H, 0, 0,
                                           qp, kp, vp, H, 0, nullptr, 0,
                                           H, 1.f, 0);
    rope_kernel<<<T, 256>>>();
    gemm_tc<<<dim3(T/64, T/128, NH), 128>>>(qp, H, HD, kp, nullptr, nullptr, H, HD, 1,
                                            scoresp, nullptr, nullptr, T, (long)T*T, nullptr, 0,
                                            HD, inv_sqrt_hd, 1);
    attn_softmax<<<dim3(T, NH), 256>>>();
    gemm_tc<<<dim3(HD/64, T/128, NH), 128>>>(scoresp, T, (long)T*T, vp, nullptr, nullptr, H, HD, 0,
                                             attnp, nullptr, nullptr, H, HD, nullptr, 0,
                                             T, 1.f, 2);
    gemm_tc<<<dim3(H/64, T/128, 1), 128>>>(attnp, H, 0, Wo, nullptr, nullptr, H, 0, 0,
                                           hresp, nullptr, nullptr, H, 0, x, 0,
                                           H, 1.f, 0);

    // MoE branch
    rms_kernel<<<T, 256>>>(hresp, ln2, h2p);
    transpose_e<<<dim3(EI/32, H), 256>>>(gpe, gpeTp, H, EI);
    transpose_e<<<dim3(EI/32, H), 256>>>(upe, upeTp, H, EI);
    transpose_e<<<dim3(H/32, EI), 256>>>(dpe, dpeTp, EI, H);
    zero_cnt_kernel<<<1, 64>>>();
    router_kernel<<<T, 64>>>(gate_w);
    prefix_kernel<<<1, 32>>>();
    scatter_kernel<<<(NPAIR + 255)/256, 256>>>();
    moe_pass1<<<dim3(EI/64, T/128, NEXP), 256>>>();
    moe_pass2<<<dim3(H/64, T/128, NEXP), 128>>>();

    // shared FFN
    gemm_tc<<<dim3(SHF/64, T/128, 2), 128>>>(h2p, H, 0, sh_gate, sh_up, nullptr, SHF, 0, 0,
                                             sgp, sup, nullptr, SHF, 0, nullptr, 0,
                                             H, 1.f, 0);
    silumul_kernel<<<(T*SHF + 255)/256, 256>>>(sgp, sup, T*SHF);
    gemm_tc<<<dim3(H/64, T/128, 1), 128>>>(sgp, SHF, 0, sh_down, nullptr, nullptr, H, 0, 0,
                                           sharedp, nullptr, nullptr, H, 0, nullptr, 0,
                                           SHF, 1.f, 0);

    // combine
    combine_kernel<<<T, 256>>>(out);
}

// round 5
// speedup vs baseline: 1.0090x; 1.0090x over previous
#include <cuda_runtime.h>
#include <math.h>

#define T 1024
#define H 1280
#define NH 10
#define HD 128
#define EI 896
#define NEXP 64
#define TOPK 6
#define SHF 1792
#define NPAIR (T*TOPK)

// ---------------- device scratch ----------------
static __device__ float g_h1[T*H];
static __device__ float g_q[T*H];
static __device__ float g_k[T*H];
static __device__ float g_v[T*H];
static __device__ float g_scores[NH*T*T];
static __device__ float g_attnout[T*H];
static __device__ float g_hres[T*H];
static __device__ float g_h2[T*H];
static __device__ float g_sg[T*SHF];
static __device__ float g_su[T*SHF];
static __device__ float g_shared[T*H];
static __device__ float g_gpeT[(size_t)NEXP*H*EI];
static __device__ float g_upeT[(size_t)NEXP*H*EI];
static __device__ float g_dpeT[(size_t)NEXP*EI*H];
static __device__ float g_act[(size_t)(NPAIR+128)*EI];
static __device__ float g_pairout[(size_t)NPAIR*H];
static __device__ int   g_cnt[NEXP];
static __device__ int   g_off[NEXP];
static __device__ int   g_cur[NEXP];
static __device__ int   g_tokE[NPAIR];
static __device__ float g_tokW[NPAIR];
static __device__ int   g_pairTok[NPAIR];
static __device__ float g_pairW[NPAIR];
static __device__ int   g_pairPos[NPAIR];

// ---------------- helpers ----------------
__device__ __forceinline__ void mma_tf32(float4& c, const unsigned a[4], const unsigned b[2]) {
    asm volatile("mma.sync.aligned.m16n8k8.row.col.f32.tf32.tf32.f32 "
        "{%0,%1,%2,%3}, {%4,%5,%6,%7}, {%8,%9}, {%0,%1,%2,%3};"
        : "+f"(c.x), "+f"(c.y), "+f"(c.z), "+f"(c.w)
        : "r"(a[0]), "r"(a[1]), "r"(a[2]), "r"(a[3]), "r"(b[0]), "r"(b[1]));
}
__device__ __forceinline__ unsigned ldtf(const float* p) {
    unsigned r; asm("cvt.rna.tf32.f32 %0, %1;" : "=r"(r) : "f"(*p)); return r;
}
__device__ __forceinline__ void cp16(const void* smem, const void* gmem) {
    unsigned sa = (unsigned)__cvta_generic_to_shared(smem);
    asm volatile("cp.async.cg.shared.global [%0], [%1], 16;" :: "r"(sa), "l"(gmem));
}
#define CP_COMMIT asm volatile("cp.async.commit_group;")
#define CP_WAIT1  asm volatile("cp.async.wait_group 1;")

#define AST 20    // 16-k row stride (+4 pad): (20g+tig)%32 all-distinct
#define BST 72    // 64-n row stride (+8 pad): (8tig+g)%32 all-distinct

// ---------------- RMSNorm ----------------
__global__ void rms_kernel(const float* __restrict__ x, const float* __restrict__ w,
                           float* __restrict__ out) {
    int t = blockIdx.x;
    const float* xr = x + (long)t*H;
    __shared__ float red[256];
    float s = 0.f;
    for (int i = threadIdx.x; i < H; i += 256) { float v = xr[i]; s += v*v; }
    red[threadIdx.x] = s; __syncthreads();
    for (int k = 128; k > 0; k >>= 1) {
        if (threadIdx.x < k) red[threadIdx.x] += red[threadIdx.x + k];
        __syncthreads();
    }
    float r = rsqrtf(red[0]/(float)H + 1e-6f);
    for (int i = threadIdx.x; i < H; i += 256) out[(long)t*H + i] = w[i]*xr[i]*r;
}

// ---------------- tf32 GEMM v2: CTA 128x64, 128 thr, warp tile 64x32 ----------------
// 3-stage cp.async, BK=16, one barrier per k-iter. Frags rounded via cvt.rna.
// mode: 0 none, 1 causal block skip, 2 K capped at m0+128.
// If Bb != null: z in {0,1,2} selects (B,C)/(Bb,Cb)/(Bc,Cc); else batch via strides.
__global__ void __launch_bounds__(128)
gemm_tc(const float* __restrict__ A, int lda, long sA,
        const float* __restrict__ B, const float* __restrict__ Bb, const float* __restrict__ Bc,
        int ldb, long sB, int transB,
        float* __restrict__ C, float* __restrict__ Cb, float* __restrict__ Cc,
        int ldc, long sC,
        const float* __restrict__ res, long sR,
        int K, float alpha, int mode) {
    int m0 = blockIdx.y*128, n0 = blockIdx.x*64;
    if (mode == 1 && n0 >= m0 + 128) return;
    int bz = blockIdx.z;
    A += (long)bz*sA;
    if (Bb) {
        if (bz == 1) { B = Bb; C = Cb; }
        else if (bz == 2) { B = Bc; C = Cc; }
    } else {
        B += (long)bz*sB; C += (long)bz*sC; if (res) res += (long)bz*sR;
    }
    int Klim = (mode == 2) ? (m0 + 128 < K ? m0 + 128 : K) : K;

    __shared__ float As[3][128*AST];
    __shared__ float Bs[3][1280];
    int tid = threadIdx.x;
    int lane = tid & 31, warpId = tid >> 5;
    int g = lane >> 2, tig = lane & 3;
    int warp_m = (warpId & 1) * 64, warp_n = (warpId >> 1) * 32;
    float4 acc[4][4];
    #pragma unroll
    for (int i = 0; i < 4; i++)
        #pragma unroll
        for (int j = 0; j < 4; j++) acc[i][j] = make_float4(0.f,0.f,0.f,0.f);

#define G_LOAD(sidx, k0v) do { int _k0 = (k0v); if (_k0 < Klim) { \
    _Pragma("unroll") for (int i = 0; i < 4; i++) { int idx = tid + i*128; int r = idx >> 2, c4 = (idx & 3) << 2; \
        cp16(&As[sidx][r*AST + c4], &A[(long)(m0+r)*lda + _k0 + c4]); } \
    if (!transB) { \
        _Pragma("unroll") for (int i = 0; i < 2; i++) { int idx = tid + i*128; int r = idx >> 4, c4 = (idx & 15) << 2; \
            cp16(&Bs[sidx][r*BST + c4], &B[(long)(_k0+r)*ldb + n0 + c4]); } \
    } else { \
        _Pragma("unroll") for (int i = 0; i < 2; i++) { int idx = tid + i*128; int r = idx >> 2, c4 = (idx & 3) << 2; \
            cp16(&Bs[sidx][r*AST + c4], &B[(long)(n0+r)*ldb + _k0 + c4]); } \
    } } CP_COMMIT; } while(0)

    int nIter = Klim >> 4;
    G_LOAD(0, 0);
    G_LOAD(1, 16);
    int st = 0;
    for (int it = 0; it < nIter; it++) {
        CP_WAIT1;
        __syncthreads();
        #pragma unroll
        for (int kk = 0; kk < 16; kk += 8) {
            unsigned a[4][4], b[4][2];
            #pragma unroll
            for (int mi = 0; mi < 4; mi++) {
                const float* ap = &As[st][(warp_m + mi*16 + g)*AST + kk + tig];
                a[mi][0] = ldtf(ap);
                a[mi][1] = ldtf(ap + 8*AST);
                a[mi][2] = ldtf(ap + 4);
                a[mi][3] = ldtf(ap + 8*AST + 4);
            }
            if (!transB) {
                #pragma unroll
                for (int ni = 0; ni < 4; ni++) {
                    int col = warp_n + ni*8 + g;
                    b[ni][0] = ldtf(&Bs[st][(kk+tig)*BST + col]);
                    b[ni][1] = ldtf(&Bs[st][(kk+tig+4)*BST + col]);
                }
            } else {
                #pragma unroll
                for (int ni = 0; ni < 4; ni++) {
                    const float* bp = &Bs[st][(warp_n + ni*8 + g)*AST + kk + tig];
                    b[ni][0] = ldtf(bp);
                    b[ni][1] = ldtf(bp + 4);
                }
            }
            #pragma unroll
            for (int mi = 0; mi < 4; mi++)
                #pragma unroll
                for (int ni = 0; ni < 4; ni++) mma_tf32(acc[mi][ni], a[mi], b[ni]);
        }
        int wst = st + 2; if (wst >= 3) wst -= 3;
        G_LOAD(wst, (it + 2) << 4);
        if (++st == 3) st = 0;
    }
#undef G_LOAD
    #pragma unroll
    for (int mi = 0; mi < 4; mi++) {
        #pragma unroll
        for (int ni = 0; ni < 4; ni++) {
            int row = m0 + warp_m + mi*16 + g;
            int col = n0 + warp_n + ni*8 + 2*tig;
            float4 c = acc[mi][ni];
            float2 v0 = { alpha*c.x, alpha*c.y };
            float2 v1 = { alpha*c.z, alpha*c.w };
            if (res) {
                float2 r0 = *(const float2*)&res[(long)row*ldc + col];
                float2 r1 = *(const float2*)&res[(long)(row+8)*ldc + col];
                v0.x += r0.x; v0.y += r0.y; v1.x += r1.x; v1.y += r1.y;
            }
            *(float2*)&C[(long)row*ldc + col] = v0;
            *(float2*)&C[(long)(row+8)*ldc + col] = v1;
        }
    }
}

// ---------------- RoPE ----------------
__global__ void rope_kernel() {
    int t = blockIdx.x, tid = threadIdx.x;
    __shared__ float cs[64], sn[64];
    if (tid < 64) {
        float inv = powf(10000.0f, -(float)tid / 64.0f);
        float fr = (float)t * inv;
        cs[tid] = cosf(fr); sn[tid] = sinf(fr);
    }
    __syncthreads();
    for (int idx = tid; idx < NH*64; idx += 256) {
        int hh = idx >> 6, j = idx & 63;
        long b = (long)t*H + hh*HD;
        float c = cs[j], s = sn[j];
        float q1 = g_q[b+j], q2 = g_q[b+j+64];
        g_q[b+j]    = q1*c - q2*s;
        g_q[b+j+64] = q2*c + q1*s;
        float k1 = g_k[b+j], k2 = g_k[b+j+64];
        g_k[b+j]    = k1*c - k2*s;
        g_k[b+j+64] = k2*c + k1*s;
    }
}

// ---------------- causal softmax (zero to next 128-boundary to match PV K-cap) --------
__global__ void attn_softmax() {
    int t = blockIdx.x, hh = blockIdx.y, tid = threadIdx.x;
    float* row = g_scores + ((long)hh*T + t)*(long)T;
    int len = t + 1;
    int zend = ((t >> 7) + 1) << 7;
    __shared__ float red[256];
    float mx = -3.0e38f;
    for (int i = tid; i < len; i += 256) mx = fmaxf(mx, row[i]);
    red[tid] = mx; __syncthreads();
    for (int s = 128; s > 0; s >>= 1) { if (tid < s) red[tid] = fmaxf(red[tid], red[tid+s]); __syncthreads(); }
    mx = red[0]; __syncthreads();
    float sum = 0.f;
    for (int i = tid; i < len; i += 256) { float e = __expf(row[i]-mx); row[i] = e; sum += e; }
    red[tid] = sum; __syncthreads();
    for (int s = 128; s > 0; s >>= 1) { if (tid < s) red[tid] += red[tid+s]; __syncthreads(); }
    float inv = 1.0f / red[0];
    for (int i = tid; i < len; i += 256) row[i] *= inv;
    for (int i = len + tid; i < zend; i += 256) row[i] = 0.f;
}

// ---------------- expert-last transpose: in[R][C][64] -> out[64][R][C] ----------------
__global__ void transpose_e(const float* __restrict__ in, float* __restrict__ out, int R, int C) {
    int r = blockIdx.y;
    int c0 = blockIdx.x * 32;
    __shared__ float tile[64*33];
    const float* src = in + ((long)r*C + c0)*64;
    for (int i = threadIdx.x; i < 2048; i += 256) {
        int ci = i >> 6, e = i & 63;
        tile[e*33 + ci] = src[i];
    }
    __syncthreads();
    for (int i = threadIdx.x; i < 2048; i += 256) {
        int e = i >> 5, ci = i & 31;
        out[(long)e*R*C + (long)r*C + c0 + ci] = tile[e*33 + ci];
    }
}

// ---------------- router ----------------
__global__ void zero_cnt_kernel() { if (threadIdx.x < NEXP) g_cnt[threadIdx.x] = 0; }

__global__ void router_kernel(const float* __restrict__ gw) {
    int t = blockIdx.x, e = threadIdx.x;
    const float* hr = g_h2 + (long)t*H;
    float s = 0.f;
    for (int h = 0; h < H; h++) s += hr[h] * gw[h*NEXP + e];
    __shared__ float probs[NEXP];
    probs[e] = s;
    __syncthreads();
    if (e == 0) {
        float mx = -3e38f;
        for (int i = 0; i < NEXP; i++) mx = fmaxf(mx, probs[i]);
        float sum = 0.f;
        for (int i = 0; i < NEXP; i++) { probs[i] = __expf(probs[i]-mx); sum += probs[i]; }
        float inv = 1.f/sum;
        for (int i = 0; i < NEXP; i++) probs[i] *= inv;
        int ti[TOPK]; float tw[TOPK]; float ws = 0.f;
        for (int j = 0; j < TOPK; j++) {
            int bi = 0; float bv = -1.f;
            for (int i = 0; i < NEXP; i++) if (probs[i] > bv) { bv = probs[i]; bi = i; }
            ti[j] = bi; tw[j] = bv; ws += bv; probs[bi] = -2.f;
        }
        float wi = 1.f/ws;
        for (int j = 0; j < TOPK; j++) {
            g_tokE[t*TOPK+j] = ti[j];
            g_tokW[t*TOPK+j] = tw[j]*wi;
            atomicAdd(&g_cnt[ti[j]], 1);
        }
    }
}

__global__ void prefix_kernel() {
    if (threadIdx.x == 0) {
        int s = 0;
        for (int e = 0; e < NEXP; e++) { g_off[e] = s; g_cur[e] = s; s += g_cnt[e]; }
    }
}

__global__ void scatter_kernel() {
    int i = blockIdx.x*256 + threadIdx.x;
    if (i < NPAIR) {
        int e = g_tokE[i];
        int pos = atomicAdd(&g_cur[e], 1);
        g_pairTok[pos] = i / TOPK;
        g_pairW[pos]   = g_tokW[i];
        g_pairPos[i]   = pos;
    }
}

// ---------------- MoE pass 1: CTA 128x64, 256 thr, warp 32x32, dual-B, 2-stage -------
__global__ void __launch_bounds__(256) moe_pass1() {
    int e = blockIdx.z;
    int cnt = g_cnt[e];
    int m0 = blockIdx.y * 128;
    if (m0 >= cnt) return;
    int n0 = blockIdx.x * 64;
    int base = g_off[e];
    const float* Bg = g_gpeT + (size_t)e*H*EI;
    const float* Bu = g_upeT + (size_t)e*H*EI;
    __shared__ int stok[128];
    __shared__ float As[2][128*AST];
    __shared__ float Bs1[2][16*BST];
    __shared__ float Bs2[2][16*BST];
    int tid = threadIdx.x;
    int lane = tid & 31, warpId = tid >> 5;
    int g = lane >> 2, tig = lane & 3;
    int warp_m = (warpId & 3) * 32, warp_n = (warpId >> 2) * 32;
    if (tid < 128) stok[tid] = (m0 + tid < cnt) ? g_pairTok[base + m0 + tid] : 0;
    __syncthreads();
    float4 accG[2][4], accU[2][4];
    #pragma unroll
    for (int i = 0; i < 2; i++)
        #pragma unroll
        for (int j = 0; j < 4; j++) { accG[i][j] = make_float4(0,0,0,0); accU[i][j] = make_float4(0,0,0,0); }

#define P1_LOAD(sidx, k0v) do { int _k0 = (k0v); if (_k0 < H) { \
    _Pragma("unroll") for (int i = 0; i < 2; i++) { int idx = tid + i*256; int r = idx >> 2, c4 = (idx & 3) << 2; \
        cp16(&As[sidx][r*AST + c4], &g_h2[(long)stok[r]*H + _k0 + c4]); } \
    { int r = tid >> 4, c4 = (tid & 15) << 2; \
        cp16(&Bs1[sidx][r*BST + c4], &Bg[(long)(_k0+r)*EI + n0 + c4]); \
        cp16(&Bs2[sidx][r*BST + c4], &Bu[(long)(_k0+r)*EI + n0 + c4]); } \
    } CP_COMMIT; } while(0)

    P1_LOAD(0, 0);
    const int nIter = H / 16;
    for (int it = 0; it < nIter; it++) {
        int s = it & 1;
        P1_LOAD(s ^ 1, (it + 1) << 4);
        CP_WAIT1;
        __syncthreads();
        #pragma unroll
        for (int kk = 0; kk < 16; kk += 8) {
            unsigned a[2][4], b1[4][2], b2[4][2];
            #pragma unroll
            for (int mi = 0; mi < 2; mi++) {
                const float* ap = &As[s][(warp_m + mi*16 + g)*AST + kk + tig];
                a[mi][0] = ldtf(ap);
                a[mi][1] = ldtf(ap + 8*AST);
                a[mi][2] = ldtf(ap + 4);
                a[mi][3] = ldtf(ap + 8*AST + 4);
            }
            #pragma unroll
            for (int ni = 0; ni < 4; ni++) {
                int col = warp_n + ni*8 + g;
                b1[ni][0] = ldtf(&Bs1[s][(kk+tig)*BST + col]);
                b1[ni][1] = ldtf(&Bs1[s][(kk+tig+4)*BST + col]);
                b2[ni][0] = ldtf(&Bs2[s][(kk+tig)*BST + col]);
                b2[ni][1] = ldtf(&Bs2[s][(kk+tig+4)*BST + col]);
            }
            #pragma unroll
            for (int mi = 0; mi < 2; mi++)
                #pragma unroll
                for (int ni = 0; ni < 4; ni++) {
                    mma_tf32(accG[mi][ni], a[mi], b1[ni]);
                    mma_tf32(accU[mi][ni], a[mi], b2[ni]);
                }
        }
        __syncthreads();
    }
#undef P1_LOAD
    #pragma unroll
    for (int mi = 0; mi < 2; mi++) {
        #pragma unroll
        for (int ni = 0; ni < 4; ni++) {
            int mrow = warp_m + mi*16 + g;
            int col = n0 + warp_n + ni*8 + 2*tig;
            float4 cg = accG[mi][ni], cu = accU[mi][ni];
            if (m0 + mrow < cnt) {
                float g0 = cg.x, g1 = cg.y;
                float2 v = { (g0/(1.f+__expf(-g0)))*cu.x, (g1/(1.f+__expf(-g1)))*cu.y };
                *(float2*)&g_act[(long)(base+m0+mrow)*EI + col] = v;
            }
            if (m0 + mrow + 8 < cnt) {
                float g0 = cg.z, g1 = cg.w;
                float2 v = { (g0/(1.f+__expf(-g0)))*cu.z, (g1/(1.f+__expf(-g1)))*cu.w };
                *(float2*)&g_act[(long)(base+m0+mrow+8)*EI + col] = v;
            }
        }
    }
}

// ---------------- MoE pass 2: CTA 128x64, 128 thr, warp 64x32, 3-stage ----------------
__global__ void __launch_bounds__(128) moe_pass2() {
    int e = blockIdx.z;
    int cnt = g_cnt[e];
    int m0 = blockIdx.y * 128;
    if (m0 >= cnt) return;
    int n0 = blockIdx.x * 64;
    int base = g_off[e];
    const float* Bm = g_dpeT + (size_t)e*EI*H;
    __shared__ float As[3][128*AST];
    __shared__ float Bs[3][16*BST];
    int tid = threadIdx.x;
    int lane = tid & 31, warpId = tid >> 5;
    int g = lane >> 2, tig = lane & 3;
    int warp_m = (warpId & 1) * 64, warp_n = (warpId >> 1) * 32;
    float4 acc[4][4];
    #pragma unroll
    for (int i = 0; i < 4; i++)
        #pragma unroll
        for (int j = 0; j < 4; j++) acc[i][j] = make_float4(0,0,0,0);

#define P2_LOAD(sidx, k0v) do { int _k0 = (k0v); if (_k0 < EI) { \
    _Pragma("unroll") for (int i = 0; i < 4; i++) { int idx = tid + i*128; int r = idx >> 2, c4 = (idx & 3) << 2; \
        int rr = m0 + r; if (rr >= cnt) rr = cnt - 1; \
        cp16(&As[sidx][r*AST + c4], &g_act[(long)(base+rr)*EI + _k0 + c4]); } \
    _Pragma("unroll") for (int i = 0; i < 2; i++) { int idx = tid + i*128; int r = idx >> 4, c4 = (idx & 15) << 2; \
        cp16(&Bs[sidx][r*BST + c4], &Bm[(long)(_k0+r)*H + n0 + c4]); } \
    } CP_COMMIT; } while(0)

    const int nIter = EI / 16;
    P2_LOAD(0, 0);
    P2_LOAD(1, 16);
    int st = 0;
    for (int it = 0; it < nIter; it++) {
        CP_WAIT1;
        __syncthreads();
        #pragma unroll
        for (int kk = 0; kk < 16; kk += 8) {
            unsigned a[4][4], b[4][2];
            #pragma unroll
            for (int mi = 0; mi < 4; mi++) {
                const float* ap = &As[st][(warp_m + mi*16 + g)*AST + kk + tig];
                a[mi][0] = ldtf(ap);
                a[mi][1] = ldtf(ap + 8*AST);
                a[mi][2] = ldtf(ap + 4);
                a[mi][3] = ldtf(ap + 8*AST + 4);
            }
            #pragma unroll
            for (int ni = 0; ni < 4; ni++) {
                int col = warp_n + ni*8 + g;
                b[ni][0] = ldtf(&Bs[st][(kk+tig)*BST + col]);
                b[ni][1] = ldtf(&Bs[st][(kk+tig+4)*BST + col]);
            }
            #pragma unroll
            for (int mi = 0; mi < 4; mi++)
                #pragma unroll
                for (int ni = 0; ni < 4; ni++) mma_tf32(acc[mi][ni], a[mi], b[ni]);
        }
        int wst = st + 2; if (wst >= 3) wst -= 3;
        P2_LOAD(wst, (it + 2) << 4);
        if (++st == 3) st = 0;
    }
#undef P2_LOAD
    #pragma unroll
    for (int mi = 0; mi < 4; mi++) {
        #pragma unroll
        for (int ni = 0; ni < 4; ni++) {
            int mrow = warp_m + mi*16 + g;
            int col = n0 + warp_n + ni*8 + 2*tig;
            float4 c = acc[mi][ni];
            if (m0 + mrow < cnt)
                *(float2*)&g_pairout[(long)(base+m0+mrow)*H + col] = make_float2(c.x, c.y);
            if (m0 + mrow + 8 < cnt)
                *(float2*)&g_pairout[(long)(base+m0+mrow+8)*H + col] = make_float2(c.z, c.w);
        }
    }
}

// ---------------- shared-FFN activation ----------------
__global__ void silumul_kernel(float* __restrict__ g, const float* __restrict__ u, int n) {
    int i = blockIdx.x*256 + threadIdx.x;
    if (i < n) {
        float x = g[i];
        g[i] = (x / (1.f + __expf(-x))) * u[i];
    }
}

// ---------------- final combine ----------------
__global__ void combine_kernel(float* __restrict__ out) {
    int t = blockIdx.x;
    int pos[TOPK]; float w[TOPK];
    #pragma unroll
    for (int j = 0; j < TOPK; j++) {
        pos[j] = g_pairPos[t*TOPK + j];
        w[j]   = g_pairW[pos[j]];
    }
    for (int h = threadIdx.x; h < H; h += 256) {
        float s = g_hres[(long)t*H + h] + g_shared[(long)t*H + h];
        #pragma unroll
        for (int j = 0; j < TOPK; j++)
            s += w[j] * g_pairout[(long)pos[j]*H + h];
        out[(long)t*H + h] = s;
    }
}

// ---------------- launch ----------------
extern "C" void kernel_launch(void* const* d_in, const int* in_sizes, int n_in,
                              void* d_out, int out_size) {
    (void)in_sizes; (void)n_in; (void)out_size;
    const float* x       = (const float*)d_in[0];
    const float* ln1     = (const float*)d_in[1];
    const float* ln2     = (const float*)d_in[2];
    const float* Wq      = (const float*)d_in[3];
    const float* Wk      = (const float*)d_in[4];
    const float* Wv      = (const float*)d_in[5];
    const float* Wo      = (const float*)d_in[6];
    const float* gate_w  = (const float*)d_in[7];
    const float* gpe     = (const float*)d_in[8];
    const float* upe     = (const float*)d_in[9];
    const float* dpe     = (const float*)d_in[10];
    const float* sh_gate = (const float*)d_in[11];
    const float* sh_up   = (const float*)d_in[12];
    const float* sh_down = (const float*)d_in[13];
    float* out = (float*)d_out;

    float *h1p,*qp,*kp,*vp,*scoresp,*attnp,*hresp,*h2p,*sgp,*sup,*sharedp,*gpeTp,*upeTp,*dpeTp;
    cudaGetSymbolAddress((void**)&h1p,     g_h1);
    cudaGetSymbolAddress((void**)&qp,      g_q);
    cudaGetSymbolAddress((void**)&kp,      g_k);
    cudaGetSymbolAddress((void**)&vp,      g_v);
    cudaGetSymbolAddress((void**)&scoresp, g_scores);
    cudaGetSymbolAddress((void**)&attnp,   g_attnout);
    cudaGetSymbolAddress((void**)&hresp,   g_hres);
    cudaGetSymbolAddress((void**)&h2p,     g_h2);
    cudaGetSymbolAddress((void**)&sgp,     g_sg);
    cudaGetSymbolAddress((void**)&sup,     g_su);
    cudaGetSymbolAddress((void**)&sharedp, g_shared);
    cudaGetSymbolAddress((void**)&gpeTp,   g_gpeT);
    cudaGetSymbolAddress((void**)&upeTp,   g_upeT);
    cudaGetSymbolAddress((void**)&dpeTp,   g_dpeT);

    const float inv_sqrt_hd = 0.08838834764831845f;

    // attention branch
    rms_kernel<<<T, 256>>>(x, ln1, h1p);
    gemm_tc<<<dim3(H/64, T/128, 3), 128>>>(h1p, H, 0, Wq, Wk, Wv, H, 0, 0,
                                           qp, kp, vp, H, 0, nullptr, 0,
                                           H, 1.f, 0);
    rope_kernel<<<T, 256>>>();
    gemm_tc<<<dim3(T/64, T/128, NH), 128>>>(qp, H, HD, kp, nullptr, nullptr, H, HD, 1,
                                            scoresp, nullptr, nullptr, T, (long)T*T, nullptr, 0,
                                            HD, inv_sqrt_hd, 1);
    attn_softmax<<<dim3(T, NH), 256>>>();
    gemm_tc<<<dim3(HD/64, T/128, NH), 128>>>(scoresp, T, (long)T*T, vp, nullptr, nullptr, H, HD, 0,
                                             attnp, nullptr, nullptr, H, HD, nullptr, 0,
                                             T, 1.f, 2);
    gemm_tc<<<dim3(H/64, T/128, 1), 128>>>(attnp, H, 0, Wo, nullptr, nullptr, H, 0, 0,
                                           hresp, nullptr, nullptr, H, 0, x, 0,
                                           H, 1.f, 0);

    // MoE branch
    rms_kernel<<<T, 256>>>(hresp, ln2, h2p);
    transpose_e<<<dim3(EI/32, H), 256>>>(gpe, gpeTp, H, EI);
    transpose_e<<<dim3(EI/32, H), 256>>>(upe, upeTp, H, EI);
    transpose_e<<<dim3(H/32, EI), 256>>>(dpe, dpeTp, EI, H);
    zero_cnt_kernel<<<1, 64>>>();
    router_kernel<<<T, 64>>>(gate_w);
    prefix_kernel<<<1, 32>>>();
    scatter_kernel<<<(NPAIR + 255)/256, 256>>>();
    moe_pass1<<<dim3(EI/64, T/128, NEXP), 256>>>();
    moe_pass2<<<dim3(H/64, T/128, NEXP), 128>>>();

    // shared FFN
    gemm_tc<<<dim3(SHF/64, T/128, 2), 128>>>(h2p, H, 0, sh_gate, sh_up, nullptr, SHF, 0, 0,
                                             sgp, sup, nullptr, SHF, 0, nullptr, 0,
                                             H, 1.f, 0);
    silumul_kernel<<<(T*SHF + 255)/256, 256>>>(sgp, sup, T*SHF);
    gemm_tc<<<dim3(H/64, T/128, 1), 128>>>(sgp, SHF, 0, sh_down, nullptr, nullptr, H, 0, 0,
                                           sharedp, nullptr, nullptr, H, 0, nullptr, 0,
                                           SHF, 1.f, 0);

    // combine
    combine_kernel<<<T, 256>>>(out);
}

// round 6
// speedup vs baseline: 1.0422x; 1.0330x over previous
#include <cuda_runtime.h>
#include <math.h>

#define T 1024
#define H 1280
#define NH 10
#define HD 128
#define EI 896
#define NEXP 64
#define TOPK 6
#define SHF 1792
#define NPAIR (T*TOPK)

// ---------------- device scratch ----------------
static __device__ float g_h1[T*H];
static __device__ float g_q[T*H];
static __device__ float g_k[T*H];
static __device__ float g_v[T*H];
static __device__ float g_scores[NH*T*T];
static __device__ float g_attnout[T*H];
static __device__ float g_hres[T*H];
static __device__ float g_h2[T*H];      // tf32-rounded (MMA input)
static __device__ float g_h2u[T*H];     // unrounded (router input)
static __device__ float g_sg[T*SHF];
static __device__ float g_su[T*SHF];
static __device__ float g_shared[T*H];
static __device__ float g_gpeT[(size_t)NEXP*H*EI];
static __device__ float g_upeT[(size_t)NEXP*H*EI];
static __device__ float g_dpeT[(size_t)NEXP*EI*H];
static __device__ float g_act[(size_t)(NPAIR+128)*EI];
static __device__ float g_pairout[(size_t)NPAIR*H];
// rounded weight copies
static __device__ float g_WqR[H*NH*HD];
static __device__ float g_WkR[H*NH*HD];
static __device__ float g_WvR[H*NH*HD];
static __device__ float g_WoR[NH*HD*H];
static __device__ float g_shgR[H*SHF];
static __device__ float g_shuR[H*SHF];
static __device__ float g_shdR[SHF*H];
static __device__ int   g_cnt[NEXP];
static __device__ int   g_off[NEXP];
static __device__ int   g_cur[NEXP];
static __device__ int   g_tokE[NPAIR];
static __device__ float g_tokW[NPAIR];
static __device__ int   g_pairTok[NPAIR];
static __device__ float g_pairW[NPAIR];
static __device__ int   g_pairPos[NPAIR];

// ---------------- helpers ----------------
__device__ __forceinline__ void mma_tf32(float4& c, const unsigned a[4], const unsigned b[2]) {
    asm volatile("mma.sync.aligned.m16n8k8.row.col.f32.tf32.tf32.f32 "
        "{%0,%1,%2,%3}, {%4,%5,%6,%7}, {%8,%9}, {%0,%1,%2,%3};"
        : "+f"(c.x), "+f"(c.y), "+f"(c.z), "+f"(c.w)
        : "r"(a[0]), "r"(a[1]), "r"(a[2]), "r"(a[3]), "r"(b[0]), "r"(b[1]));
}
__device__ __forceinline__ float rtf(float f) {
    unsigned r; asm("cvt.rna.tf32.f32 %0, %1;" : "=r"(r) : "f"(f));
    return __uint_as_float(r);
}
__device__ __forceinline__ void cp16(const void* smem, const void* gmem) {
    unsigned sa = (unsigned)__cvta_generic_to_shared(smem);
    asm volatile("cp.async.cg.shared.global [%0], [%1], 16;" :: "r"(sa), "l"(gmem));
}
#define CP_COMMIT asm volatile("cp.async.commit_group;")
#define CP_WAIT1  asm volatile("cp.async.wait_group 1;")

#define AST 20    // 16-k row stride (+4 pad)
#define BST 72    // 64-n row stride (+8 pad)

// ---------------- one-shot tf32 rounding of weights ----------------
__global__ void round_tf32(const float4* __restrict__ in, float4* __restrict__ out, int n4) {
    int i = blockIdx.x*256 + threadIdx.x;
    if (i < n4) {
        float4 v = in[i];
        v.x = rtf(v.x); v.y = rtf(v.y); v.z = rtf(v.z); v.w = rtf(v.w);
        out[i] = v;
    }
}

// ---------------- RMSNorm (writes tf32-rounded; optional raw copy) ----------------
__global__ void rms_kernel(const float* __restrict__ x, const float* __restrict__ w,
                           float* __restrict__ out, float* __restrict__ outu) {
    int t = blockIdx.x;
    const float* xr = x + (long)t*H;
    __shared__ float red[256];
    float s = 0.f;
    for (int i = threadIdx.x; i < H; i += 256) { float v = xr[i]; s += v*v; }
    red[threadIdx.x] = s; __syncthreads();
    for (int k = 128; k > 0; k >>= 1) {
        if (threadIdx.x < k) red[threadIdx.x] += red[threadIdx.x + k];
        __syncthreads();
    }
    float r = rsqrtf(red[0]/(float)H + 1e-6f);
    for (int i = threadIdx.x; i < H; i += 256) {
        float v = w[i]*xr[i]*r;
        out[(long)t*H + i] = rtf(v);
        if (outu) outu[(long)t*H + i] = v;
    }
}

// ---------------- tf32 GEMM: CTA 128x64, 128 thr, warp tile 64x32 ----------------
// 3-stage cp.async, BK=16, raw tf32 bits from smem (inputs pre-rounded).
// mode: 0 none, 1 causal block skip, 2 K capped at m0+128.
__global__ void __launch_bounds__(128)
gemm_tc(const float* __restrict__ A, int lda, long sA,
        const float* __restrict__ B, const float* __restrict__ Bb, const float* __restrict__ Bc,
        int ldb, long sB, int transB,
        float* __restrict__ C, float* __restrict__ Cb, float* __restrict__ Cc,
        int ldc, long sC,
        const float* __restrict__ res, long sR,
        int K, float alpha, int mode, int roundC) {
    int m0 = blockIdx.y*128, n0 = blockIdx.x*64;
    if (mode == 1 && n0 >= m0 + 128) return;
    int bz = blockIdx.z;
    A += (long)bz*sA;
    if (Bb) {
        if (bz == 1) { B = Bb; C = Cb; }
        else if (bz == 2) { B = Bc; C = Cc; }
    } else {
        B += (long)bz*sB; C += (long)bz*sC; if (res) res += (long)bz*sR;
    }
    int Klim = (mode == 2) ? (m0 + 128 < K ? m0 + 128 : K) : K;

    __shared__ float As[3][128*AST];
    __shared__ float Bs[3][1280];
    int tid = threadIdx.x;
    int lane = tid & 31, warpId = tid >> 5;
    int g = lane >> 2, tig = lane & 3;
    int warp_m = (warpId & 1) * 64, warp_n = (warpId >> 1) * 32;
    float4 acc[4][4];
    #pragma unroll
    for (int i = 0; i < 4; i++)
        #pragma unroll
        for (int j = 0; j < 4; j++) acc[i][j] = make_float4(0.f,0.f,0.f,0.f);

#define G_LOAD(sidx, k0v) do { int _k0 = (k0v); if (_k0 < Klim) { \
    _Pragma("unroll") for (int i = 0; i < 4; i++) { int idx = tid + i*128; int r = idx >> 2, c4 = (idx & 3) << 2; \
        cp16(&As[sidx][r*AST + c4], &A[(long)(m0+r)*lda + _k0 + c4]); } \
    if (!transB) { \
        _Pragma("unroll") for (int i = 0; i < 2; i++) { int idx = tid + i*128; int r = idx >> 4, c4 = (idx & 15) << 2; \
            cp16(&Bs[sidx][r*BST + c4], &B[(long)(_k0+r)*ldb + n0 + c4]); } \
    } else { \
        _Pragma("unroll") for (int i = 0; i < 2; i++) { int idx = tid + i*128; int r = idx >> 2, c4 = (idx & 3) << 2; \
            cp16(&Bs[sidx][r*AST + c4], &B[(long)(n0+r)*ldb + _k0 + c4]); } \
    } } CP_COMMIT; } while(0)

    int nIter = Klim >> 4;
    G_LOAD(0, 0);
    G_LOAD(1, 16);
    int st = 0;
    for (int it = 0; it < nIter; it++) {
        CP_WAIT1;
        __syncthreads();
        #pragma unroll
        for (int kk = 0; kk < 16; kk += 8) {
            unsigned a[4][4], b[4][2];
            #pragma unroll
            for (int mi = 0; mi < 4; mi++) {
                const float* ap = &As[st][(warp_m + mi*16 + g)*AST + kk + tig];
                a[mi][0] = __float_as_uint(ap[0]);
                a[mi][1] = __float_as_uint(ap[8*AST]);
                a[mi][2] = __float_as_uint(ap[4]);
                a[mi][3] = __float_as_uint(ap[8*AST + 4]);
            }
            if (!transB) {
                #pragma unroll
                for (int ni = 0; ni < 4; ni++) {
                    int col = warp_n + ni*8 + g;
                    b[ni][0] = __float_as_uint(Bs[st][(kk+tig)*BST + col]);
                    b[ni][1] = __float_as_uint(Bs[st][(kk+tig+4)*BST + col]);
                }
            } else {
                #pragma unroll
                for (int ni = 0; ni < 4; ni++) {
                    const float* bp = &Bs[st][(warp_n + ni*8 + g)*AST + kk + tig];
                    b[ni][0] = __float_as_uint(bp[0]);
                    b[ni][1] = __float_as_uint(bp[4]);
                }
            }
            #pragma unroll
            for (int mi = 0; mi < 4; mi++)
                #pragma unroll
                for (int ni = 0; ni < 4; ni++) mma_tf32(acc[mi][ni], a[mi], b[ni]);
        }
        int wst = st + 2; if (wst >= 3) wst -= 3;
        G_LOAD(wst, (it + 2) << 4);
        if (++st == 3) st = 0;
    }
#undef G_LOAD
    #pragma unroll
    for (int mi = 0; mi < 4; mi++) {
        #pragma unroll
        for (int ni = 0; ni < 4; ni++) {
            int row = m0 + warp_m + mi*16 + g;
            int col = n0 + warp_n + ni*8 + 2*tig;
            float4 c = acc[mi][ni];
            float2 v0 = { alpha*c.x, alpha*c.y };
            float2 v1 = { alpha*c.z, alpha*c.w };
            if (res) {
                float2 r0 = *(const float2*)&res[(long)row*ldc + col];
                float2 r1 = *(const float2*)&res[(long)(row+8)*ldc + col];
                v0.x += r0.x; v0.y += r0.y; v1.x += r1.x; v1.y += r1.y;
            }
            if (roundC) {
                v0.x = rtf(v0.x); v0.y = rtf(v0.y);
                v1.x = rtf(v1.x); v1.y = rtf(v1.y);
            }
            *(float2*)&C[(long)row*ldc + col] = v0;
            *(float2*)&C[(long)(row+8)*ldc + col] = v1;
        }
    }
}

// ---------------- RoPE (rounds q,k; also rounds v) ----------------
__global__ void rope_kernel() {
    int t = blockIdx.x, tid = threadIdx.x;
    __shared__ float cs[64], sn[64];
    if (tid < 64) {
        float inv = powf(10000.0f, -(float)tid / 64.0f);
        float fr = (float)t * inv;
        cs[tid] = cosf(fr); sn[tid] = sinf(fr);
    }
    __syncthreads();
    for (int idx = tid; idx < NH*64; idx += 256) {
        int hh = idx >> 6, j = idx & 63;
        long b = (long)t*H + hh*HD;
        float c = cs[j], s = sn[j];
        float q1 = g_q[b+j], q2 = g_q[b+j+64];
        g_q[b+j]    = rtf(q1*c - q2*s);
        g_q[b+j+64] = rtf(q2*c + q1*s);
        float k1 = g_k[b+j], k2 = g_k[b+j+64];
        g_k[b+j]    = rtf(k1*c - k2*s);
        g_k[b+j+64] = rtf(k2*c + k1*s);
    }
    for (int i = tid; i < H; i += 256) {
        long b = (long)t*H + i;
        g_v[b] = rtf(g_v[b]);
    }
}

// ---------------- causal softmax (rounds probs; zeros to 128-boundary) ----------------
__global__ void attn_softmax() {
    int t = blockIdx.x, hh = blockIdx.y, tid = threadIdx.x;
    float* row = g_scores + ((long)hh*T + t)*(long)T;
    int len = t + 1;
    int zend = ((t >> 7) + 1) << 7;
    __shared__ float red[256];
    float mx = -3.0e38f;
    for (int i = tid; i < len; i += 256) mx = fmaxf(mx, row[i]);
    red[tid] = mx; __syncthreads();
    for (int s = 128; s > 0; s >>= 1) { if (tid < s) red[tid] = fmaxf(red[tid], red[tid+s]); __syncthreads(); }
    mx = red[0]; __syncthreads();
    float sum = 0.f;
    for (int i = tid; i < len; i += 256) { float e = __expf(row[i]-mx); row[i] = e; sum += e; }
    red[tid] = sum; __syncthreads();
    for (int s = 128; s > 0; s >>= 1) { if (tid < s) red[tid] += red[tid+s]; __syncthreads(); }
    float inv = 1.0f / red[0];
    for (int i = tid; i < len; i += 256) row[i] = rtf(row[i] * inv);
    for (int i = len + tid; i < zend; i += 256) row[i] = 0.f;
}

// ---------------- expert-last transpose (+tf32 round): in[R][C][64] -> out[64][R][C] ----
__global__ void transpose_e(const float* __restrict__ in, float* __restrict__ out, int R, int C) {
    int r = blockIdx.y;
    int c0 = blockIdx.x * 32;
    __shared__ float tile[64*33];
    const float* src = in + ((long)r*C + c0)*64;
    for (int i = threadIdx.x; i < 2048; i += 256) {
        int ci = i >> 6, e = i & 63;
        tile[e*33 + ci] = src[i];
    }
    __syncthreads();
    for (int i = threadIdx.x; i < 2048; i += 256) {
        int e = i >> 5, ci = i & 31;
        out[(long)e*R*C + (long)r*C + c0 + ci] = rtf(tile[e*33 + ci]);
    }
}

// ---------------- router (uses unrounded h2) ----------------
__global__ void zero_cnt_kernel() { if (threadIdx.x < NEXP) g_cnt[threadIdx.x] = 0; }

__global__ void router_kernel(const float* __restrict__ gw) {
    int t = blockIdx.x, e = threadIdx.x;
    const float* hr = g_h2u + (long)t*H;
    float s = 0.f;
    for (int h = 0; h < H; h++) s += hr[h] * gw[h*NEXP + e];
    __shared__ float probs[NEXP];
    probs[e] = s;
    __syncthreads();
    if (e == 0) {
        float mx = -3e38f;
        for (int i = 0; i < NEXP; i++) mx = fmaxf(mx, probs[i]);
        float sum = 0.f;
        for (int i = 0; i < NEXP; i++) { probs[i] = __expf(probs[i]-mx); sum += probs[i]; }
        float inv = 1.f/sum;
        for (int i = 0; i < NEXP; i++) probs[i] *= inv;
        int ti[TOPK]; float tw[TOPK]; float ws = 0.f;
        for (int j = 0; j < TOPK; j++) {
            int bi = 0; float bv = -1.f;
            for (int i = 0; i < NEXP; i++) if (probs[i] > bv) { bv = probs[i]; bi = i; }
            ti[j] = bi; tw[j] = bv; ws += bv; probs[bi] = -2.f;
        }
        float wi = 1.f/ws;
        for (int j = 0; j < TOPK; j++) {
            g_tokE[t*TOPK+j] = ti[j];
            g_tokW[t*TOPK+j] = tw[j]*wi;
            atomicAdd(&g_cnt[ti[j]], 1);
        }
    }
}

__global__ void prefix_kernel() {
    if (threadIdx.x == 0) {
        int s = 0;
        for (int e = 0; e < NEXP; e++) { g_off[e] = s; g_cur[e] = s; s += g_cnt[e]; }
    }
}

__global__ void scatter_kernel() {
    int i = blockIdx.x*256 + threadIdx.x;
    if (i < NPAIR) {
        int e = g_tokE[i];
        int pos = atomicAdd(&g_cur[e], 1);
        g_pairTok[pos] = i / TOPK;
        g_pairW[pos]   = g_tokW[i];
        g_pairPos[i]   = pos;
    }
}

// ---------------- MoE pass 1: CTA 128x64, 256 thr, warp 32x32, dual-B, 2-stage -------
__global__ void __launch_bounds__(256) moe_pass1() {
    int e = blockIdx.z;
    int cnt = g_cnt[e];
    int m0 = blockIdx.y * 128;
    if (m0 >= cnt) return;
    int n0 = blockIdx.x * 64;
    int base = g_off[e];
    const float* Bg = g_gpeT + (size_t)e*H*EI;
    const float* Bu = g_upeT + (size_t)e*H*EI;
    __shared__ int stok[128];
    __shared__ float As[2][128*AST];
    __shared__ float Bs1[2][16*BST];
    __shared__ float Bs2[2][16*BST];
    int tid = threadIdx.x;
    int lane = tid & 31, warpId = tid >> 5;
    int g = lane >> 2, tig = lane & 3;
    int warp_m = (warpId & 3) * 32, warp_n = (warpId >> 2) * 32;
    if (tid < 128) stok[tid] = (m0 + tid < cnt) ? g_pairTok[base + m0 + tid] : 0;
    __syncthreads();
    float4 accG[2][4], accU[2][4];
    #pragma unroll
    for (int i = 0; i < 2; i++)
        #pragma unroll
        for (int j = 0; j < 4; j++) { accG[i][j] = make_float4(0,0,0,0); accU[i][j] = make_float4(0,0,0,0); }

#define P1_LOAD(sidx, k0v) do { int _k0 = (k0v); if (_k0 < H) { \
    _Pragma("unroll") for (int i = 0; i < 2; i++) { int idx = tid + i*256; int r = idx >> 2, c4 = (idx & 3) << 2; \
        cp16(&As[sidx][r*AST + c4], &g_h2[(long)stok[r]*H + _k0 + c4]); } \
    { int r = tid >> 4, c4 = (tid & 15) << 2; \
        cp16(&Bs1[sidx][r*BST + c4], &Bg[(long)(_k0+r)*EI + n0 + c4]); \
        cp16(&Bs2[sidx][r*BST + c4], &Bu[(long)(_k0+r)*EI + n0 + c4]); } \
    } CP_COMMIT; } while(0)

    P1_LOAD(0, 0);
    const int nIter = H / 16;
    for (int it = 0; it < nIter; it++) {
        int s = it & 1;
        P1_LOAD(s ^ 1, (it + 1) << 4);
        CP_WAIT1;
        __syncthreads();
        #pragma unroll
        for (int kk = 0; kk < 16; kk += 8) {
            unsigned a[2][4], b1[4][2], b2[4][2];
            #pragma unroll
            for (int mi = 0; mi < 2; mi++) {
                const float* ap = &As[s][(warp_m + mi*16 + g)*AST + kk + tig];
                a[mi][0] = __float_as_uint(ap[0]);
                a[mi][1] = __float_as_uint(ap[8*AST]);
                a[mi][2] = __float_as_uint(ap[4]);
                a[mi][3] = __float_as_uint(ap[8*AST + 4]);
            }
            #pragma unroll
            for (int ni = 0; ni < 4; ni++) {
                int col = warp_n + ni*8 + g;
                b1[ni][0] = __float_as_uint(Bs1[s][(kk+tig)*BST + col]);
                b1[ni][1] = __float_as_uint(Bs1[s][(kk+tig+4)*BST + col]);
                b2[ni][0] = __float_as_uint(Bs2[s][(kk+tig)*BST + col]);
                b2[ni][1] = __float_as_uint(Bs2[s][(kk+tig+4)*BST + col]);
            }
            #pragma unroll
            for (int mi = 0; mi < 2; mi++)
                #pragma unroll
                for (int ni = 0; ni < 4; ni++) {
                    mma_tf32(accG[mi][ni], a[mi], b1[ni]);
                    mma_tf32(accU[mi][ni], a[mi], b2[ni]);
                }
        }
        __syncthreads();
    }
#undef P1_LOAD
    #pragma unroll
    for (int mi = 0; mi < 2; mi++) {
        #pragma unroll
        for (int ni = 0; ni < 4; ni++) {
            int mrow = warp_m + mi*16 + g;
            int col = n0 + warp_n + ni*8 + 2*tig;
            float4 cg = accG[mi][ni], cu = accU[mi][ni];
            if (m0 + mrow < cnt) {
                float g0 = cg.x, g1 = cg.y;
                float2 v = { rtf((g0/(1.f+__expf(-g0)))*cu.x), rtf((g1/(1.f+__expf(-g1)))*cu.y) };
                *(float2*)&g_act[(long)(base+m0+mrow)*EI + col] = v;
            }
            if (m0 + mrow + 8 < cnt) {
                float g0 = cg.z, g1 = cg.w;
                float2 v = { rtf((g0/(1.f+__expf(-g0)))*cu.z), rtf((g1/(1.f+__expf(-g1)))*cu.w) };
                *(float2*)&g_act[(long)(base+m0+mrow+8)*EI + col] = v;
            }
        }
    }
}

// ---------------- MoE pass 2: CTA 128x64, 128 thr, warp 64x32, 3-stage ----------------
__global__ void __launch_bounds__(128) moe_pass2() {
    int e = blockIdx.z;
    int cnt = g_cnt[e];
    int m0 = blockIdx.y * 128;
    if (m0 >= cnt) return;
    int n0 = blockIdx.x * 64;
    int base = g_off[e];
    const float* Bm = g_dpeT + (size_t)e*EI*H;
    __shared__ float As[3][128*AST];
    __shared__ float Bs[3][16*BST];
    int tid = threadIdx.x;
    int lane = tid & 31, warpId = tid >> 5;
    int g = lane >> 2, tig = lane & 3;
    int warp_m = (warpId & 1) * 64, warp_n = (warpId >> 1) * 32;
    float4 acc[4][4];
    #pragma unroll
    for (int i = 0; i < 4; i++)
        #pragma unroll
        for (int j = 0; j < 4; j++) acc[i][j] = make_float4(0,0,0,0);

#define P2_LOAD(sidx, k0v) do { int _k0 = (k0v); if (_k0 < EI) { \
    _Pragma("unroll") for (int i = 0; i < 4; i++) { int idx = tid + i*128; int r = idx >> 2, c4 = (idx & 3) << 2; \
        int rr = m0 + r; if (rr >= cnt) rr = cnt - 1; \
        cp16(&As[sidx][r*AST + c4], &g_act[(long)(base+rr)*EI + _k0 + c4]); } \
    _Pragma("unroll") for (int i = 0; i < 2; i++) { int idx = tid + i*128; int r = idx >> 4, c4 = (idx & 15) << 2; \
        cp16(&Bs[sidx][r*BST + c4], &Bm[(long)(_k0+r)*H + n0 + c4]); } \
    } CP_COMMIT; } while(0)

    const int nIter = EI / 16;
    P2_LOAD(0, 0);
    P2_LOAD(1, 16);
    int st = 0;
    for (int it = 0; it < nIter; it++) {
        CP_WAIT1;
        __syncthreads();
        #pragma unroll
        for (int kk = 0; kk < 16; kk += 8) {
            unsigned a[4][4], b[4][2];
            #pragma unroll
            for (int mi = 0; mi < 4; mi++) {
                const float* ap = &As[st][(warp_m + mi*16 + g)*AST + kk + tig];
                a[mi][0] = __float_as_uint(ap[0]);
                a[mi][1] = __float_as_uint(ap[8*AST]);
                a[mi][2] = __float_as_uint(ap[4]);
                a[mi][3] = __float_as_uint(ap[8*AST + 4]);
            }
            #pragma unroll
            for (int ni = 0; ni < 4; ni++) {
                int col = warp_n + ni*8 + g;
                b[ni][0] = __float_as_uint(Bs[st][(kk+tig)*BST + col]);
                b[ni][1] = __float_as_uint(Bs[st][(kk+tig+4)*BST + col]);
            }
            #pragma unroll
            for (int mi = 0; mi < 4; mi++)
                #pragma unroll
                for (int ni = 0; ni < 4; ni++) mma_tf32(acc[mi][ni], a[mi], b[ni]);
        }
        int wst = st + 2; if (wst >= 3) wst -= 3;
        P2_LOAD(wst, (it + 2) << 4);
        if (++st == 3) st = 0;
    }
#undef P2_LOAD
    #pragma unroll
    for (int mi = 0; mi < 4; mi++) {
        #pragma unroll
        for (int ni = 0; ni < 4; ni++) {
            int mrow = warp_m + mi*16 + g;
            int col = n0 + warp_n + ni*8 + 2*tig;
            float4 c = acc[mi][ni];
            if (m0 + mrow < cnt)
                *(float2*)&g_pairout[(long)(base+m0+mrow)*H + col] = make_float2(c.x, c.y);
            if (m0 + mrow + 8 < cnt)
                *(float2*)&g_pairout[(long)(base+m0+mrow+8)*H + col] = make_float2(c.z, c.w);
        }
    }
}

// ---------------- shared-FFN activation (rounds output) ----------------
__global__ void silumul_kernel(float* __restrict__ g, const float* __restrict__ u, int n) {
    int i = blockIdx.x*256 + threadIdx.x;
    if (i < n) {
        float x = g[i];
        g[i] = rtf((x / (1.f + __expf(-x))) * u[i]);
    }
}

// ---------------- final combine ----------------
__global__ void combine_kernel(float* __restrict__ out) {
    int t = blockIdx.x;
    int pos[TOPK]; float w[TOPK];
    #pragma unroll
    for (int j = 0; j < TOPK; j++) {
        pos[j] = g_pairPos[t*TOPK + j];
        w[j]   = g_pairW[pos[j]];
    }
    for (int h = threadIdx.x; h < H; h += 256) {
        float s = g_hres[(long)t*H + h] + g_shared[(long)t*H + h];
        #pragma unroll
        for (int j = 0; j < TOPK; j++)
            s += w[j] * g_pairout[(long)pos[j]*H + h];
        out[(long)t*H + h] = s;
    }
}

// ---------------- launch ----------------
extern "C" void kernel_launch(void* const* d_in, const int* in_sizes, int n_in,
                              void* d_out, int out_size) {
    (void)in_sizes; (void)n_in; (void)out_size;
    const float* x       = (const float*)d_in[0];
    const float* ln1     = (const float*)d_in[1];
    const float* ln2     = (const float*)d_in[2];
    const float* Wq      = (const float*)d_in[3];
    const float* Wk      = (const float*)d_in[4];
    const float* Wv      = (const float*)d_in[5];
    const float* Wo      = (const float*)d_in[6];
    const float* gate_w  = (const float*)d_in[7];
    const float* gpe     = (const float*)d_in[8];
    const float* upe     = (const float*)d_in[9];
    const float* dpe     = (const float*)d_in[10];
    const float* sh_gate = (const float*)d_in[11];
    const float* sh_up   = (const float*)d_in[12];
    const float* sh_down = (const float*)d_in[13];
    float* out = (float*)d_out;

    float *h1p,*qp,*kp,*vp,*scoresp,*attnp,*hresp,*h2p,*h2up,*sgp,*sup,*sharedp,*gpeTp,*upeTp,*dpeTp;
    float *wqr,*wkr,*wvr,*wor,*shgr,*shur,*shdr;
    cudaGetSymbolAddress((void**)&h1p,     g_h1);
    cudaGetSymbolAddress((void**)&qp,      g_q);
    cudaGetSymbolAddress((void**)&kp,      g_k);
    cudaGetSymbolAddress((void**)&vp,      g_v);
    cudaGetSymbolAddress((void**)&scoresp, g_scores);
    cudaGetSymbolAddress((void**)&attnp,   g_attnout);
    cudaGetSymbolAddress((void**)&hresp,   g_hres);
    cudaGetSymbolAddress((void**)&h2p,     g_h2);
    cudaGetSymbolAddress((void**)&h2up,    g_h2u);
    cudaGetSymbolAddress((void**)&sgp,     g_sg);
    cudaGetSymbolAddress((void**)&sup,     g_su);
    cudaGetSymbolAddress((void**)&sharedp, g_shared);
    cudaGetSymbolAddress((void**)&gpeTp,   g_gpeT);
    cudaGetSymbolAddress((void**)&upeTp,   g_upeT);
    cudaGetSymbolAddress((void**)&dpeTp,   g_dpeT);
    cudaGetSymbolAddress((void**)&wqr,     g_WqR);
    cudaGetSymbolAddress((void**)&wkr,     g_WkR);
    cudaGetSymbolAddress((void**)&wvr,     g_WvR);
    cudaGetSymbolAddress((void**)&wor,     g_WoR);
    cudaGetSymbolAddress((void**)&shgr,    g_shgR);
    cudaGetSymbolAddress((void**)&shur,    g_shuR);
    cudaGetSymbolAddress((void**)&shdr,    g_shdR);

    const float inv_sqrt_hd = 0.08838834764831845f;

    // one-shot weight rounding to tf32
    int nqkv4 = H*NH*HD/4, nsh4 = H*SHF/4;
    round_tf32<<<(nqkv4+255)/256, 256>>>((const float4*)Wq, (float4*)wqr, nqkv4);
    round_tf32<<<(nqkv4+255)/256, 256>>>((const float4*)Wk, (float4*)wkr, nqkv4);
    round_tf32<<<(nqkv4+255)/256, 256>>>((const float4*)Wv, (float4*)wvr, nqkv4);
    round_tf32<<<(nqkv4+255)/256, 256>>>((const float4*)Wo, (float4*)wor, nqkv4);
    round_tf32<<<(nsh4+255)/256, 256>>>((const float4*)sh_gate, (float4*)shgr, nsh4);
    round_tf32<<<(nsh4+255)/256, 256>>>((const float4*)sh_up,   (float4*)shur, nsh4);
    round_tf32<<<(nsh4+255)/256, 256>>>((const float4*)sh_down, (float4*)shdr, nsh4);

    // attention branch
    rms_kernel<<<T, 256>>>(x, ln1, h1p, nullptr);
    gemm_tc<<<dim3(H/64, T/128, 3), 128>>>(h1p, H, 0, wqr, wkr, wvr, H, 0, 0,
                                           qp, kp, vp, H, 0, nullptr, 0,
                                           H, 1.f, 0, 0);
    rope_kernel<<<T, 256>>>();
    gemm_tc<<<dim3(T/64, T/128, NH), 128>>>(qp, H, HD, kp, nullptr, nullptr, H, HD, 1,
                                            scoresp, nullptr, nullptr, T, (long)T*T, nullptr, 0,
                                            HD, inv_sqrt_hd, 1, 0);
    attn_softmax<<<dim3(T, NH), 256>>>();
    gemm_tc<<<dim3(HD/64, T/128, NH), 128>>>(scoresp, T, (long)T*T, vp, nullptr, nullptr, H, HD, 0,
                                             attnp, nullptr, nullptr, H, HD, nullptr, 0,
                                             T, 1.f, 2, 1);
    gemm_tc<<<dim3(H/64, T/128, 1), 128>>>(attnp, H, 0, wor, nullptr, nullptr, H, 0, 0,
                                           hresp, nullptr, nullptr, H, 0, x, 0,
                                           H, 1.f, 0, 0);

    // MoE branch
    rms_kernel<<<T, 256>>>(hresp, ln2, h2p, h2up);
    transpose_e<<<dim3(EI/32, H), 256>>>(gpe, gpeTp, H, EI);
    transpose_e<<<dim3(EI/32, H), 256>>>(upe, upeTp, H, EI);
    transpose_e<<<dim3(H/32, EI), 256>>>(dpe, dpeTp, EI, H);
    zero_cnt_kernel<<<1, 64>>>();
    router_kernel<<<T, 64>>>(gate_w);
    prefix_kernel<<<1, 32>>>();
    scatter_kernel<<<(NPAIR + 255)/256, 256>>>();
    moe_pass1<<<dim3(EI/64, T/128, NEXP), 256>>>();
    moe_pass2<<<dim3(H/64, T/128, NEXP), 128>>>();

    // shared FFN
    gemm_tc<<<dim3(SHF/64, T/128, 2), 128>>>(h2p, H, 0, shgr, shur, nullptr, SHF, 0, 0,
                                             sgp, sup, nullptr, SHF, 0, nullptr, 0,
                                             H, 1.f, 0, 0);
    silumul_kernel<<<(T*SHF + 255)/256, 256>>>(sgp, sup, T*SHF);
    gemm_tc<<<dim3(H/64, T/128, 1), 128>>>(sgp, SHF, 0, shdr, nullptr, nullptr, H, 0, 0,
                                           sharedp, nullptr, nullptr, H, 0, nullptr, 0,
                                           SHF, 1.f, 0, 0);

    // combine
    combine_kernel<<<T, 256>>>(out);
}

// round 7
// speedup vs baseline: 1.0677x; 1.0244x over previous
#include <cuda_runtime.h>
#include <cuda_bf16.h>
#include <math.h>

#define T 1024
#define H 1280
#define NH 10
#define HD 128
#define EI 896
#define NEXP 64
#define TOPK 6
#define SHF 1792
#define NPAIR (T*TOPK)

// ---------------- device scratch ----------------
static __device__ float g_h1[T*H];
static __device__ float g_q[T*H];
static __device__ float g_k[T*H];
static __device__ float g_v[T*H];
static __device__ float g_scores[NH*T*T];
static __device__ float g_attnout[T*H];
static __device__ float g_hres[T*H];
static __device__ float g_h2[T*H];              // tf32-rounded fp32 (shared FFN)
static __device__ float g_h2u[T*H];             // unrounded fp32 (router)
static __device__ __nv_bfloat16 g_h2b[T*H];     // bf16 (MoE pass1 A)
static __device__ float g_sg[T*SHF];
static __device__ float g_su[T*SHF];
static __device__ float g_shared[T*H];
// bf16 expert weights, pair-interleaved: [e][k/2][n] as bf162
static __device__ unsigned g_gpeB[(size_t)NEXP*(H/2)*EI];
static __device__ unsigned g_upeB[(size_t)NEXP*(H/2)*EI];
static __device__ unsigned g_dpeB[(size_t)NEXP*(EI/2)*H];
static __device__ __nv_bfloat16 g_actB[(size_t)(NPAIR+128)*EI];
static __device__ float g_pairout[(size_t)NPAIR*H];
// rounded fp32 weight copies (tf32 GEMMs)
static __device__ float g_WqR[H*NH*HD];
static __device__ float g_WkR[H*NH*HD];
static __device__ float g_WvR[H*NH*HD];
static __device__ float g_WoR[NH*HD*H];
static __device__ float g_shgR[H*SHF];
static __device__ float g_shuR[H*SHF];
static __device__ float g_shdR[SHF*H];
static __device__ int   g_cnt[NEXP];
static __device__ int   g_off[NEXP];
static __device__ int   g_cur[NEXP];
static __device__ int   g_tokE[NPAIR];
static __device__ float g_tokW[NPAIR];
static __device__ int   g_pairTok[NPAIR];
static __device__ float g_pairW[NPAIR];
static __device__ int   g_pairPos[NPAIR];

// ---------------- helpers ----------------
__device__ __forceinline__ void mma_tf32(float4& c, const unsigned a[4], const unsigned b[2]) {
    asm volatile("mma.sync.aligned.m16n8k8.row.col.f32.tf32.tf32.f32 "
        "{%0,%1,%2,%3}, {%4,%5,%6,%7}, {%8,%9}, {%0,%1,%2,%3};"
        : "+f"(c.x), "+f"(c.y), "+f"(c.z), "+f"(c.w)
        : "r"(a[0]), "r"(a[1]), "r"(a[2]), "r"(a[3]), "r"(b[0]), "r"(b[1]));
}
__device__ __forceinline__ void mma_bf16(float4& c, const unsigned a[4], const unsigned b[2]) {
    asm volatile("mma.sync.aligned.m16n8k16.row.col.f32.bf16.bf16.f32 "
        "{%0,%1,%2,%3}, {%4,%5,%6,%7}, {%8,%9}, {%0,%1,%2,%3};"
        : "+f"(c.x), "+f"(c.y), "+f"(c.z), "+f"(c.w)
        : "r"(a[0]), "r"(a[1]), "r"(a[2]), "r"(a[3]), "r"(b[0]), "r"(b[1]));
}
__device__ __forceinline__ float rtf(float f) {
    unsigned r; asm("cvt.rna.tf32.f32 %0, %1;" : "=r"(r) : "f"(f));
    return __uint_as_float(r);
}
__device__ __forceinline__ void cp16(const void* smem, const void* gmem) {
    unsigned sa = (unsigned)__cvta_generic_to_shared(smem);
    asm volatile("cp.async.cg.shared.global [%0], [%1], 16;" :: "r"(sa), "l"(gmem));
}
#define CP_COMMIT asm volatile("cp.async.commit_group;")
#define CP_WAIT1  asm volatile("cp.async.wait_group 1;")

#define AST 20    // fp32 A row stride (16k + 4 pad)
#define BST 72    // fp32 B row stride (64n + 8 pad)
#define BST2 72   // bf162 B row stride (64n + 8 pad)

// ---------------- fused weight rounding ----------------
__global__ void round_all(const float4* w0, float4* o0, const float4* w1, float4* o1,
                          const float4* w2, float4* o2, const float4* w3, float4* o3,
                          const float4* w4, float4* o4, const float4* w5, float4* o5,
                          const float4* w6, float4* o6) {
    int z = blockIdx.y;
    const float4* in; float4* out; int n4;
    switch (z) {
        case 0: in = w0; out = o0; n4 = H*NH*HD/4; break;
        case 1: in = w1; out = o1; n4 = H*NH*HD/4; break;
        case 2: in = w2; out = o2; n4 = H*NH*HD/4; break;
        case 3: in = w3; out = o3; n4 = H*NH*HD/4; break;
        case 4: in = w4; out = o4; n4 = H*SHF/4; break;
        case 5: in = w5; out = o5; n4 = H*SHF/4; break;
        default: in = w6; out = o6; n4 = SHF*H/4; break;
    }
    int i = blockIdx.x*256 + threadIdx.x;
    if (i < n4) {
        float4 v = in[i];
        v.x = rtf(v.x); v.y = rtf(v.y); v.z = rtf(v.z); v.w = rtf(v.w);
        out[i] = v;
    }
}

// ---------------- RMSNorm ----------------
__global__ void rms_kernel(const float* __restrict__ x, const float* __restrict__ w,
                           float* __restrict__ out, float* __restrict__ outu,
                           __nv_bfloat16* __restrict__ outb) {
    int t = blockIdx.x;
    const float* xr = x + (long)t*H;
    __shared__ float red[256];
    float s = 0.f;
    for (int i = threadIdx.x; i < H; i += 256) { float v = xr[i]; s += v*v; }
    red[threadIdx.x] = s; __syncthreads();
    for (int k = 128; k > 0; k >>= 1) {
        if (threadIdx.x < k) red[threadIdx.x] += red[threadIdx.x + k];
        __syncthreads();
    }
    float r = rsqrtf(red[0]/(float)H + 1e-6f);
    for (int i = threadIdx.x; i < H; i += 256) {
        float v = w[i]*xr[i]*r;
        out[(long)t*H + i] = rtf(v);
        if (outu) outu[(long)t*H + i] = v;
        if (outb) outb[(long)t*H + i] = __float2bfloat16(v);
    }
}

// ---------------- tf32 GEMM: CTA 64x64, 128 thr, warp 32x32, BK=16, 3-stage ----------
// mode: 0 none, 1 causal block skip, 2 K capped at m0+64.
__global__ void __launch_bounds__(128)
gemm_tc(const float* __restrict__ A, int lda, long sA,
        const float* __restrict__ B, const float* __restrict__ Bb, const float* __restrict__ Bc,
        int ldb, long sB, int transB,
        float* __restrict__ C, float* __restrict__ Cb, float* __restrict__ Cc,
        int ldc, long sC,
        const float* __restrict__ res, long sR,
        int K, float alpha, int mode, int roundC) {
    int m0 = blockIdx.y*64, n0 = blockIdx.x*64;
    if (mode == 1 && n0 >= m0 + 64) return;
    int bz = blockIdx.z;
    A += (long)bz*sA;
    if (Bb) {
        if (bz == 1) { B = Bb; C = Cb; }
        else if (bz == 2) { B = Bc; C = Cc; }
    } else {
        B += (long)bz*sB; C += (long)bz*sC; if (res) res += (long)bz*sR;
    }
    int Klim = (mode == 2) ? (m0 + 64 < K ? m0 + 64 : K) : K;

    __shared__ float As[3][64*AST];
    __shared__ float Bs[3][1280];
    int tid = threadIdx.x;
    int lane = tid & 31, warpId = tid >> 5;
    int g = lane >> 2, tig = lane & 3;
    int warp_m = (warpId & 1) * 32, warp_n = (warpId >> 1) * 32;
    float4 acc[2][4];
    #pragma unroll
    for (int i = 0; i < 2; i++)
        #pragma unroll
        for (int j = 0; j < 4; j++) acc[i][j] = make_float4(0.f,0.f,0.f,0.f);

#define G_LOAD(sidx, k0v) do { int _k0 = (k0v); if (_k0 < Klim) { \
    _Pragma("unroll") for (int i = 0; i < 2; i++) { int idx = tid + i*128; int r = idx >> 2, c4 = (idx & 3) << 2; \
        cp16(&As[sidx][r*AST + c4], &A[(long)(m0+r)*lda + _k0 + c4]); } \
    if (!transB) { \
        _Pragma("unroll") for (int i = 0; i < 2; i++) { int idx = tid + i*128; int r = idx >> 4, c4 = (idx & 15) << 2; \
            cp16(&Bs[sidx][r*BST + c4], &B[(long)(_k0+r)*ldb + n0 + c4]); } \
    } else { \
        _Pragma("unroll") for (int i = 0; i < 2; i++) { int idx = tid + i*128; int r = idx >> 2, c4 = (idx & 3) << 2; \
            cp16(&Bs[sidx][r*AST + c4], &B[(long)(n0+r)*ldb + _k0 + c4]); } \
    } } CP_COMMIT; } while(0)

    int nIter = Klim >> 4;
    G_LOAD(0, 0);
    G_LOAD(1, 16);
    int st = 0;
    for (int it = 0; it < nIter; it++) {
        CP_WAIT1;
        __syncthreads();
        #pragma unroll
        for (int kk = 0; kk < 16; kk += 8) {
            unsigned a[2][4], b[4][2];
            #pragma unroll
            for (int mi = 0; mi < 2; mi++) {
                const float* ap = &As[st][(warp_m + mi*16 + g)*AST + kk + tig];
                a[mi][0] = __float_as_uint(ap[0]);
                a[mi][1] = __float_as_uint(ap[8*AST]);
                a[mi][2] = __float_as_uint(ap[4]);
                a[mi][3] = __float_as_uint(ap[8*AST + 4]);
            }
            if (!transB) {
                #pragma unroll
                for (int ni = 0; ni < 4; ni++) {
                    int col = warp_n + ni*8 + g;
                    b[ni][0] = __float_as_uint(Bs[st][(kk+tig)*BST + col]);
                    b[ni][1] = __float_as_uint(Bs[st][(kk+tig+4)*BST + col]);
                }
            } else {
                #pragma unroll
                for (int ni = 0; ni < 4; ni++) {
                    const float* bp = &Bs[st][(warp_n + ni*8 + g)*AST + kk + tig];
                    b[ni][0] = __float_as_uint(bp[0]);
                    b[ni][1] = __float_as_uint(bp[4]);
                }
            }
            #pragma unroll
            for (int mi = 0; mi < 2; mi++)
                #pragma unroll
                for (int ni = 0; ni < 4; ni++) mma_tf32(acc[mi][ni], a[mi], b[ni]);
        }
        int wst = st + 2; if (wst >= 3) wst -= 3;
        G_LOAD(wst, (it + 2) << 4);
        if (++st == 3) st = 0;
    }
#undef G_LOAD
    #pragma unroll
    for (int mi = 0; mi < 2; mi++) {
        #pragma unroll
        for (int ni = 0; ni < 4; ni++) {
            int row = m0 + warp_m + mi*16 + g;
            int col = n0 + warp_n + ni*8 + 2*tig;
            float4 c = acc[mi][ni];
            float2 v0 = { alpha*c.x, alpha*c.y };
            float2 v1 = { alpha*c.z, alpha*c.w };
            if (res) {
                float2 r0 = *(const float2*)&res[(long)row*ldc + col];
                float2 r1 = *(const float2*)&res[(long)(row+8)*ldc + col];
                v0.x += r0.x; v0.y += r0.y; v1.x += r1.x; v1.y += r1.y;
            }
            if (roundC) {
                v0.x = rtf(v0.x); v0.y = rtf(v0.y);
                v1.x = rtf(v1.x); v1.y = rtf(v1.y);
            }
            *(float2*)&C[(long)row*ldc + col] = v0;
            *(float2*)&C[(long)(row+8)*ldc + col] = v1;
        }
    }
}

// ---------------- RoPE (rounds q,k,v) ----------------
__global__ void rope_kernel() {
    int t = blockIdx.x, tid = threadIdx.x;
    __shared__ float cs[64], sn[64];
    if (tid < 64) {
        float inv = powf(10000.0f, -(float)tid / 64.0f);
        float fr = (float)t * inv;
        cs[tid] = cosf(fr); sn[tid] = sinf(fr);
    }
    __syncthreads();
    for (int idx = tid; idx < NH*64; idx += 256) {
        int hh = idx >> 6, j = idx & 63;
        long b = (long)t*H + hh*HD;
        float c = cs[j], s = sn[j];
        float q1 = g_q[b+j], q2 = g_q[b+j+64];
        g_q[b+j]    = rtf(q1*c - q2*s);
        g_q[b+j+64] = rtf(q2*c + q1*s);
        float k1 = g_k[b+j], k2 = g_k[b+j+64];
        g_k[b+j]    = rtf(k1*c - k2*s);
        g_k[b+j+64] = rtf(k2*c + k1*s);
    }
    for (int i = tid; i < H; i += 256) {
        long b = (long)t*H + i;
        g_v[b] = rtf(g_v[b]);
    }
}

// ---------------- causal softmax (zeros to next 64-boundary) ----------------
__global__ void attn_softmax() {
    int t = blockIdx.x, hh = blockIdx.y, tid = threadIdx.x;
    float* row = g_scores + ((long)hh*T + t)*(long)T;
    int len = t + 1;
    int zend = ((t >> 6) + 1) << 6;
    __shared__ float red[256];
    float mx = -3.0e38f;
    for (int i = tid; i < len; i += 256) mx = fmaxf(mx, row[i]);
    red[tid] = mx; __syncthreads();
    for (int s = 128; s > 0; s >>= 1) { if (tid < s) red[tid] = fmaxf(red[tid], red[tid+s]); __syncthreads(); }
    mx = red[0]; __syncthreads();
    float sum = 0.f;
    for (int i = tid; i < len; i += 256) { float e = __expf(row[i]-mx); row[i] = e; sum += e; }
    red[tid] = sum; __syncthreads();
    for (int s = 128; s > 0; s >>= 1) { if (tid < s) red[tid] += red[tid+s]; __syncthreads(); }
    float inv = 1.0f / red[0];
    for (int i = tid; i < len; i += 256) row[i] = rtf(row[i] * inv);
    for (int i = len + tid; i < zend; i += 256) row[i] = 0.f;
}

// ---------------- expert transpose -> bf16 pairs: in[R][C][64] -> out[64][R/2][C] bf162 --
__global__ void transpose_eb(const float* __restrict__ in, unsigned* __restrict__ out,
                             int R, int C) {
    int r0 = blockIdx.y * 2, c0 = blockIdx.x * 32;
    __shared__ float tile[2][32][65];
    for (int i = threadIdx.x; i < 4096; i += 256) {
        int r = i >> 11, rem = i & 2047, ci = rem >> 6, e = rem & 63;
        tile[r][ci][e] = in[((long)(r0+r)*C + c0+ci)*64 + e];
    }
    __syncthreads();
    long half = (long)(R >> 1)*C;
    for (int j = threadIdx.x; j < 2048; j += 256) {
        int e = j >> 5, ci = j & 31;
        __nv_bfloat162 v = __floats2bfloat162_rn(tile[0][ci][e], tile[1][ci][e]);
        out[(long)e*half + (long)(r0 >> 1)*C + c0 + ci] = *(unsigned*)&v;
    }
}

// ---------------- router ----------------
__global__ void zero_cnt_kernel() { if (threadIdx.x < NEXP) g_cnt[threadIdx.x] = 0; }

__global__ void router_kernel(const float* __restrict__ gw) {
    int t = blockIdx.x, e = threadIdx.x;
    const float* hr = g_h2u + (long)t*H;
    float s = 0.f;
    for (int h = 0; h < H; h++) s += hr[h] * gw[h*NEXP + e];
    __shared__ float probs[NEXP];
    probs[e] = s;
    __syncthreads();
    if (e == 0) {
        float mx = -3e38f;
        for (int i = 0; i < NEXP; i++) mx = fmaxf(mx, probs[i]);
        float sum = 0.f;
        for (int i = 0; i < NEXP; i++) { probs[i] = __expf(probs[i]-mx); sum += probs[i]; }
        float inv = 1.f/sum;
        for (int i = 0; i < NEXP; i++) probs[i] *= inv;
        int ti[TOPK]; float tw[TOPK]; float ws = 0.f;
        for (int j = 0; j < TOPK; j++) {
            int bi = 0; float bv = -1.f;
            for (int i = 0; i < NEXP; i++) if (probs[i] > bv) { bv = probs[i]; bi = i; }
            ti[j] = bi; tw[j] = bv; ws += bv; probs[bi] = -2.f;
        }
        float wi = 1.f/ws;
        for (int j = 0; j < TOPK; j++) {
            g_tokE[t*TOPK+j] = ti[j];
            g_tokW[t*TOPK+j] = tw[j]*wi;
            atomicAdd(&g_cnt[ti[j]], 1);
        }
    }
}

__global__ void prefix_kernel() {
    if (threadIdx.x == 0) {
        int s = 0;
        for (int e = 0; e < NEXP; e++) { g_off[e] = s; g_cur[e] = s; s += g_cnt[e]; }
    }
}

__global__ void scatter_kernel() {
    int i = blockIdx.x*256 + threadIdx.x;
    if (i < NPAIR) {
        int e = g_tokE[i];
        int pos = atomicAdd(&g_cur[e], 1);
        g_pairTok[pos] = i / TOPK;
        g_pairW[pos]   = g_tokW[i];
        g_pairPos[i]   = pos;
    }
}

// ---------------- MoE pass 1 (bf16): CTA 128x64, 256 thr, warp 32x32, dual-B, 3-stage --
__global__ void __launch_bounds__(256) moe_pass1() {
    int e = blockIdx.z;
    int cnt = g_cnt[e];
    int m0 = blockIdx.y * 128;
    if (m0 >= cnt) return;
    int n0 = blockIdx.x * 64;
    int base = g_off[e];
    const unsigned* Bg = g_gpeB + (size_t)e*(H/2)*EI;
    const unsigned* Bu = g_upeB + (size_t)e*(H/2)*EI;
    __shared__ int stok[128];
    __shared__ unsigned AsB[3][2][128][4];   // [stage][kgrp][m][4 bf162]
    __shared__ unsigned Bs1[3][8][BST2];
    __shared__ unsigned Bs2[3][8][BST2];
    int tid = threadIdx.x;
    int lane = tid & 31, warpId = tid >> 5;
    int g = lane >> 2, tig = lane & 3;
    int warp_m = (warpId & 3) * 32, warp_n = (warpId >> 2) * 32;
    if (tid < 128) stok[tid] = (m0 + tid < cnt) ? g_pairTok[base + m0 + tid] : 0;
    __syncthreads();
    float4 accG[2][4], accU[2][4];
    #pragma unroll
    for (int i = 0; i < 2; i++)
        #pragma unroll
        for (int j = 0; j < 4; j++) { accG[i][j] = make_float4(0,0,0,0); accU[i][j] = make_float4(0,0,0,0); }

#define P1_LOAD(sidx, k0v) do { int _k0 = (k0v); if (_k0 < H) { \
    { int r = tid >> 1, grp = tid & 1; \
      cp16(&AsB[sidx][grp][r][0], &g_h2b[(long)stok[r]*H + _k0 + grp*8]); } \
    if (tid < 128) { int r = tid >> 4, c = (tid & 15) << 2; \
      cp16(&Bs1[sidx][r][c], &Bg[((long)(_k0 >> 1) + r)*EI + n0 + c]); } \
    else { int t2 = tid - 128; int r = t2 >> 4, c = (t2 & 15) << 2; \
      cp16(&Bs2[sidx][r][c], &Bu[((long)(_k0 >> 1) + r)*EI + n0 + c]); } \
    } CP_COMMIT; } while(0)

    const int nIter = H / 16;
    P1_LOAD(0, 0);
    P1_LOAD(1, 16);
    int st = 0;
    for (int it = 0; it < nIter; it++) {
        CP_WAIT1;
        __syncthreads();
        unsigned a[2][4], b1[4][2], b2[4][2];
        #pragma unroll
        for (int mi = 0; mi < 2; mi++) {
            int row = warp_m + mi*16 + g;
            a[mi][0] = AsB[st][0][row][tig];
            a[mi][1] = AsB[st][0][row+8][tig];
            a[mi][2] = AsB[st][1][row][tig];
            a[mi][3] = AsB[st][1][row+8][tig];
        }
        #pragma unroll
        for (int ni = 0; ni < 4; ni++) {
            int col = warp_n + ni*8 + g;
            b1[ni][0] = Bs1[st][tig][col];
            b1[ni][1] = Bs1[st][tig+4][col];
            b2[ni][0] = Bs2[st][tig][col];
            b2[ni][1] = Bs2[st][tig+4][col];
        }
        #pragma unroll
        for (int mi = 0; mi < 2; mi++)
            #pragma unroll
            for (int ni = 0; ni < 4; ni++) {
                mma_bf16(accG[mi][ni], a[mi], b1[ni]);
                mma_bf16(accU[mi][ni], a[mi], b2[ni]);
            }
        int wst = st + 2; if (wst >= 3) wst -= 3;
        P1_LOAD(wst, (it + 2) << 4);
        if (++st == 3) st = 0;
    }
#undef P1_LOAD
    #pragma unroll
    for (int mi = 0; mi < 2; mi++) {
        #pragma unroll
        for (int ni = 0; ni < 4; ni++) {
            int mrow = warp_m + mi*16 + g;
            int col = n0 + warp_n + ni*8 + 2*tig;
            float4 cg = accG[mi][ni], cu = accU[mi][ni];
            if (m0 + mrow < cnt) {
                float g0 = cg.x, g1 = cg.y;
                __nv_bfloat162 v = __floats2bfloat162_rn((g0/(1.f+__expf(-g0)))*cu.x,
                                                         (g1/(1.f+__expf(-g1)))*cu.y);
                *(__nv_bfloat162*)&g_actB[(long)(base+m0+mrow)*EI + col] = v;
            }
            if (m0 + mrow + 8 < cnt) {
                float g0 = cg.z, g1 = cg.w;
                __nv_bfloat162 v = __floats2bfloat162_rn((g0/(1.f+__expf(-g0)))*cu.z,
                                                         (g1/(1.f+__expf(-g1)))*cu.w);
                *(__nv_bfloat162*)&g_actB[(long)(base+m0+mrow+8)*EI + col] = v;
            }
        }
    }
}

// ---------------- MoE pass 2 (bf16): CTA 128x64, 128 thr, warp 64x32, 3-stage ----------
__global__ void __launch_bounds__(128) moe_pass2() {
    int e = blockIdx.z;
    int cnt = g_cnt[e];
    int m0 = blockIdx.y * 128;
    if (m0 >= cnt) return;
    int n0 = blockIdx.x * 64;
    int base = g_off[e];
    const unsigned* Bm = g_dpeB + (size_t)e*(EI/2)*H;
    __shared__ unsigned AsB[3][2][128][4];
    __shared__ unsigned Bs[3][8][BST2];
    int tid = threadIdx.x;
    int lane = tid & 31, warpId = tid >> 5;
    int g = lane >> 2, tig = lane & 3;
    int warp_m = (warpId & 1) * 64, warp_n = (warpId >> 1) * 32;
    float4 acc[4][4];
    #pragma unroll
    for (int i = 0; i < 4; i++)
        #pragma unroll
        for (int j = 0; j < 4; j++) acc[i][j] = make_float4(0,0,0,0);

#define P2_LOAD(sidx, k0v) do { int _k0 = (k0v); if (_k0 < EI) { \
    _Pragma("unroll") for (int i = 0; i < 2; i++) { int idx = tid + i*128; int r = idx >> 1, grp = idx & 1; \
        int rr = m0 + r; if (rr >= cnt) rr = cnt - 1; \
        cp16(&AsB[sidx][grp][r][0], &g_actB[(long)(base+rr)*EI + _k0 + grp*8]); } \
    { int r = tid >> 4, c = (tid & 15) << 2; \
      cp16(&Bs[sidx][r][c], &Bm[((long)(_k0 >> 1) + r)*H + n0 + c]); } \
    } CP_COMMIT; } while(0)

    const int nIter = EI / 16;
    P2_LOAD(0, 0);
    P2_LOAD(1, 16);
    int st = 0;
    for (int it = 0; it < nIter; it++) {
        CP_WAIT1;
        __syncthreads();
        unsigned a[4][4], b[4][2];
        #pragma unroll
        for (int mi = 0; mi < 4; mi++) {
            int row = warp_m + mi*16 + g;
            a[mi][0] = AsB[st][0][row][tig];
            a[mi][1] = AsB[st][0][row+8][tig];
            a[mi][2] = AsB[st][1][row][tig];
            a[mi][3] = AsB[st][1][row+8][tig];
        }
        #pragma unroll
        for (int ni = 0; ni < 4; ni++) {
            int col = warp_n + ni*8 + g;
            b[ni][0] = Bs[st][tig][col];
            b[ni][1] = Bs[st][tig+4][col];
        }
        #pragma unroll
        for (int mi = 0; mi < 4; mi++)
            #pragma unroll
            for (int ni = 0; ni < 4; ni++) mma_bf16(acc[mi][ni], a[mi], b[ni]);
        int wst = st + 2; if (wst >= 3) wst -= 3;
        P2_LOAD(wst, (it + 2) << 4);
        if (++st == 3) st = 0;
    }
#undef P2_LOAD
    #pragma unroll
    for (int mi = 0; mi < 4; mi++) {
        #pragma unroll
        for (int ni = 0; ni < 4; ni++) {
            int mrow = warp_m + mi*16 + g;
            int col = n0 + warp_n + ni*8 + 2*tig;
            float4 c = acc[mi][ni];
            if (m0 + mrow < cnt)
                *(float2*)&g_pairout[(long)(base+m0+mrow)*H + col] = make_float2(c.x, c.y);
            if (m0 + mrow + 8 < cnt)
                *(float2*)&g_pairout[(long)(base+m0+mrow+8)*H + col] = make_float2(c.z, c.w);
        }
    }
}

// ---------------- shared-FFN activation (rounds output) ----------------
__global__ void silumul_kernel(float* __restrict__ g, const float* __restrict__ u, int n) {
    int i = blockIdx.x*256 + threadIdx.x;
    if (i < n) {
        float x = g[i];
        g[i] = rtf((x / (1.f + __expf(-x))) * u[i]);
    }
}

// ---------------- final combine ----------------
__global__ void combine_kernel(float* __restrict__ out) {
    int t = blockIdx.x;
    int pos[TOPK]; float w[TOPK];
    #pragma unroll
    for (int j = 0; j < TOPK; j++) {
        pos[j] = g_pairPos[t*TOPK + j];
        w[j]   = g_pairW[pos[j]];
    }
    for (int h = threadIdx.x; h < H; h += 256) {
        float s = g_hres[(long)t*H + h] + g_shared[(long)t*H + h];
        #pragma unroll
        for (int j = 0; j < TOPK; j++)
            s += w[j] * g_pairout[(long)pos[j]*H + h];
        out[(long)t*H + h] = s;
    }
}

// ---------------- launch ----------------
extern "C" void kernel_launch(void* const* d_in, const int* in_sizes, int n_in,
                              void* d_out, int out_size) {
    (void)in_sizes; (void)n_in; (void)out_size;
    const float* x       = (const float*)d_in[0];
    const float* ln1     = (const float*)d_in[1];
    const float* ln2     = (const float*)d_in[2];
    const float* Wq      = (const float*)d_in[3];
    const float* Wk      = (const float*)d_in[4];
    const float* Wv      = (const float*)d_in[5];
    const float* Wo      = (const float*)d_in[6];
    const float* gate_w  = (const float*)d_in[7];
    const float* gpe     = (const float*)d_in[8];
    const float* upe     = (const float*)d_in[9];
    const float* dpe     = (const float*)d_in[10];
    const float* sh_gate = (const float*)d_in[11];
    const float* sh_up   = (const float*)d_in[12];
    const float* sh_down = (const float*)d_in[13];
    float* out = (float*)d_out;

    float *h1p,*qp,*kp,*vp,*scoresp,*attnp,*hresp,*h2p,*h2up,*sgp,*sup,*sharedp;
    __nv_bfloat16 *h2bp;
    unsigned *gpeBp,*upeBp,*dpeBp;
    float *wqr,*wkr,*wvr,*wor,*shgr,*shur,*shdr;
    cudaGetSymbolAddress((void**)&h1p,     g_h1);
    cudaGetSymbolAddress((void**)&qp,      g_q);
    cudaGetSymbolAddress((void**)&kp,      g_k);
    cudaGetSymbolAddress((void**)&vp,      g_v);
    cudaGetSymbolAddress((void**)&scoresp, g_scores);
    cudaGetSymbolAddress((void**)&attnp,   g_attnout);
    cudaGetSymbolAddress((void**)&hresp,   g_hres);
    cudaGetSymbolAddress((void**)&h2p,     g_h2);
    cudaGetSymbolAddress((void**)&h2up,    g_h2u);
    cudaGetSymbolAddress((void**)&h2bp,    g_h2b);
    cudaGetSymbolAddress((void**)&sgp,     g_sg);
    cudaGetSymbolAddress((void**)&sup,     g_su);
    cudaGetSymbolAddress((void**)&sharedp, g_shared);
    cudaGetSymbolAddress((void**)&gpeBp,   g_gpeB);
    cudaGetSymbolAddress((void**)&upeBp,   g_upeB);
    cudaGetSymbolAddress((void**)&dpeBp,   g_dpeB);
    cudaGetSymbolAddress((void**)&wqr,     g_WqR);
    cudaGetSymbolAddress((void**)&wkr,     g_WkR);
    cudaGetSymbolAddress((void**)&wvr,     g_WvR);
    cudaGetSymbolAddress((void**)&wor,     g_WoR);
    cudaGetSymbolAddress((void**)&shgr,    g_shgR);
    cudaGetSymbolAddress((void**)&shur,    g_shuR);
    cudaGetSymbolAddress((void**)&shdr,    g_shdR);

    const float inv_sqrt_hd = 0.08838834764831845f;

    // fused one-shot weight rounding (7 matrices in one launch)
    round_all<<<dim3((H*SHF/4 + 255)/256, 7), 256>>>(
        (const float4*)Wq, (float4*)wqr, (const float4*)Wk, (float4*)wkr,
        (const float4*)Wv, (float4*)wvr, (const float4*)Wo, (float4*)wor,
        (const float4*)sh_gate, (float4*)shgr, (const float4*)sh_up, (float4*)shur,
        (const float4*)sh_down, (float4*)shdr);

    // attention branch
    rms_kernel<<<T, 256>>>(x, ln1, h1p, nullptr, nullptr);
    gemm_tc<<<dim3(H/64, T/64, 3), 128>>>(h1p, H, 0, wqr, wkr, wvr, H, 0, 0,
                                          qp, kp, vp, H, 0, nullptr, 0,
                                          H, 1.f, 0, 0);
    rope_kernel<<<T, 256>>>();
    gemm_tc<<<dim3(T/64, T/64, NH), 128>>>(qp, H, HD, kp, nullptr, nullptr, H, HD, 1,
                                           scoresp, nullptr, nullptr, T, (long)T*T, nullptr, 0,
                                           HD, inv_sqrt_hd, 1, 0);
    attn_softmax<<<dim3(T, NH), 256>>>();
    gemm_tc<<<dim3(HD/64, T/64, NH), 128>>>(scoresp, T, (long)T*T, vp, nullptr, nullptr, H, HD, 0,
                                            attnp, nullptr, nullptr, H, HD, nullptr, 0,
                                            T, 1.f, 2, 1);
    gemm_tc<<<dim3(H/64, T/64, 1), 128>>>(attnp, H, 0, wor, nullptr, nullptr, H, 0, 0,
                                          hresp, nullptr, nullptr, H, 0, x, 0,
                                          H, 1.f, 0, 0);

    // MoE branch
    rms_kernel<<<T, 256>>>(hresp, ln2, h2p, h2up, h2bp);
    transpose_eb<<<dim3(EI/32, H/2), 256>>>(gpe, gpeBp, H, EI);
    transpose_eb<<<dim3(EI/32, H/2), 256>>>(upe, upeBp, H, EI);
    transpose_eb<<<dim3(H/32, EI/2), 256>>>(dpe, dpeBp, EI, H);
    zero_cnt_kernel<<<1, 64>>>();
    router_kernel<<<T, 64>>>(gate_w);
    prefix_kernel<<<1, 32>>>();
    scatter_kernel<<<(NPAIR + 255)/256, 256>>>();
    moe_pass1<<<dim3(EI/64, T/128, NEXP), 256>>>();
    moe_pass2<<<dim3(H/64, T/128, NEXP), 128>>>();

    // shared FFN (tf32)
    gemm_tc<<<dim3(SHF/64, T/64, 2), 128>>>(h2p, H, 0, shgr, shur, nullptr, SHF, 0, 0,
                                            sgp, sup, nullptr, SHF, 0, nullptr, 0,
                                            H, 1.f, 0, 0);
    silumul_kernel<<<(T*SHF + 255)/256, 256>>>(sgp, sup, T*SHF);
    gemm_tc<<<dim3(H/64, T/64, 1), 128>>>(sgp, SHF, 0, shdr, nullptr, nullptr, H, 0, 0,
                                          sharedp, nullptr, nullptr, H, 0, nullptr, 0,
                                          SHF, 1.f, 0, 0);

    // combine
    combine_kernel<<<T, 256>>>(out);
}

// round 9
// speedup vs baseline: 1.1621x; 1.0884x over previous
#include <cuda_runtime.h>
#include <cuda_bf16.h>
#include <math.h>

#define T 1024
#define H 1280
#define NH 10
#define HD 128
#define EI 896
#define NEXP 64
#define TOPK 6
#define SHF 1792
#define NPAIR (T*TOPK)

// ---------------- device scratch ----------------
static __device__ float g_h1[T*H];
static __device__ float g_q[T*H];
static __device__ float g_k[T*H];
static __device__ float g_v[T*H];
static __device__ float g_scores[NH*T*T];
static __device__ float g_attnout[T*H];
static __device__ float g_hres[T*H];
static __device__ float g_h2[T*H];              // tf32-rounded fp32 (shared FFN)
static __device__ float g_h2u[T*H];             // unrounded fp32 (router)
static __device__ __nv_bfloat16 g_h2b[T*H];     // bf16 (MoE pass1 A)
static __device__ float g_sg[T*SHF];
static __device__ float g_su[T*SHF];
static __device__ float g_shared[T*H];
// bf16 expert weights, [e][k][n] plain bf16
static __device__ __nv_bfloat16 g_gpeB[(size_t)NEXP*H*EI];
static __device__ __nv_bfloat16 g_upeB[(size_t)NEXP*H*EI];
static __device__ __nv_bfloat16 g_dpeB[(size_t)NEXP*EI*H];
static __device__ __nv_bfloat16 g_actB[(size_t)(NPAIR+128)*EI];
static __device__ float g_pairout[(size_t)NPAIR*H];
// rounded fp32 weight copies (tf32 GEMMs)
static __device__ float g_WqR[H*NH*HD];
static __device__ float g_WkR[H*NH*HD];
static __device__ float g_WvR[H*NH*HD];
static __device__ float g_WoR[NH*HD*H];
static __device__ float g_shgR[H*SHF];
static __device__ float g_shuR[H*SHF];
static __device__ float g_shdR[SHF*H];
static __device__ int   g_cnt[NEXP];
static __device__ int   g_off[NEXP];
static __device__ int   g_cur[NEXP];
static __device__ int   g_tokE[NPAIR];
static __device__ float g_tokW[NPAIR];
static __device__ int   g_pairTok[NPAIR];
static __device__ float g_pairW[NPAIR];
static __device__ int   g_pairPos[NPAIR];

// ---------------- helpers ----------------
__device__ __forceinline__ void mma_tf32(float4& c, const unsigned a[4], const unsigned b[2]) {
    asm volatile("mma.sync.aligned.m16n8k8.row.col.f32.tf32.tf32.f32 "
        "{%0,%1,%2,%3}, {%4,%5,%6,%7}, {%8,%9}, {%0,%1,%2,%3};"
        : "+f"(c.x), "+f"(c.y), "+f"(c.z), "+f"(c.w)
        : "r"(a[0]), "r"(a[1]), "r"(a[2]), "r"(a[3]), "r"(b[0]), "r"(b[1]));
}
__device__ __forceinline__ void mma_bf16(float4& c, const unsigned a[4], const unsigned b[2]) {
    asm volatile("mma.sync.aligned.m16n8k16.row.col.f32.bf16.bf16.f32 "
        "{%0,%1,%2,%3}, {%4,%5,%6,%7}, {%8,%9}, {%0,%1,%2,%3};"
        : "+f"(c.x), "+f"(c.y), "+f"(c.z), "+f"(c.w)
        : "r"(a[0]), "r"(a[1]), "r"(a[2]), "r"(a[3]), "r"(b[0]), "r"(b[1]));
}
__device__ __forceinline__ float rtf(float f) {
    unsigned r; asm("cvt.rna.tf32.f32 %0, %1;" : "=r"(r) : "f"(f));
    return __uint_as_float(r);
}
__device__ __forceinline__ void cp16(const void* smem, const void* gmem) {
    unsigned sa = (unsigned)__cvta_generic_to_shared(smem);
    asm volatile("cp.async.cg.shared.global [%0], [%1], 16;" :: "r"(sa), "l"(gmem));
}
__device__ __forceinline__ void ldsm4(unsigned& r0, unsigned& r1, unsigned& r2, unsigned& r3,
                                      unsigned addr) {
    asm volatile("ldmatrix.sync.aligned.m8n8.x4.shared.b16 {%0,%1,%2,%3}, [%4];"
        : "=r"(r0), "=r"(r1), "=r"(r2), "=r"(r3) : "r"(addr));
}
__device__ __forceinline__ void ldsm4t(unsigned& r0, unsigned& r1, unsigned& r2, unsigned& r3,
                                       unsigned addr) {
    asm volatile("ldmatrix.sync.aligned.m8n8.x4.trans.shared.b16 {%0,%1,%2,%3}, [%4];"
        : "=r"(r0), "=r"(r1), "=r"(r2), "=r"(r3) : "r"(addr));
}
#define CP_COMMIT asm volatile("cp.async.commit_group;")
#define CP_WAIT1  asm volatile("cp.async.wait_group 1;")

#define AST 36    // tf32 A/transB row stride (32k + 4 pad) words
#define BST 72    // tf32 B row stride (64n + 8 pad) words

// ---------------- fused weight rounding (all 7 to tf32 fp32 copies) ------------------
__global__ void round_all(const float4* w0, float4* o0, const float4* w1, float4* o1,
                          const float4* w2, float4* o2, const float4* w3, float4* o3,
                          const float4* w4, float4* o4, const float4* w5, float4* o5,
                          const float4* w6, float4* o6) {
    int z = blockIdx.y;
    const float4* in; float4* out; int n4;
    switch (z) {
        case 0: in = w0; out = o0; n4 = H*NH*HD/4; break;
        case 1: in = w1; out = o1; n4 = H*NH*HD/4; break;
        case 2: in = w2; out = o2; n4 = H*NH*HD/4; break;
        case 3: in = w3; out = o3; n4 = H*NH*HD/4; break;
        case 4: in = w4; out = o4; n4 = H*SHF/4; break;
        case 5: in = w5; out = o5; n4 = H*SHF/4; break;
        default: in = w6; out = o6; n4 = SHF*H/4; break;
    }
    int i = blockIdx.x*256 + threadIdx.x;
    if (i < n4) {
        float4 v = in[i];
        v.x = rtf(v.x); v.y = rtf(v.y); v.z = rtf(v.z); v.w = rtf(v.w);
        out[i] = v;
    }
}

// ---------------- RMSNorm ----------------
__global__ void rms_kernel(const float* __restrict__ x, const float* __restrict__ w,
                           float* __restrict__ out, float* __restrict__ outu,
                           __nv_bfloat16* __restrict__ outb) {
    int t = blockIdx.x;
    const float* xr = x + (long)t*H;
    __shared__ float red[256];
    float s = 0.f;
    for (int i = threadIdx.x; i < H; i += 256) { float v = xr[i]; s += v*v; }
    red[threadIdx.x] = s; __syncthreads();
    for (int k = 128; k > 0; k >>= 1) {
        if (threadIdx.x < k) red[threadIdx.x] += red[threadIdx.x + k];
        __syncthreads();
    }
    float r = rsqrtf(red[0]/(float)H + 1e-6f);
    for (int i = threadIdx.x; i < H; i += 256) {
        float v = w[i]*xr[i]*r;
        out[(long)t*H + i] = rtf(v);
        if (outu) outu[(long)t*H + i] = v;
        if (outb) outb[(long)t*H + i] = __float2bfloat16(v);
    }
}

// ---------------- tf32 GEMM (R3-proven core): 64x64, BK32, 2-stage, 128 thr ----------
// mode: 0 none, 1 causal block skip, 2 K capped at m0+64.
__global__ void __launch_bounds__(128)
gemm_tc(const float* __restrict__ A, int lda, long sA,
        const float* __restrict__ B, const float* __restrict__ Bb, const float* __restrict__ Bc,
        int ldb, long sB, int transB,
        float* __restrict__ C, float* __restrict__ Cb, float* __restrict__ Cc,
        int ldc, long sC,
        const float* __restrict__ res, long sR,
        int K, float alpha, int mode, int roundC) {
    int m0 = blockIdx.y*64, n0 = blockIdx.x*64;
    if (mode == 1 && n0 >= m0 + 64) return;
    int bz = blockIdx.z;
    A += (long)bz*sA;
    if (Bb) {
        if (bz == 1) { B = Bb; C = Cb; }
        else if (bz == 2) { B = Bc; C = Cc; }
    } else {
        B += (long)bz*sB; C += (long)bz*sC; if (res) res += (long)bz*sR;
    }
    int Klim = (mode == 2) ? (m0 + 64 < K ? m0 + 64 : K) : K;

    __shared__ float As[2][64*AST];
    __shared__ float Bs[2][2304];
    int tid = threadIdx.x;
    int lane = tid & 31, warpId = tid >> 5;
    int g = lane >> 2, tig = lane & 3;
    int warp_m = (warpId & 1) * 32, warp_n = (warpId >> 1) * 32;
    float4 acc[2][4];
    #pragma unroll
    for (int i = 0; i < 2; i++)
        #pragma unroll
        for (int j = 0; j < 4; j++) acc[i][j] = make_float4(0.f,0.f,0.f,0.f);

#define G_LOAD(sidx, k0v) do { int _k0 = (k0v); if (_k0 < Klim) { \
    _Pragma("unroll") for (int i = 0; i < 4; i++) { int idx = tid + i*128; int r = idx >> 3, c4 = (idx & 7) << 2; \
        cp16(&As[sidx][r*AST + c4], &A[(long)(m0+r)*lda + _k0 + c4]); } \
    if (!transB) { \
        _Pragma("unroll") for (int i = 0; i < 4; i++) { int idx = tid + i*128; int r = idx >> 4, c4 = (idx & 15) << 2; \
            cp16(&Bs[sidx][r*BST + c4], &B[(long)(_k0+r)*ldb + n0 + c4]); } \
    } else { \
        _Pragma("unroll") for (int i = 0; i < 4; i++) { int idx = tid + i*128; int r = idx >> 3, c4 = (idx & 7) << 2; \
            cp16(&Bs[sidx][r*AST + c4], &B[(long)(n0+r)*ldb + _k0 + c4]); } \
    } } CP_COMMIT; } while(0)

    int nIter = Klim >> 5;
    G_LOAD(0, 0);
    for (int it = 0; it < nIter; it++) {
        int s = it & 1;
        G_LOAD(s ^ 1, (it + 1) << 5);
        CP_WAIT1;
        __syncthreads();
        #pragma unroll
        for (int kk = 0; kk < 32; kk += 8) {
            unsigned a[2][4], b[4][2];
            #pragma unroll
            for (int mi = 0; mi < 2; mi++) {
                const float* ap = &As[s][(warp_m + mi*16 + g)*AST + kk + tig];
                a[mi][0] = __float_as_uint(ap[0]);
                a[mi][1] = __float_as_uint(ap[8*AST]);
                a[mi][2] = __float_as_uint(ap[4]);
                a[mi][3] = __float_as_uint(ap[8*AST + 4]);
            }
            if (!transB) {
                #pragma unroll
                for (int ni = 0; ni < 4; ni++) {
                    int col = warp_n + ni*8 + g;
                    b[ni][0] = __float_as_uint(Bs[s][(kk+tig)*BST + col]);
                    b[ni][1] = __float_as_uint(Bs[s][(kk+tig+4)*BST + col]);
                }
            } else {
                #pragma unroll
                for (int ni = 0; ni < 4; ni++) {
                    const float* bp = &Bs[s][(warp_n + ni*8 + g)*AST + kk + tig];
                    b[ni][0] = __float_as_uint(bp[0]);
                    b[ni][1] = __float_as_uint(bp[4]);
                }
            }
            #pragma unroll
            for (int mi = 0; mi < 2; mi++)
                #pragma unroll
                for (int ni = 0; ni < 4; ni++) mma_tf32(acc[mi][ni], a[mi], b[ni]);
        }
        __syncthreads();
    }
#undef G_LOAD
    #pragma unroll
    for (int mi = 0; mi < 2; mi++) {
        #pragma unroll
        for (int ni = 0; ni < 4; ni++) {
            int row = m0 + warp_m + mi*16 + g;
            int col = n0 + warp_n + ni*8 + 2*tig;
            float4 c = acc[mi][ni];
            float2 v0 = { alpha*c.x, alpha*c.y };
            float2 v1 = { alpha*c.z, alpha*c.w };
            if (res) {
                float2 r0 = *(const float2*)&res[(long)row*ldc + col];
                float2 r1 = *(const float2*)&res[(long)(row+8)*ldc + col];
                v0.x += r0.x; v0.y += r0.y; v1.x += r1.x; v1.y += r1.y;
            }
            if (roundC) {
                v0.x = rtf(v0.x); v0.y = rtf(v0.y);
                v1.x = rtf(v1.x); v1.y = rtf(v1.y);
            }
            *(float2*)&C[(long)row*ldc + col] = v0;
            *(float2*)&C[(long)(row+8)*ldc + col] = v1;
        }
    }
}

// ---------------- RoPE (rounds q,k,v) ----------------
__global__ void rope_kernel() {
    int t = blockIdx.x, tid = threadIdx.x;
    __shared__ float cs[64], sn[64];
    if (tid < 64) {
        float inv = powf(10000.0f, -(float)tid / 64.0f);
        float fr = (float)t * inv;
        cs[tid] = cosf(fr); sn[tid] = sinf(fr);
    }
    __syncthreads();
    for (int idx = tid; idx < NH*64; idx += 256) {
        int hh = idx >> 6, j = idx & 63;
        long b = (long)t*H + hh*HD;
        float c = cs[j], s = sn[j];
        float q1 = g_q[b+j], q2 = g_q[b+j+64];
        g_q[b+j]    = rtf(q1*c - q2*s);
        g_q[b+j+64] = rtf(q2*c + q1*s);
        float k1 = g_k[b+j], k2 = g_k[b+j+64];
        g_k[b+j]    = rtf(k1*c - k2*s);
        g_k[b+j+64] = rtf(k2*c + k1*s);
    }
    for (int i = tid; i < H; i += 256) {
        long b = (long)t*H + i;
        g_v[b] = rtf(g_v[b]);
    }
}

// ---------------- causal softmax (zeros to next 64-boundary) ----------------
__global__ void attn_softmax() {
    int t = blockIdx.x, hh = blockIdx.y, tid = threadIdx.x;
    float* row = g_scores + ((long)hh*T + t)*(long)T;
    int len = t + 1;
    int zend = ((t >> 6) + 1) << 6;
    __shared__ float red[256];
    float mx = -3.0e38f;
    for (int i = tid; i < len; i += 256) mx = fmaxf(mx, row[i]);
    red[tid] = mx; __syncthreads();
    for (int s = 128; s > 0; s >>= 1) { if (tid < s) red[tid] = fmaxf(red[tid], red[tid+s]); __syncthreads(); }
    mx = red[0]; __syncthreads();
    float sum = 0.f;
    for (int i = tid; i < len; i += 256) { float e = __expf(row[i]-mx); row[i] = e; sum += e; }
    red[tid] = sum; __syncthreads();
    for (int s = 128; s > 0; s >>= 1) { if (tid < s) red[tid] += red[tid+s]; __syncthreads(); }
    float inv = 1.0f / red[0];
    for (int i = tid; i < len; i += 256) row[i] = rtf(row[i] * inv);
    for (int i = len + tid; i < zend; i += 256) row[i] = 0.f;
}

// ------- expert transpose -> plain bf16 [e][k][n]: in[R][C][64] fp32 ------------------
__global__ void transpose_eb(const float* __restrict__ in, unsigned* __restrict__ out,
                             int R, int C) {
    int r0 = blockIdx.y * 2, c0 = blockIdx.x * 32;
    __shared__ float tile[2][32][65];
    for (int i = threadIdx.x; i < 4096; i += 256) {
        int r = i >> 11, rem = i & 2047, ci = rem >> 6, e = rem & 63;
        tile[r][ci][e] = in[((long)(r0+r)*C + c0+ci)*64 + e];
    }
    __syncthreads();
    int C2 = C >> 1;
    long RC2 = (long)R*C2;
    for (int j = threadIdx.x; j < 2048; j += 256) {
        int e = j >> 5, rem = j & 31, r = rem >> 4, cp = rem & 15;
        __nv_bfloat162 v = __floats2bfloat162_rn(tile[r][2*cp][e], tile[r][2*cp+1][e]);
        out[(long)e*RC2 + (long)(r0+r)*C2 + (c0 >> 1) + cp] = *(unsigned*)&v;
    }
}

// ---------------- router ----------------
__global__ void zero_cnt_kernel() { if (threadIdx.x < NEXP) g_cnt[threadIdx.x] = 0; }

__global__ void router_kernel(const float* __restrict__ gw) {
    int t = blockIdx.x, e = threadIdx.x;
    const float* hr = g_h2u + (long)t*H;
    float s = 0.f;
    for (int h = 0; h < H; h++) s += hr[h] * gw[h*NEXP + e];
    __shared__ float probs[NEXP];
    probs[e] = s;
    __syncthreads();
    if (e == 0) {
        float mx = -3e38f;
        for (int i = 0; i < NEXP; i++) mx = fmaxf(mx, probs[i]);
        float sum = 0.f;
        for (int i = 0; i < NEXP; i++) { probs[i] = __expf(probs[i]-mx); sum += probs[i]; }
        float inv = 1.f/sum;
        for (int i = 0; i < NEXP; i++) probs[i] *= inv;
        int ti[TOPK]; float tw[TOPK]; float ws = 0.f;
        for (int j = 0; j < TOPK; j++) {
            int bi = 0; float bv = -1.f;
            for (int i = 0; i < NEXP; i++) if (probs[i] > bv) { bv = probs[i]; bi = i; }
            ti[j] = bi; tw[j] = bv; ws += bv; probs[bi] = -2.f;
        }
        float wi = 1.f/ws;
        for (int j = 0; j < TOPK; j++) {
            g_tokE[t*TOPK+j] = ti[j];
            g_tokW[t*TOPK+j] = tw[j]*wi;
            atomicAdd(&g_cnt[ti[j]], 1);
        }
    }
}

__global__ void prefix_kernel() {
    if (threadIdx.x == 0) {
        int s = 0;
        for (int e = 0; e < NEXP; e++) { g_off[e] = s; g_cur[e] = s; s += g_cnt[e]; }
    }
}

__global__ void scatter_kernel() {
    int i = blockIdx.x*256 + threadIdx.x;
    if (i < NPAIR) {
        int e = g_tokE[i];
        int pos = atomicAdd(&g_cur[e], 1);
        g_pairTok[pos] = i / TOPK;
        g_pairW[pos]   = g_tokW[i];
        g_pairPos[i]   = pos;
    }
}

// -------- bf16 dual GEMM + SiLU epilogue (MoE pass1): CTA 128x64, 256 thr, LDSM -------
__global__ void __launch_bounds__(256)
gemm_bf16_dual(const __nv_bfloat16* __restrict__ A, int lda,
               const __nv_bfloat16* __restrict__ B1g, const __nv_bfloat16* __restrict__ B2g,
               long sB, int ldb,
               __nv_bfloat16* __restrict__ Cout, int ldc,
               int K) {
    int e = blockIdx.z;
    int m0 = blockIdx.y * 128;
    int cnt = g_cnt[e], base = g_off[e];
    if (m0 >= cnt) return;
    const __nv_bfloat16* B1 = B1g + (long)e*sB;
    const __nv_bfloat16* B2 = B2g + (long)e*sB;
    int n0 = blockIdx.x * 64;

    __shared__ int stok[128];
    __shared__ unsigned As[3][128][12];    // 48B rows: 16 bf16 + 16B pad
    __shared__ unsigned Bs1[3][16][36];    // 144B rows: 64 bf16 + 16B pad
    __shared__ unsigned Bs2[3][16][36];
    int tid = threadIdx.x;
    int lane = tid & 31, warpId = tid >> 5;
    int g = lane >> 2, tig = lane & 3;
    int warp_m = (warpId & 3) * 32, warp_n = (warpId >> 2) * 32;
    if (tid < 128) stok[tid] = (m0 + tid < cnt) ? g_pairTok[base + m0 + tid] : 0;
    __syncthreads();
    float4 accG[2][4], accU[2][4];
    #pragma unroll
    for (int i = 0; i < 2; i++)
        #pragma unroll
        for (int j = 0; j < 4; j++) { accG[i][j] = make_float4(0,0,0,0); accU[i][j] = make_float4(0,0,0,0); }

#define D_LOAD(sidx, k0v) do { int _k0 = (k0v); if (_k0 < K) { \
    { int r = tid >> 1, ch = tid & 1; \
      cp16(&As[sidx][r][ch*4], &A[(long)stok[r]*lda + _k0 + ch*8]); } \
    if (tid < 128) { int r = tid >> 3, ch = tid & 7; \
      cp16(&Bs1[sidx][r][ch*4], &B1[(long)(_k0+r)*ldb + n0 + ch*8]); } \
    else { int t2 = tid - 128; int r = t2 >> 3, ch = t2 & 7; \
      cp16(&Bs2[sidx][r][ch*4], &B2[(long)(_k0+r)*ldb + n0 + ch*8]); } \
    } CP_COMMIT; } while(0)

    const int nIter = K >> 4;
    D_LOAD(0, 0);
    D_LOAD(1, 16);
    int st = 0;
    int half16 = (lane >> 4) * 16;
    for (int it = 0; it < nIter; it++) {
        CP_WAIT1;
        __syncthreads();
        unsigned aBase = (unsigned)__cvta_generic_to_shared(&As[st][0][0]);
        unsigned b1Base = (unsigned)__cvta_generic_to_shared(&Bs1[st][0][0]);
        unsigned b2Base = (unsigned)__cvta_generic_to_shared(&Bs2[st][0][0]);
        unsigned a[2][4], b1[4][2], b2[4][2];
        #pragma unroll
        for (int mi = 0; mi < 2; mi++) {
            int row = warp_m + mi*16 + (lane & 15);
            ldsm4(a[mi][0], a[mi][1], a[mi][2], a[mi][3], aBase + row*48 + half16);
        }
        #pragma unroll
        for (int nh = 0; nh < 2; nh++) {
            int krow = lane & 15;
            int col = warp_n + nh*16 + (lane >> 4) * 8;
            ldsm4t(b1[nh*2][0], b1[nh*2][1], b1[nh*2+1][0], b1[nh*2+1][1],
                   b1Base + krow*144 + col*2);
            ldsm4t(b2[nh*2][0], b2[nh*2][1], b2[nh*2+1][0], b2[nh*2+1][1],
                   b2Base + krow*144 + col*2);
        }
        #pragma unroll
        for (int mi = 0; mi < 2; mi++)
            #pragma unroll
            for (int ni = 0; ni < 4; ni++) {
                mma_bf16(accG[mi][ni], a[mi], b1[ni]);
                mma_bf16(accU[mi][ni], a[mi], b2[ni]);
            }
        int wst = st + 2; if (wst >= 3) wst -= 3;
        D_LOAD(wst, (it + 2) << 4);
        if (++st == 3) st = 0;
    }
#undef D_LOAD
    #pragma unroll
    for (int mi = 0; mi < 2; mi++) {
        #pragma unroll
        for (int ni = 0; ni < 4; ni++) {
            int mrow = warp_m + mi*16 + g;
            int col = n0 + warp_n + ni*8 + 2*tig;
            float4 cg = accG[mi][ni], cu = accU[mi][ni];
            if (m0 + mrow < cnt) {
                float g0 = cg.x, g1 = cg.y;
                __nv_bfloat162 v = __floats2bfloat162_rn((g0/(1.f+__expf(-g0)))*cu.x,
                                                         (g1/(1.f+__expf(-g1)))*cu.y);
                *(__nv_bfloat162*)&Cout[(long)(base+m0+mrow)*ldc + col] = v;
            }
            if (m0 + mrow + 8 < cnt) {
                float g0 = cg.z, g1 = cg.w;
                __nv_bfloat162 v = __floats2bfloat162_rn((g0/(1.f+__expf(-g0)))*cu.z,
                                                         (g1/(1.f+__expf(-g1)))*cu.w);
                *(__nv_bfloat162*)&Cout[(long)(base+m0+mrow+8)*ldc + col] = v;
            }
        }
    }
}

// -------- bf16 single GEMM (MoE pass2): CTA 128x64, 128 thr, warp 64x32, LDSM --------
__global__ void __launch_bounds__(128)
gemm_bf16_one(const __nv_bfloat16* __restrict__ A, int lda,
              const __nv_bfloat16* __restrict__ Bg, long sB, int ldb,
              float* __restrict__ Cout, int ldc,
              int K) {
    int e = blockIdx.z;
    int m0 = blockIdx.y * 128;
    int cnt = g_cnt[e], base = g_off[e];
    if (m0 >= cnt) return;
    const __nv_bfloat16* B = Bg + (long)e*sB;
    int n0 = blockIdx.x * 64;

    __shared__ unsigned As[3][128][12];
    __shared__ unsigned Bs[3][16][36];
    int tid = threadIdx.x;
    int lane = tid & 31, warpId = tid >> 5;
    int g = lane >> 2, tig = lane & 3;
    int warp_m = (warpId & 1) * 64, warp_n = (warpId >> 1) * 32;
    float4 acc[4][4];
    #pragma unroll
    for (int i = 0; i < 4; i++)
        #pragma unroll
        for (int j = 0; j < 4; j++) acc[i][j] = make_float4(0,0,0,0);

#define S_LOAD(sidx, k0v) do { int _k0 = (k0v); if (_k0 < K) { \
    _Pragma("unroll") for (int i = 0; i < 2; i++) { int idx = tid + i*128; int r = idx >> 1, ch = idx & 1; \
      int rr = m0 + r; if (rr >= cnt) rr = cnt - 1; \
      cp16(&As[sidx][r][ch*4], &A[(long)(base + rr)*lda + _k0 + ch*8]); } \
    { int r = tid >> 3, ch = tid & 7; \
      cp16(&Bs[sidx][r][ch*4], &B[(long)(_k0+r)*ldb + n0 + ch*8]); } \
    } CP_COMMIT; } while(0)

    const int nIter = K >> 4;
    S_LOAD(0, 0);
    S_LOAD(1, 16);
    int st = 0;
    int half16 = (lane >> 4) * 16;
    for (int it = 0; it < nIter; it++) {
        CP_WAIT1;
        __syncthreads();
        unsigned aBase = (unsigned)__cvta_generic_to_shared(&As[st][0][0]);
        unsigned bBase = (unsigned)__cvta_generic_to_shared(&Bs[st][0][0]);
        unsigned a[4][4], b[4][2];
        #pragma unroll
        for (int mi = 0; mi < 4; mi++) {
            int row = warp_m + mi*16 + (lane & 15);
            ldsm4(a[mi][0], a[mi][1], a[mi][2], a[mi][3], aBase + row*48 + half16);
        }
        #pragma unroll
        for (int nh = 0; nh < 2; nh++) {
            int krow = lane & 15;
            int col = warp_n + nh*16 + (lane >> 4) * 8;
            ldsm4t(b[nh*2][0], b[nh*2][1], b[nh*2+1][0], b[nh*2+1][1],
                   bBase + krow*144 + col*2);
        }
        #pragma unroll
        for (int mi = 0; mi < 4; mi++)
            #pragma unroll
            for (int ni = 0; ni < 4; ni++) mma_bf16(acc[mi][ni], a[mi], b[ni]);
        int wst = st + 2; if (wst >= 3) wst -= 3;
        S_LOAD(wst, (it + 2) << 4);
        if (++st == 3) st = 0;
    }
#undef S_LOAD
    #pragma unroll
    for (int mi = 0; mi < 4; mi++) {
        #pragma unroll
        for (int ni = 0; ni < 4; ni++) {
            int mrow = warp_m + mi*16 + g;
            int col = n0 + warp_n + ni*8 + 2*tig;
            float4 c = acc[mi][ni];
            if (m0 + mrow < cnt)
                *(float2*)&Cout[(long)(base+m0+mrow)*ldc + col] = make_float2(c.x, c.y);
            if (m0 + mrow + 8 < cnt)
                *(float2*)&Cout[(long)(base+m0+mrow+8)*ldc + col] = make_float2(c.z, c.w);
        }
    }
}

// ---------------- shared-FFN activation (tf32 path, rounds output) ----------------
__global__ void silumul_kernel(float* __restrict__ g, const float* __restrict__ u, int n) {
    int i = blockIdx.x*256 + threadIdx.x;
    if (i < n) {
        float x = g[i];
        g[i] = rtf((x / (1.f + __expf(-x))) * u[i]);
    }
}

// ---------------- final combine ----------------
__global__ void combine_kernel(float* __restrict__ out) {
    int t = blockIdx.x;
    int pos[TOPK]; float w[TOPK];
    #pragma unroll
    for (int j = 0; j < TOPK; j++) {
        pos[j] = g_pairPos[t*TOPK + j];
        w[j]   = g_pairW[pos[j]];
    }
    for (int h = threadIdx.x; h < H; h += 256) {
        float s = g_hres[(long)t*H + h] + g_shared[(long)t*H + h];
        #pragma unroll
        for (int j = 0; j < TOPK; j++)
            s += w[j] * g_pairout[(long)pos[j]*H + h];
        out[(long)t*H + h] = s;
    }
}

// ---------------- launch ----------------
extern "C" void kernel_launch(void* const* d_in, const int* in_sizes, int n_in,
                              void* d_out, int out_size) {
    (void)in_sizes; (void)n_in; (void)out_size;
    const float* x       = (const float*)d_in[0];
    const float* ln1     = (const float*)d_in[1];
    const float* ln2     = (const float*)d_in[2];
    const float* Wq      = (const float*)d_in[3];
    const float* Wk      = (const float*)d_in[4];
    const float* Wv      = (const float*)d_in[5];
    const float* Wo      = (const float*)d_in[6];
    const float* gate_w  = (const float*)d_in[7];
    const float* gpe     = (const float*)d_in[8];
    const float* upe     = (const float*)d_in[9];
    const float* dpe     = (const float*)d_in[10];
    const float* sh_gate = (const float*)d_in[11];
    const float* sh_up   = (const float*)d_in[12];
    const float* sh_down = (const float*)d_in[13];
    float* out = (float*)d_out;

    float *h1p,*qp,*kp,*vp,*scoresp,*attnp,*hresp,*h2p,*h2up,*sgp,*sup,*sharedp,*pairoutp;
    __nv_bfloat16 *h2bp,*actBp,*gpeBp,*upeBp,*dpeBp;
    float *wqr,*wkr,*wvr,*wor,*shgr,*shur,*shdr;
    cudaGetSymbolAddress((void**)&h1p,     g_h1);
    cudaGetSymbolAddress((void**)&qp,      g_q);
    cudaGetSymbolAddress((void**)&kp,      g_k);
    cudaGetSymbolAddress((void**)&vp,      g_v);
    cudaGetSymbolAddress((void**)&scoresp, g_scores);
    cudaGetSymbolAddress((void**)&attnp,   g_attnout);
    cudaGetSymbolAddress((void**)&hresp,   g_hres);
    cudaGetSymbolAddress((void**)&h2p,     g_h2);
    cudaGetSymbolAddress((void**)&h2up,    g_h2u);
    cudaGetSymbolAddress((void**)&h2bp,    g_h2b);
    cudaGetSymbolAddress((void**)&sgp,     g_sg);
    cudaGetSymbolAddress((void**)&sup,     g_su);
    cudaGetSymbolAddress((void**)&sharedp, g_shared);
    cudaGetSymbolAddress((void**)&actBp,   g_actB);
    cudaGetSymbolAddress((void**)&pairoutp,g_pairout);
    cudaGetSymbolAddress((void**)&gpeBp,   g_gpeB);
    cudaGetSymbolAddress((void**)&upeBp,   g_upeB);
    cudaGetSymbolAddress((void**)&dpeBp,   g_dpeB);
    cudaGetSymbolAddress((void**)&wqr,     g_WqR);
    cudaGetSymbolAddress((void**)&wkr,     g_WkR);
    cudaGetSymbolAddress((void**)&wvr,     g_WvR);
    cudaGetSymbolAddress((void**)&wor,     g_WoR);
    cudaGetSymbolAddress((void**)&shgr,    g_shgR);
    cudaGetSymbolAddress((void**)&shur,    g_shuR);
    cudaGetSymbolAddress((void**)&shdr,    g_shdR);

    const float inv_sqrt_hd = 0.08838834764831845f;

    // fused one-shot weight rounding (7 matrices -> tf32 fp32 copies)
    round_all<<<dim3((H*SHF/4 + 255)/256, 7), 256>>>(
        (const float4*)Wq, (float4*)wqr, (const float4*)Wk, (float4*)wkr,
        (const float4*)Wv, (float4*)wvr, (const float4*)Wo, (float4*)wor,
        (const float4*)sh_gate, (float4*)shgr, (const float4*)sh_up, (float4*)shur,
        (const float4*)sh_down, (float4*)shdr);

    // attention branch (tf32)
    rms_kernel<<<T, 256>>>(x, ln1, h1p, nullptr, nullptr);
    gemm_tc<<<dim3(H/64, T/64, 3), 128>>>(h1p, H, 0, wqr, wkr, wvr, H, 0, 0,
                                          qp, kp, vp, H, 0, nullptr, 0,
                                          H, 1.f, 0, 0);
    rope_kernel<<<T, 256>>>();
    gemm_tc<<<dim3(T/64, T/64, NH), 128>>>(qp, H, HD, kp, nullptr, nullptr, H, HD, 1,
                                           scoresp, nullptr, nullptr, T, (long)T*T, nullptr, 0,
                                           HD, inv_sqrt_hd, 1, 0);
    attn_softmax<<<dim3(T, NH), 256>>>();
    gemm_tc<<<dim3(HD/64, T/64, NH), 128>>>(scoresp, T, (long)T*T, vp, nullptr, nullptr, H, HD, 0,
                                            attnp, nullptr, nullptr, H, HD, nullptr, 0,
                                            T, 1.f, 2, 1);
    gemm_tc<<<dim3(H/64, T/64, 1), 128>>>(attnp, H, 0, wor, nullptr, nullptr, H, 0, 0,
                                          hresp, nullptr, nullptr, H, 0, x, 0,
                                          H, 1.f, 0, 0);

    // MoE branch (bf16 LDSM)
    rms_kernel<<<T, 256>>>(hresp, ln2, h2p, h2up, h2bp);
    transpose_eb<<<dim3(EI/32, H/2), 256>>>(gpe, (unsigned*)gpeBp, H, EI);
    transpose_eb<<<dim3(EI/32, H/2), 256>>>(upe, (unsigned*)upeBp, H, EI);
    transpose_eb<<<dim3(H/32, EI/2), 256>>>(dpe, (unsigned*)dpeBp, EI, H);
    zero_cnt_kernel<<<1, 64>>>();
    router_kernel<<<T, 64>>>(gate_w);
    prefix_kernel<<<1, 32>>>();
    scatter_kernel<<<(NPAIR + 255)/256, 256>>>();
    gemm_bf16_dual<<<dim3(EI/64, T/128, NEXP), 256>>>(
        h2bp, H, gpeBp, upeBp, (long)H*EI, EI, actBp, EI, H);
    gemm_bf16_one<<<dim3(H/64, T/128, NEXP), 128>>>(
        actBp, EI, dpeBp, (long)EI*H, H, pairoutp, H, EI);

    // shared FFN (tf32, proven numerics)
    gemm_tc<<<dim3(SHF/64, T/64, 2), 128>>>(h2p, H, 0, shgr, shur, nullptr, SHF, 0, 0,
                                            sgp, sup, nullptr, SHF, 0, nullptr, 0,
                                            H, 1.f, 0, 0);
    silumul_kernel<<<(T*SHF + 255)/256, 256>>>(sgp, sup, T*SHF);
    gemm_tc<<<dim3(H/64, T/64, 1), 128>>>(sgp, SHF, 0, shdr, nullptr, nullptr, H, 0, 0,
                                          sharedp, nullptr, nullptr, H, 0, nullptr, 0,
                                          SHF, 1.f, 0, 0);

    // combine
    combine_kernel<<<T, 256>>>(out);
}

// round 10
// speedup vs baseline: 1.2932x; 1.1129x over previous
#include <cuda_runtime.h>
#include <cuda_bf16.h>
#include <math.h>

#define T 1024
#define H 1280
#define NH 10
#define HD 128
#define EI 896
#define NEXP 64
#define TOPK 6
#define SHF 1792
#define NPAIR (T*TOPK)

// ---------------- device scratch ----------------
static __device__ float g_h1[T*H];
static __device__ float g_q[T*H];
static __device__ float g_k[T*H];
static __device__ float g_v[T*H];
static __device__ float g_scores[NH*T*T];
static __device__ float g_attnout[T*H];
static __device__ float g_hres[T*H];
static __device__ float g_h2[T*H];              // tf32-rounded fp32 (shared FFN)
static __device__ float g_h2u[T*H];             // unrounded fp32 (router)
static __device__ __nv_bfloat16 g_h2b[T*H];     // bf16 (MoE pass1 A)
static __device__ float g_sg[T*SHF];
static __device__ float g_su[T*SHF];
static __device__ float g_shared[T*H];
// bf16 expert weights, [e][k][n] plain bf16
static __device__ __nv_bfloat16 g_gpeB[(size_t)NEXP*H*EI];
static __device__ __nv_bfloat16 g_upeB[(size_t)NEXP*H*EI];
static __device__ __nv_bfloat16 g_dpeB[(size_t)NEXP*EI*H];
static __device__ __nv_bfloat16 g_actB[(size_t)(NPAIR+128)*EI];
static __device__ float g_pairout[(size_t)NPAIR*H];
// rounded fp32 weight copies (tf32 GEMMs)
static __device__ float g_WqR[H*NH*HD];
static __device__ float g_WkR[H*NH*HD];
static __device__ float g_WvR[H*NH*HD];
static __device__ float g_WoR[NH*HD*H];
static __device__ float g_shgR[H*SHF];
static __device__ float g_shuR[H*SHF];
static __device__ float g_shdR[SHF*H];
static __device__ int   g_cnt[NEXP];
static __device__ int   g_off[NEXP];
static __device__ int   g_cur[NEXP];
static __device__ int   g_tokE[NPAIR];
static __device__ float g_tokW[NPAIR];
static __device__ int   g_pairTok[NPAIR];
static __device__ float g_pairW[NPAIR];
static __device__ int   g_pairPos[NPAIR];

// ---------------- helpers ----------------
__device__ __forceinline__ void mma_tf32(float4& c, const unsigned a[4], const unsigned b[2]) {
    asm volatile("mma.sync.aligned.m16n8k8.row.col.f32.tf32.tf32.f32 "
        "{%0,%1,%2,%3}, {%4,%5,%6,%7}, {%8,%9}, {%0,%1,%2,%3};"
        : "+f"(c.x), "+f"(c.y), "+f"(c.z), "+f"(c.w)
        : "r"(a[0]), "r"(a[1]), "r"(a[2]), "r"(a[3]), "r"(b[0]), "r"(b[1]));
}
__device__ __forceinline__ void mma_bf16(float4& c, const unsigned a[4], const unsigned b[2]) {
    asm volatile("mma.sync.aligned.m16n8k16.row.col.f32.bf16.bf16.f32 "
        "{%0,%1,%2,%3}, {%4,%5,%6,%7}, {%8,%9}, {%0,%1,%2,%3};"
        : "+f"(c.x), "+f"(c.y), "+f"(c.z), "+f"(c.w)
        : "r"(a[0]), "r"(a[1]), "r"(a[2]), "r"(a[3]), "r"(b[0]), "r"(b[1]));
}
__device__ __forceinline__ float rtf(float f) {
    unsigned r; asm("cvt.rna.tf32.f32 %0, %1;" : "=r"(r) : "f"(f));
    return __uint_as_float(r);
}
__device__ __forceinline__ void cp16(const void* smem, const void* gmem) {
    unsigned sa = (unsigned)__cvta_generic_to_shared(smem);
    asm volatile("cp.async.cg.shared.global [%0], [%1], 16;" :: "r"(sa), "l"(gmem));
}
__device__ __forceinline__ void ldsm4(unsigned& r0, unsigned& r1, unsigned& r2, unsigned& r3,
                                      unsigned addr) {
    asm volatile("ldmatrix.sync.aligned.m8n8.x4.shared.b16 {%0,%1,%2,%3}, [%4];"
        : "=r"(r0), "=r"(r1), "=r"(r2), "=r"(r3) : "r"(addr));
}
__device__ __forceinline__ void ldsm4t(unsigned& r0, unsigned& r1, unsigned& r2, unsigned& r3,
                                       unsigned addr) {
    asm volatile("ldmatrix.sync.aligned.m8n8.x4.trans.shared.b16 {%0,%1,%2,%3}, [%4];"
        : "=r"(r0), "=r"(r1), "=r"(r2), "=r"(r3) : "r"(addr));
}
#define CP_COMMIT asm volatile("cp.async.commit_group;")
#define CP_WAIT1  asm volatile("cp.async.wait_group 1;")

#define AST 36    // tf32 A/transB row stride (32k + 4 pad) words
#define BST 72    // tf32 B row stride (64n + 8 pad) words

// ---------------- weight rounding: attention mats (z 0..3) ----------------
__global__ void round_attn(const float4* w0, float4* o0, const float4* w1, float4* o1,
                           const float4* w2, float4* o2, const float4* w3, float4* o3) {
    int z = blockIdx.y;
    const float4* in; float4* out;
    switch (z) { case 0: in=w0; out=o0; break; case 1: in=w1; out=o1; break;
                 case 2: in=w2; out=o2; break; default: in=w3; out=o3; }
    int i = blockIdx.x*256 + threadIdx.x;
    if (i < H*NH*HD/4) {
        float4 v = in[i];
        v.x = rtf(v.x); v.y = rtf(v.y); v.z = rtf(v.z); v.w = rtf(v.w);
        out[i] = v;
    }
}

// ---------------- weight rounding: shared-FFN mats (z 0..2) ----------------
__global__ void round_shared(const float4* w4, float4* o4, const float4* w5, float4* o5,
                             const float4* w6, float4* o6) {
    int z = blockIdx.y;
    const float4* in; float4* out; int n4;
    switch (z) { case 0: in=w4; out=o4; n4=H*SHF/4; break;
                 case 1: in=w5; out=o5; n4=H*SHF/4; break;
                 default: in=w6; out=o6; n4=SHF*H/4; }
    int i = blockIdx.x*256 + threadIdx.x;
    if (i < n4) {
        float4 v = in[i];
        v.x = rtf(v.x); v.y = rtf(v.y); v.z = rtf(v.z); v.w = rtf(v.w);
        out[i] = v;
    }
}

// ---------------- RMSNorm ----------------
__global__ void rms_kernel(const float* __restrict__ x, const float* __restrict__ w,
                           float* __restrict__ out, float* __restrict__ outu,
                           __nv_bfloat16* __restrict__ outb) {
    int t = blockIdx.x;
    const float* xr = x + (long)t*H;
    __shared__ float red[256];
    float s = 0.f;
    for (int i = threadIdx.x; i < H; i += 256) { float v = xr[i]; s += v*v; }
    red[threadIdx.x] = s; __syncthreads();
    for (int k = 128; k > 0; k >>= 1) {
        if (threadIdx.x < k) red[threadIdx.x] += red[threadIdx.x + k];
        __syncthreads();
    }
    float r = rsqrtf(red[0]/(float)H + 1e-6f);
    for (int i = threadIdx.x; i < H; i += 256) {
        float v = w[i]*xr[i]*r;
        out[(long)t*H + i] = rtf(v);
        if (outu) outu[(long)t*H + i] = v;
        if (outb) outb[(long)t*H + i] = __float2bfloat16(v);
    }
}

// ---------------- tf32 GEMM (R3-proven core): 64x64, BK32, 2-stage, 128 thr ----------
// mode: 0 none, 1 causal block skip, 2 K capped at m0+64.
__global__ void __launch_bounds__(128)
gemm_tc(const float* __restrict__ A, int lda, long sA,
        const float* __restrict__ B, const float* __restrict__ Bb, const float* __restrict__ Bc,
        int ldb, long sB, int transB,
        float* __restrict__ C, float* __restrict__ Cb, float* __restrict__ Cc,
        int ldc, long sC,
        const float* __restrict__ res, long sR,
        int K, float alpha, int mode, int roundC) {
    int m0 = blockIdx.y*64, n0 = blockIdx.x*64;
    if (mode == 1 && n0 >= m0 + 64) return;
    int bz = blockIdx.z;
    A += (long)bz*sA;
    if (Bb) {
        if (bz == 1) { B = Bb; C = Cb; }
        else if (bz == 2) { B = Bc; C = Cc; }
    } else {
        B += (long)bz*sB; C += (long)bz*sC; if (res) res += (long)bz*sR;
    }
    int Klim = (mode == 2) ? (m0 + 64 < K ? m0 + 64 : K) : K;

    __shared__ float As[2][64*AST];
    __shared__ float Bs[2][2304];
    int tid = threadIdx.x;
    int lane = tid & 31, warpId = tid >> 5;
    int g = lane >> 2, tig = lane & 3;
    int warp_m = (warpId & 1) * 32, warp_n = (warpId >> 1) * 32;
    float4 acc[2][4];
    #pragma unroll
    for (int i = 0; i < 2; i++)
        #pragma unroll
        for (int j = 0; j < 4; j++) acc[i][j] = make_float4(0.f,0.f,0.f,0.f);

#define G_LOAD(sidx, k0v) do { int _k0 = (k0v); if (_k0 < Klim) { \
    _Pragma("unroll") for (int i = 0; i < 4; i++) { int idx = tid + i*128; int r = idx >> 3, c4 = (idx & 7) << 2; \
        cp16(&As[sidx][r*AST + c4], &A[(long)(m0+r)*lda + _k0 + c4]); } \
    if (!transB) { \
        _Pragma("unroll") for (int i = 0; i < 4; i++) { int idx = tid + i*128; int r = idx >> 4, c4 = (idx & 15) << 2; \
            cp16(&Bs[sidx][r*BST + c4], &B[(long)(_k0+r)*ldb + n0 + c4]); } \
    } else { \
        _Pragma("unroll") for (int i = 0; i < 4; i++) { int idx = tid + i*128; int r = idx >> 3, c4 = (idx & 7) << 2; \
            cp16(&Bs[sidx][r*AST + c4], &B[(long)(n0+r)*ldb + _k0 + c4]); } \
    } } CP_COMMIT; } while(0)

    int nIter = Klim >> 5;
    G_LOAD(0, 0);
    for (int it = 0; it < nIter; it++) {
        int s = it & 1;
        G_LOAD(s ^ 1, (it + 1) << 5);
        CP_WAIT1;
        __syncthreads();
        #pragma unroll
        for (int kk = 0; kk < 32; kk += 8) {
            unsigned a[2][4], b[4][2];
            #pragma unroll
            for (int mi = 0; mi < 2; mi++) {
                const float* ap = &As[s][(warp_m + mi*16 + g)*AST + kk + tig];
                a[mi][0] = __float_as_uint(ap[0]);
                a[mi][1] = __float_as_uint(ap[8*AST]);
                a[mi][2] = __float_as_uint(ap[4]);
                a[mi][3] = __float_as_uint(ap[8*AST + 4]);
            }
            if (!transB) {
                #pragma unroll
                for (int ni = 0; ni < 4; ni++) {
                    int col = warp_n + ni*8 + g;
                    b[ni][0] = __float_as_uint(Bs[s][(kk+tig)*BST + col]);
                    b[ni][1] = __float_as_uint(Bs[s][(kk+tig+4)*BST + col]);
                }
            } else {
                #pragma unroll
                for (int ni = 0; ni < 4; ni++) {
                    const float* bp = &Bs[s][(warp_n + ni*8 + g)*AST + kk + tig];
                    b[ni][0] = __float_as_uint(bp[0]);
                    b[ni][1] = __float_as_uint(bp[4]);
                }
            }
            #pragma unroll
            for (int mi = 0; mi < 2; mi++)
                #pragma unroll
                for (int ni = 0; ni < 4; ni++) mma_tf32(acc[mi][ni], a[mi], b[ni]);
        }
        __syncthreads();
    }
#undef G_LOAD
    #pragma unroll
    for (int mi = 0; mi < 2; mi++) {
        #pragma unroll
        for (int ni = 0; ni < 4; ni++) {
            int row = m0 + warp_m + mi*16 + g;
            int col = n0 + warp_n + ni*8 + 2*tig;
            float4 c = acc[mi][ni];
            float2 v0 = { alpha*c.x, alpha*c.y };
            float2 v1 = { alpha*c.z, alpha*c.w };
            if (res) {
                float2 r0 = *(const float2*)&res[(long)row*ldc + col];
                float2 r1 = *(const float2*)&res[(long)(row+8)*ldc + col];
                v0.x += r0.x; v0.y += r0.y; v1.x += r1.x; v1.y += r1.y;
            }
            if (roundC) {
                v0.x = rtf(v0.x); v0.y = rtf(v0.y);
                v1.x = rtf(v1.x); v1.y = rtf(v1.y);
            }
            *(float2*)&C[(long)row*ldc + col] = v0;
            *(float2*)&C[(long)(row+8)*ldc + col] = v1;
        }
    }
}

// ---------------- RoPE (rounds q,k,v) ----------------
__global__ void rope_kernel() {
    int t = blockIdx.x, tid = threadIdx.x;
    __shared__ float cs[64], sn[64];
    if (tid < 64) {
        float inv = powf(10000.0f, -(float)tid / 64.0f);
        float fr = (float)t * inv;
        cs[tid] = cosf(fr); sn[tid] = sinf(fr);
    }
    __syncthreads();
    for (int idx = tid; idx < NH*64; idx += 256) {
        int hh = idx >> 6, j = idx & 63;
        long b = (long)t*H + hh*HD;
        float c = cs[j], s = sn[j];
        float q1 = g_q[b+j], q2 = g_q[b+j+64];
        g_q[b+j]    = rtf(q1*c - q2*s);
        g_q[b+j+64] = rtf(q2*c + q1*s);
        float k1 = g_k[b+j], k2 = g_k[b+j+64];
        g_k[b+j]    = rtf(k1*c - k2*s);
        g_k[b+j+64] = rtf(k2*c + k1*s);
    }
    for (int i = tid; i < H; i += 256) {
        long b = (long)t*H + i;
        g_v[b] = rtf(g_v[b]);
    }
}

// ---------------- causal softmax (zeros to next 64-boundary) ----------------
__global__ void attn_softmax() {
    int t = blockIdx.x, hh = blockIdx.y, tid = threadIdx.x;
    float* row = g_scores + ((long)hh*T + t)*(long)T;
    int len = t + 1;
    int zend = ((t >> 6) + 1) << 6;
    __shared__ float red[256];
    float mx = -3.0e38f;
    for (int i = tid; i < len; i += 256) mx = fmaxf(mx, row[i]);
    red[tid] = mx; __syncthreads();
    for (int s = 128; s > 0; s >>= 1) { if (tid < s) red[tid] = fmaxf(red[tid], red[tid+s]); __syncthreads(); }
    mx = red[0]; __syncthreads();
    float sum = 0.f;
    for (int i = tid; i < len; i += 256) { float e = __expf(row[i]-mx); row[i] = e; sum += e; }
    red[tid] = sum; __syncthreads();
    for (int s = 128; s > 0; s >>= 1) { if (tid < s) red[tid] += red[tid+s]; __syncthreads(); }
    float inv = 1.0f / red[0];
    for (int i = tid; i < len; i += 256) row[i] = rtf(row[i] * inv);
    for (int i = len + tid; i < zend; i += 256) row[i] = 0.f;
}

// ------- expert transpose -> plain bf16 [e][k][n]: in[R][C][64] fp32 ------------------
__global__ void transpose_eb(const float* __restrict__ in, unsigned* __restrict__ out,
                             int R, int C) {
    int r0 = blockIdx.y * 2, c0 = blockIdx.x * 32;
    __shared__ float tile[2][32][65];
    for (int i = threadIdx.x; i < 4096; i += 256) {
        int r = i >> 11, rem = i & 2047, ci = rem >> 6, e = rem & 63;
        tile[r][ci][e] = in[((long)(r0+r)*C + c0+ci)*64 + e];
    }
    __syncthreads();
    int C2 = C >> 1;
    long RC2 = (long)R*C2;
    for (int j = threadIdx.x; j < 2048; j += 256) {
        int e = j >> 5, rem = j & 31, r = rem >> 4, cp = rem & 15;
        __nv_bfloat162 v = __floats2bfloat162_rn(tile[r][2*cp][e], tile[r][2*cp+1][e]);
        out[(long)e*RC2 + (long)(r0+r)*C2 + (c0 >> 1) + cp] = *(unsigned*)&v;
    }
}

// ---------------- router ----------------
__global__ void zero_cnt_kernel() { if (threadIdx.x < NEXP) g_cnt[threadIdx.x] = 0; }

__global__ void router_kernel(const float* __restrict__ gw) {
    int t = blockIdx.x, e = threadIdx.x;
    const float* hr = g_h2u + (long)t*H;
    float s = 0.f;
    for (int h = 0; h < H; h++) s += hr[h] * gw[h*NEXP + e];
    __shared__ float probs[NEXP];
    probs[e] = s;
    __syncthreads();
    if (e == 0) {
        float mx = -3e38f;
        for (int i = 0; i < NEXP; i++) mx = fmaxf(mx, probs[i]);
        float sum = 0.f;
        for (int i = 0; i < NEXP; i++) { probs[i] = __expf(probs[i]-mx); sum += probs[i]; }
        float inv = 1.f/sum;
        for (int i = 0; i < NEXP; i++) probs[i] *= inv;
        int ti[TOPK]; float tw[TOPK]; float ws = 0.f;
        for (int j = 0; j < TOPK; j++) {
            int bi = 0; float bv = -1.f;
            for (int i = 0; i < NEXP; i++) if (probs[i] > bv) { bv = probs[i]; bi = i; }
            ti[j] = bi; tw[j] = bv; ws += bv; probs[bi] = -2.f;
        }
        float wi = 1.f/ws;
        for (int j = 0; j < TOPK; j++) {
            g_tokE[t*TOPK+j] = ti[j];
            g_tokW[t*TOPK+j] = tw[j]*wi;
            atomicAdd(&g_cnt[ti[j]], 1);
        }
    }
}

__global__ void prefix_kernel() {
    if (threadIdx.x == 0) {
        int s = 0;
        for (int e = 0; e < NEXP; e++) { g_off[e] = s; g_cur[e] = s; s += g_cnt[e]; }
    }
}

__global__ void scatter_kernel() {
    int i = blockIdx.x*256 + threadIdx.x;
    if (i < NPAIR) {
        int e = g_tokE[i];
        int pos = atomicAdd(&g_cur[e], 1);
        g_pairTok[pos] = i / TOPK;
        g_pairW[pos]   = g_tokW[i];
        g_pairPos[i]   = pos;
    }
}

// -------- bf16 dual GEMM + SiLU epilogue (MoE pass1): CTA 128x64, 256 thr, LDSM -------
__global__ void __launch_bounds__(256)
gemm_bf16_dual(const __nv_bfloat16* __restrict__ A, int lda,
               const __nv_bfloat16* __restrict__ B1g, const __nv_bfloat16* __restrict__ B2g,
               long sB, int ldb,
               __nv_bfloat16* __restrict__ Cout, int ldc,
               int K) {
    int e = blockIdx.z;
    int m0 = blockIdx.y * 128;
    int cnt = g_cnt[e], base = g_off[e];
    if (m0 >= cnt) return;
    const __nv_bfloat16* B1 = B1g + (long)e*sB;
    const __nv_bfloat16* B2 = B2g + (long)e*sB;
    int n0 = blockIdx.x * 64;

    __shared__ int stok[128];
    __shared__ unsigned As[3][128][12];    // 48B rows: 16 bf16 + 16B pad
    __shared__ unsigned Bs1[3][16][36];    // 144B rows: 64 bf16 + 16B pad
    __shared__ unsigned Bs2[3][16][36];
    int tid = threadIdx.x;
    int lane = tid & 31, warpId = tid >> 5;
    int g = lane >> 2, tig = lane & 3;
    int warp_m = (warpId & 3) * 32, warp_n = (warpId >> 2) * 32;
    if (tid < 128) stok[tid] = (m0 + tid < cnt) ? g_pairTok[base + m0 + tid] : 0;
    __syncthreads();
    float4 accG[2][4], accU[2][4];
    #pragma unroll
    for (int i = 0; i < 2; i++)
        #pragma unroll
        for (int j = 0; j < 4; j++) { accG[i][j] = make_float4(0,0,0,0); accU[i][j] = make_float4(0,0,0,0); }

#define D_LOAD(sidx, k0v) do { int _k0 = (k0v); if (_k0 < K) { \
    { int r = tid >> 1, ch = tid & 1; \
      cp16(&As[sidx][r][ch*4], &A[(long)stok[r]*lda + _k0 + ch*8]); } \
    if (tid < 128) { int r = tid >> 3, ch = tid & 7; \
      cp16(&Bs1[sidx][r][ch*4], &B1[(long)(_k0+r)*ldb + n0 + ch*8]); } \
    else { int t2 = tid - 128; int r = t2 >> 3, ch = t2 & 7; \
      cp16(&Bs2[sidx][r][ch*4], &B2[(long)(_k0+r)*ldb + n0 + ch*8]); } \
    } CP_COMMIT; } while(0)

    const int nIter = K >> 4;
    D_LOAD(0, 0);
    D_LOAD(1, 16);
    int st = 0;
    int half16 = (lane >> 4) * 16;
    for (int it = 0; it < nIter; it++) {
        CP_WAIT1;
        __syncthreads();
        unsigned aBase = (unsigned)__cvta_generic_to_shared(&As[st][0][0]);
        unsigned b1Base = (unsigned)__cvta_generic_to_shared(&Bs1[st][0][0]);
        unsigned b2Base = (unsigned)__cvta_generic_to_shared(&Bs2[st][0][0]);
        unsigned a[2][4], b1[4][2], b2[4][2];
        #pragma unroll
        for (int mi = 0; mi < 2; mi++) {
            int row = warp_m + mi*16 + (lane & 15);
            ldsm4(a[mi][0], a[mi][1], a[mi][2], a[mi][3], aBase + row*48 + half16);
        }
        #pragma unroll
        for (int nh = 0; nh < 2; nh++) {
            int krow = lane & 15;
            int col = warp_n + nh*16 + (lane >> 4) * 8;
            ldsm4t(b1[nh*2][0], b1[nh*2][1], b1[nh*2+1][0], b1[nh*2+1][1],
                   b1Base + krow*144 + col*2);
            ldsm4t(b2[nh*2][0], b2[nh*2][1], b2[nh*2+1][0], b2[nh*2+1][1],
                   b2Base + krow*144 + col*2);
        }
        #pragma unroll
        for (int mi = 0; mi < 2; mi++)
            #pragma unroll
            for (int ni = 0; ni < 4; ni++) {
                mma_bf16(accG[mi][ni], a[mi], b1[ni]);
                mma_bf16(accU[mi][ni], a[mi], b2[ni]);
            }
        int wst = st + 2; if (wst >= 3) wst -= 3;
        D_LOAD(wst, (it + 2) << 4);
        if (++st == 3) st = 0;
    }
#undef D_LOAD
    #pragma unroll
    for (int mi = 0; mi < 2; mi++) {
        #pragma unroll
        for (int ni = 0; ni < 4; ni++) {
            int mrow = warp_m + mi*16 + g;
            int col = n0 + warp_n + ni*8 + 2*tig;
            float4 cg = accG[mi][ni], cu = accU[mi][ni];
            if (m0 + mrow < cnt) {
                float g0 = cg.x, g1 = cg.y;
                __nv_bfloat162 v = __floats2bfloat162_rn((g0/(1.f+__expf(-g0)))*cu.x,
                                                         (g1/(1.f+__expf(-g1)))*cu.y);
                *(__nv_bfloat162*)&Cout[(long)(base+m0+mrow)*ldc + col] = v;
            }
            if (m0 + mrow + 8 < cnt) {
                float g0 = cg.z, g1 = cg.w;
                __nv_bfloat162 v = __floats2bfloat162_rn((g0/(1.f+__expf(-g0)))*cu.z,
                                                         (g1/(1.f+__expf(-g1)))*cu.w);
                *(__nv_bfloat162*)&Cout[(long)(base+m0+mrow+8)*ldc + col] = v;
            }
        }
    }
}

// -------- bf16 single GEMM (MoE pass2): CTA 128x64, 128 thr, warp 64x32, LDSM --------
__global__ void __launch_bounds__(128)
gemm_bf16_one(const __nv_bfloat16* __restrict__ A, int lda,
              const __nv_bfloat16* __restrict__ Bg, long sB, int ldb,
              float* __restrict__ Cout, int ldc,
              int K) {
    int e = blockIdx.z;
    int m0 = blockIdx.y * 128;
    int cnt = g_cnt[e], base = g_off[e];
    if (m0 >= cnt) return;
    const __nv_bfloat16* B = Bg + (long)e*sB;
    int n0 = blockIdx.x * 64;

    __shared__ unsigned As[3][128][12];
    __shared__ unsigned Bs[3][16][36];
    int tid = threadIdx.x;
    int lane = tid & 31, warpId = tid >> 5;
    int g = lane >> 2, tig = lane & 3;
    int warp_m = (warpId & 1) * 64, warp_n = (warpId >> 1) * 32;
    float4 acc[4][4];
    #pragma unroll
    for (int i = 0; i < 4; i++)
        #pragma unroll
        for (int j = 0; j < 4; j++) acc[i][j] = make_float4(0,0,0,0);

#define S_LOAD(sidx, k0v) do { int _k0 = (k0v); if (_k0 < K) { \
    _Pragma("unroll") for (int i = 0; i < 2; i++) { int idx = tid + i*128; int r = idx >> 1, ch = idx & 1; \
      int rr = m0 + r; if (rr >= cnt) rr = cnt - 1; \
      cp16(&As[sidx][r][ch*4], &A[(long)(base + rr)*lda + _k0 + ch*8]); } \
    { int r = tid >> 3, ch = tid & 7; \
      cp16(&Bs[sidx][r][ch*4], &B[(long)(_k0+r)*ldb + n0 + ch*8]); } \
    } CP_COMMIT; } while(0)

    const int nIter = K >> 4;
    S_LOAD(0, 0);
    S_LOAD(1, 16);
    int st = 0;
    int half16 = (lane >> 4) * 16;
    for (int it = 0; it < nIter; it++) {
        CP_WAIT1;
        __syncthreads();
        unsigned aBase = (unsigned)__cvta_generic_to_shared(&As[st][0][0]);
        unsigned bBase = (unsigned)__cvta_generic_to_shared(&Bs[st][0][0]);
        unsigned a[4][4], b[4][2];
        #pragma unroll
        for (int mi = 0; mi < 4; mi++) {
            int row = warp_m + mi*16 + (lane & 15);
            ldsm4(a[mi][0], a[mi][1], a[mi][2], a[mi][3], aBase + row*48 + half16);
        }
        #pragma unroll
        for (int nh = 0; nh < 2; nh++) {
            int krow = lane & 15;
            int col = warp_n + nh*16 + (lane >> 4) * 8;
            ldsm4t(b[nh*2][0], b[nh*2][1], b[nh*2+1][0], b[nh*2+1][1],
                   bBase + krow*144 + col*2);
        }
        #pragma unroll
        for (int mi = 0; mi < 4; mi++)
            #pragma unroll
            for (int ni = 0; ni < 4; ni++) mma_bf16(acc[mi][ni], a[mi], b[ni]);
        int wst = st + 2; if (wst >= 3) wst -= 3;
        S_LOAD(wst, (it + 2) << 4);
        if (++st == 3) st = 0;
    }
#undef S_LOAD
    #pragma unroll
    for (int mi = 0; mi < 4; mi++) {
        #pragma unroll
        for (int ni = 0; ni < 4; ni++) {
            int mrow = warp_m + mi*16 + g;
            int col = n0 + warp_n + ni*8 + 2*tig;
            float4 c = acc[mi][ni];
            if (m0 + mrow < cnt)
                *(float2*)&Cout[(long)(base+m0+mrow)*ldc + col] = make_float2(c.x, c.y);
            if (m0 + mrow + 8 < cnt)
                *(float2*)&Cout[(long)(base+m0+mrow+8)*ldc + col] = make_float2(c.z, c.w);
        }
    }
}

// ---------------- shared-FFN activation (tf32 path, rounds output) ----------------
__global__ void silumul_kernel(float* __restrict__ g, const float* __restrict__ u, int n) {
    int i = blockIdx.x*256 + threadIdx.x;
    if (i < n) {
        float x = g[i];
        g[i] = rtf((x / (1.f + __expf(-x))) * u[i]);
    }
}

// ---------------- final combine ----------------
__global__ void combine_kernel(float* __restrict__ out) {
    int t = blockIdx.x;
    int pos[TOPK]; float w[TOPK];
    #pragma unroll
    for (int j = 0; j < TOPK; j++) {
        pos[j] = g_pairPos[t*TOPK + j];
        w[j]   = g_pairW[pos[j]];
    }
    for (int h = threadIdx.x; h < H; h += 256) {
        float s = g_hres[(long)t*H + h] + g_shared[(long)t*H + h];
        #pragma unroll
        for (int j = 0; j < TOPK; j++)
            s += w[j] * g_pairout[(long)pos[j]*H + h];
        out[(long)t*H + h] = s;
    }
}

// ---------------- launch ----------------
extern "C" void kernel_launch(void* const* d_in, const int* in_sizes, int n_in,
                              void* d_out, int out_size) {
    (void)in_sizes; (void)n_in; (void)out_size;
    const float* x       = (const float*)d_in[0];
    const float* ln1     = (const float*)d_in[1];
    const float* ln2     = (const float*)d_in[2];
    const float* Wq      = (const float*)d_in[3];
    const float* Wk      = (const float*)d_in[4];
    const float* Wv      = (const float*)d_in[5];
    const float* Wo      = (const float*)d_in[6];
    const float* gate_w  = (const float*)d_in[7];
    const float* gpe     = (const float*)d_in[8];
    const float* upe     = (const float*)d_in[9];
    const float* dpe     = (const float*)d_in[10];
    const float* sh_gate = (const float*)d_in[11];
    const float* sh_up   = (const float*)d_in[12];
    const float* sh_down = (const float*)d_in[13];
    float* out = (float*)d_out;

    float *h1p,*qp,*kp,*vp,*scoresp,*attnp,*hresp,*h2p,*h2up,*sgp,*sup,*sharedp,*pairoutp;
    __nv_bfloat16 *h2bp,*actBp,*gpeBp,*upeBp,*dpeBp;
    float *wqr,*wkr,*wvr,*wor,*shgr,*shur,*shdr;
    cudaGetSymbolAddress((void**)&h1p,     g_h1);
    cudaGetSymbolAddress((void**)&qp,      g_q);
    cudaGetSymbolAddress((void**)&kp,      g_k);
    cudaGetSymbolAddress((void**)&vp,      g_v);
    cudaGetSymbolAddress((void**)&scoresp, g_scores);
    cudaGetSymbolAddress((void**)&attnp,   g_attnout);
    cudaGetSymbolAddress((void**)&hresp,   g_hres);
    cudaGetSymbolAddress((void**)&h2p,     g_h2);
    cudaGetSymbolAddress((void**)&h2up,    g_h2u);
    cudaGetSymbolAddress((void**)&h2bp,    g_h2b);
    cudaGetSymbolAddress((void**)&sgp,     g_sg);
    cudaGetSymbolAddress((void**)&sup,     g_su);
    cudaGetSymbolAddress((void**)&sharedp, g_shared);
    cudaGetSymbolAddress((void**)&actBp,   g_actB);
    cudaGetSymbolAddress((void**)&pairoutp,g_pairout);
    cudaGetSymbolAddress((void**)&gpeBp,   g_gpeB);
    cudaGetSymbolAddress((void**)&upeBp,   g_upeB);
    cudaGetSymbolAddress((void**)&dpeBp,   g_dpeB);
    cudaGetSymbolAddress((void**)&wqr,     g_WqR);
    cudaGetSymbolAddress((void**)&wkr,     g_WkR);
    cudaGetSymbolAddress((void**)&wvr,     g_WvR);
    cudaGetSymbolAddress((void**)&wor,     g_WoR);
    cudaGetSymbolAddress((void**)&shgr,    g_shgR);
    cudaGetSymbolAddress((void**)&shur,    g_shuR);
    cudaGetSymbolAddress((void**)&shdr,    g_shdR);

    const float inv_sqrt_hd = 0.08838834764831845f;

    // side stream + fork/join events (host objects; created per call, leaked —
    // only ~2 calls ever happen: correctness + capture)
    cudaStream_t s2;
    cudaStreamCreateWithFlags(&s2, cudaStreamNonBlocking);
    cudaEvent_t evFork, evSide, evH2, evShared;
    cudaEventCreateWithFlags(&evFork,   cudaEventDisableTiming);
    cudaEventCreateWithFlags(&evSide,   cudaEventDisableTiming);
    cudaEventCreateWithFlags(&evH2,     cudaEventDisableTiming);
    cudaEventCreateWithFlags(&evShared, cudaEventDisableTiming);

    // fork: side stream handles input-only work (shared-weight rounding + transposes)
    cudaEventRecord(evFork, 0);
    cudaStreamWaitEvent(s2, evFork, 0);
    round_shared<<<dim3((H*SHF/4 + 255)/256, 3), 256, 0, s2>>>(
        (const float4*)sh_gate, (float4*)shgr, (const float4*)sh_up, (float4*)shur,
        (const float4*)sh_down, (float4*)shdr);
    transpose_eb<<<dim3(EI/32, H/2), 256, 0, s2>>>(gpe, (unsigned*)gpeBp, H, EI);
    transpose_eb<<<dim3(EI/32, H/2), 256, 0, s2>>>(upe, (unsigned*)upeBp, H, EI);
    transpose_eb<<<dim3(H/32, EI/2), 256, 0, s2>>>(dpe, (unsigned*)dpeBp, EI, H);
    cudaEventRecord(evSide, s2);

    // main stream: attention weight rounding + attention chain (tf32)
    round_attn<<<dim3((H*NH*HD/4 + 255)/256, 4), 256>>>(
        (const float4*)Wq, (float4*)wqr, (const float4*)Wk, (float4*)wkr,
        (const float4*)Wv, (float4*)wvr, (const float4*)Wo, (float4*)wor);
    rms_kernel<<<T, 256>>>(x, ln1, h1p, nullptr, nullptr);
    gemm_tc<<<dim3(H/64, T/64, 3), 128>>>(h1p, H, 0, wqr, wkr, wvr, H, 0, 0,
                                          qp, kp, vp, H, 0, nullptr, 0,
                                          H, 1.f, 0, 0);
    rope_kernel<<<T, 256>>>();
    gemm_tc<<<dim3(T/64, T/64, NH), 128>>>(qp, H, HD, kp, nullptr, nullptr, H, HD, 1,
                                           scoresp, nullptr, nullptr, T, (long)T*T, nullptr, 0,
                                           HD, inv_sqrt_hd, 1, 0);
    attn_softmax<<<dim3(T, NH), 256>>>();
    gemm_tc<<<dim3(HD/64, T/64, NH), 128>>>(scoresp, T, (long)T*T, vp, nullptr, nullptr, H, HD, 0,
                                            attnp, nullptr, nullptr, H, HD, nullptr, 0,
                                            T, 1.f, 2, 1);
    gemm_tc<<<dim3(H/64, T/64, 1), 128>>>(attnp, H, 0, wor, nullptr, nullptr, H, 0, 0,
                                          hresp, nullptr, nullptr, H, 0, x, 0,
                                          H, 1.f, 0, 0);

    // h2 (all three variants)
    rms_kernel<<<T, 256>>>(hresp, ln2, h2p, h2up, h2bp);
    cudaEventRecord(evH2, 0);

    // side stream: shared FFN (tf32) overlaps router + MoE on main
    cudaStreamWaitEvent(s2, evH2, 0);
    gemm_tc<<<dim3(SHF/64, T/64, 2), 128, 0, s2>>>(h2p, H, 0, shgr, shur, nullptr, SHF, 0, 0,
                                                   sgp, sup, nullptr, SHF, 0, nullptr, 0,
                                                   H, 1.f, 0, 0);
    silumul_kernel<<<(T*SHF + 255)/256, 256, 0, s2>>>(sgp, sup, T*SHF);
    gemm_tc<<<dim3(H/64, T/64, 1), 128, 0, s2>>>(sgp, SHF, 0, shdr, nullptr, nullptr, H, 0, 0,
                                                 sharedp, nullptr, nullptr, H, 0, nullptr, 0,
                                                 SHF, 1.f, 0, 0);
    cudaEventRecord(evShared, s2);

    // main: router + MoE (bf16 LDSM)
    zero_cnt_kernel<<<1, 64>>>();
    router_kernel<<<T, 64>>>(gate_w);
    prefix_kernel<<<1, 32>>>();
    scatter_kernel<<<(NPAIR + 255)/256, 256>>>();
    cudaStreamWaitEvent(0, evSide, 0);   // transposed expert weights ready
    gemm_bf16_dual<<<dim3(EI/64, T/128, NEXP), 256>>>(
        h2bp, H, gpeBp, upeBp, (long)H*EI, EI, actBp, EI, H);
    gemm_bf16_one<<<dim3(H/64, T/128, NEXP), 128>>>(
        actBp, EI, dpeBp, (long)EI*H, H, pairoutp, H, EI);

    // join shared FFN, then combine
    cudaStreamWaitEvent(0, evShared, 0);
    combine_kernel<<<T, 256>>>(out);
}

// round 11
// speedup vs baseline: 1.6296x; 1.2601x over previous
#include <cuda_runtime.h>
#include <cuda_bf16.h>
#include <math.h>

#define T 1024
#define H 1280
#define NH 10
#define HD 128
#define EI 896
#define NEXP 64
#define TOPK 6
#define SHF 1792
#define NPAIR (T*TOPK)

// ---------------- device scratch ----------------
static __device__ float g_h1[T*H];
static __device__ float g_q[T*H];
static __device__ float g_k[T*H];
static __device__ float g_v[T*H];
static __device__ float g_scores[NH*T*T];
static __device__ float g_attnout[T*H];
static __device__ float g_hres[T*H];
static __device__ float g_h2[T*H];              // tf32-rounded fp32 (shared FFN)
static __device__ float g_h2u[T*H];             // unrounded fp32 (router)
static __device__ __nv_bfloat16 g_h2b[T*H];     // bf16 (MoE pass1 A)
static __device__ float g_sg[T*SHF];
static __device__ float g_su[T*SHF];
static __device__ float g_shared[T*H];
// bf16 expert weights, [e][k][n] plain bf16
static __device__ __nv_bfloat16 g_gpeB[(size_t)NEXP*H*EI];
static __device__ __nv_bfloat16 g_upeB[(size_t)NEXP*H*EI];
static __device__ __nv_bfloat16 g_dpeB[(size_t)NEXP*EI*H];
static __device__ __nv_bfloat16 g_actB[(size_t)(NPAIR+128)*EI];
static __device__ float g_pairout[(size_t)NPAIR*H];
// rounded fp32 weight copies (tf32 GEMMs)
static __device__ float g_WqR[H*NH*HD];
static __device__ float g_WkR[H*NH*HD];
static __device__ float g_WvR[H*NH*HD];
static __device__ float g_WoR[NH*HD*H];
static __device__ float g_shgR[H*SHF];
static __device__ float g_shuR[H*SHF];
static __device__ float g_shdR[SHF*H];
static __device__ int   g_cnt[NEXP];
static __device__ int   g_off[NEXP];
static __device__ int   g_cur[NEXP];
static __device__ int   g_tokE[NPAIR];
static __device__ float g_tokW[NPAIR];
static __device__ int   g_pairTok[NPAIR];
static __device__ float g_pairW[NPAIR];
static __device__ int   g_pairPos[NPAIR];

// ---------------- helpers ----------------
__device__ __forceinline__ void mma_tf32(float4& c, const unsigned a[4], const unsigned b[2]) {
    asm volatile("mma.sync.aligned.m16n8k8.row.col.f32.tf32.tf32.f32 "
        "{%0,%1,%2,%3}, {%4,%5,%6,%7}, {%8,%9}, {%0,%1,%2,%3};"
        : "+f"(c.x), "+f"(c.y), "+f"(c.z), "+f"(c.w)
        : "r"(a[0]), "r"(a[1]), "r"(a[2]), "r"(a[3]), "r"(b[0]), "r"(b[1]));
}
__device__ __forceinline__ void mma_bf16(float4& c, const unsigned a[4], const unsigned b[2]) {
    asm volatile("mma.sync.aligned.m16n8k16.row.col.f32.bf16.bf16.f32 "
        "{%0,%1,%2,%3}, {%4,%5,%6,%7}, {%8,%9}, {%0,%1,%2,%3};"
        : "+f"(c.x), "+f"(c.y), "+f"(c.z), "+f"(c.w)
        : "r"(a[0]), "r"(a[1]), "r"(a[2]), "r"(a[3]), "r"(b[0]), "r"(b[1]));
}
__device__ __forceinline__ float rtf(float f) {
    unsigned r; asm("cvt.rna.tf32.f32 %0, %1;" : "=r"(r) : "f"(f));
    return __uint_as_float(r);
}
__device__ __forceinline__ void cp16(const void* smem, const void* gmem) {
    unsigned sa = (unsigned)__cvta_generic_to_shared(smem);
    asm volatile("cp.async.cg.shared.global [%0], [%1], 16;" :: "r"(sa), "l"(gmem));
}
__device__ __forceinline__ void ldsm4(unsigned& r0, unsigned& r1, unsigned& r2, unsigned& r3,
                                      unsigned addr) {
    asm volatile("ldmatrix.sync.aligned.m8n8.x4.shared.b16 {%0,%1,%2,%3}, [%4];"
        : "=r"(r0), "=r"(r1), "=r"(r2), "=r"(r3) : "r"(addr));
}
__device__ __forceinline__ void ldsm4t(unsigned& r0, unsigned& r1, unsigned& r2, unsigned& r3,
                                       unsigned addr) {
    asm volatile("ldmatrix.sync.aligned.m8n8.x4.trans.shared.b16 {%0,%1,%2,%3}, [%4];"
        : "=r"(r0), "=r"(r1), "=r"(r2), "=r"(r3) : "r"(addr));
}
#define CP_COMMIT asm volatile("cp.async.commit_group;")
#define CP_WAIT1  asm volatile("cp.async.wait_group 1;")

#define AST 36    // tf32 A/transB row stride (32k + 4 pad) words
#define BST 72    // tf32 B row stride (64n + 8 pad) words

// ---------------- weight rounding: attention mats (z 0..3) ----------------
__global__ void round_attn(const float4* w0, float4* o0, const float4* w1, float4* o1,
                           const float4* w2, float4* o2, const float4* w3, float4* o3) {
    int z = blockIdx.y;
    const float4* in; float4* out;
    switch (z) { case 0: in=w0; out=o0; break; case 1: in=w1; out=o1; break;
                 case 2: in=w2; out=o2; break; default: in=w3; out=o3; }
    int i = blockIdx.x*256 + threadIdx.x;
    if (i < H*NH*HD/4) {
        float4 v = in[i];
        v.x = rtf(v.x); v.y = rtf(v.y); v.z = rtf(v.z); v.w = rtf(v.w);
        out[i] = v;
    }
}

// ---------------- weight rounding: shared-FFN mats (z 0..2) ----------------
__global__ void round_shared(const float4* w4, float4* o4, const float4* w5, float4* o5,
                             const float4* w6, float4* o6) {
    int z = blockIdx.y;
    const float4* in; float4* out; int n4;
    switch (z) { case 0: in=w4; out=o4; n4=H*SHF/4; break;
                 case 1: in=w5; out=o5; n4=H*SHF/4; break;
                 default: in=w6; out=o6; n4=SHF*H/4; }
    int i = blockIdx.x*256 + threadIdx.x;
    if (i < n4) {
        float4 v = in[i];
        v.x = rtf(v.x); v.y = rtf(v.y); v.z = rtf(v.z); v.w = rtf(v.w);
        out[i] = v;
    }
}

// ---------------- RMSNorm ----------------
__global__ void rms_kernel(const float* __restrict__ x, const float* __restrict__ w,
                           float* __restrict__ out, float* __restrict__ outu,
                           __nv_bfloat16* __restrict__ outb) {
    int t = blockIdx.x;
    const float* xr = x + (long)t*H;
    __shared__ float red[256];
    float s = 0.f;
    for (int i = threadIdx.x; i < H; i += 256) { float v = xr[i]; s += v*v; }
    red[threadIdx.x] = s; __syncthreads();
    for (int k = 128; k > 0; k >>= 1) {
        if (threadIdx.x < k) red[threadIdx.x] += red[threadIdx.x + k];
        __syncthreads();
    }
    float r = rsqrtf(red[0]/(float)H + 1e-6f);
    for (int i = threadIdx.x; i < H; i += 256) {
        float v = w[i]*xr[i]*r;
        out[(long)t*H + i] = rtf(v);
        if (outu) outu[(long)t*H + i] = v;
        if (outb) outb[(long)t*H + i] = __float2bfloat16(v);
    }
}

// ---------------- tf32 GEMM (R3-proven core): 64x64, BK32, 2-stage, 128 thr ----------
// mode: 0 none, 1 causal block skip, 2 K capped at m0+64.
__global__ void __launch_bounds__(128)
gemm_tc(const float* __restrict__ A, int lda, long sA,
        const float* __restrict__ B, const float* __restrict__ Bb, const float* __restrict__ Bc,
        int ldb, long sB, int transB,
        float* __restrict__ C, float* __restrict__ Cb, float* __restrict__ Cc,
        int ldc, long sC,
        const float* __restrict__ res, long sR,
        int K, float alpha, int mode, int roundC) {
    int m0 = blockIdx.y*64, n0 = blockIdx.x*64;
    if (mode == 1 && n0 >= m0 + 64) return;
    int bz = blockIdx.z;
    A += (long)bz*sA;
    if (Bb) {
        if (bz == 1) { B = Bb; C = Cb; }
        else if (bz == 2) { B = Bc; C = Cc; }
    } else {
        B += (long)bz*sB; C += (long)bz*sC; if (res) res += (long)bz*sR;
    }
    int Klim = (mode == 2) ? (m0 + 64 < K ? m0 + 64 : K) : K;

    __shared__ float As[2][64*AST];
    __shared__ float Bs[2][2304];
    int tid = threadIdx.x;
    int lane = tid & 31, warpId = tid >> 5;
    int g = lane >> 2, tig = lane & 3;
    int warp_m = (warpId & 1) * 32, warp_n = (warpId >> 1) * 32;
    float4 acc[2][4];
    #pragma unroll
    for (int i = 0; i < 2; i++)
        #pragma unroll
        for (int j = 0; j < 4; j++) acc[i][j] = make_float4(0.f,0.f,0.f,0.f);

#define G_LOAD(sidx, k0v) do { int _k0 = (k0v); if (_k0 < Klim) { \
    _Pragma("unroll") for (int i = 0; i < 4; i++) { int idx = tid + i*128; int r = idx >> 3, c4 = (idx & 7) << 2; \
        cp16(&As[sidx][r*AST + c4], &A[(long)(m0+r)*lda + _k0 + c4]); } \
    if (!transB) { \
        _Pragma("unroll") for (int i = 0; i < 4; i++) { int idx = tid + i*128; int r = idx >> 4, c4 = (idx & 15) << 2; \
            cp16(&Bs[sidx][r*BST + c4], &B[(long)(_k0+r)*ldb + n0 + c4]); } \
    } else { \
        _Pragma("unroll") for (int i = 0; i < 4; i++) { int idx = tid + i*128; int r = idx >> 3, c4 = (idx & 7) << 2; \
            cp16(&Bs[sidx][r*AST + c4], &B[(long)(n0+r)*ldb + _k0 + c4]); } \
    } } CP_COMMIT; } while(0)

    int nIter = Klim >> 5;
    G_LOAD(0, 0);
    for (int it = 0; it < nIter; it++) {
        int s = it & 1;
        G_LOAD(s ^ 1, (it + 1) << 5);
        CP_WAIT1;
        __syncthreads();
        #pragma unroll
        for (int kk = 0; kk < 32; kk += 8) {
            unsigned a[2][4], b[4][2];
            #pragma unroll
            for (int mi = 0; mi < 2; mi++) {
                const float* ap = &As[s][(warp_m + mi*16 + g)*AST + kk + tig];
                a[mi][0] = __float_as_uint(ap[0]);
                a[mi][1] = __float_as_uint(ap[8*AST]);
                a[mi][2] = __float_as_uint(ap[4]);
                a[mi][3] = __float_as_uint(ap[8*AST + 4]);
            }
            if (!transB) {
                #pragma unroll
                for (int ni = 0; ni < 4; ni++) {
                    int col = warp_n + ni*8 + g;
                    b[ni][0] = __float_as_uint(Bs[s][(kk+tig)*BST + col]);
                    b[ni][1] = __float_as_uint(Bs[s][(kk+tig+4)*BST + col]);
                }
            } else {
                #pragma unroll
                for (int ni = 0; ni < 4; ni++) {
                    const float* bp = &Bs[s][(warp_n + ni*8 + g)*AST + kk + tig];
                    b[ni][0] = __float_as_uint(bp[0]);
                    b[ni][1] = __float_as_uint(bp[4]);
                }
            }
            #pragma unroll
            for (int mi = 0; mi < 2; mi++)
                #pragma unroll
                for (int ni = 0; ni < 4; ni++) mma_tf32(acc[mi][ni], a[mi], b[ni]);
        }
        __syncthreads();
    }
#undef G_LOAD
    #pragma unroll
    for (int mi = 0; mi < 2; mi++) {
        #pragma unroll
        for (int ni = 0; ni < 4; ni++) {
            int row = m0 + warp_m + mi*16 + g;
            int col = n0 + warp_n + ni*8 + 2*tig;
            float4 c = acc[mi][ni];
            float2 v0 = { alpha*c.x, alpha*c.y };
            float2 v1 = { alpha*c.z, alpha*c.w };
            if (res) {
                float2 r0 = *(const float2*)&res[(long)row*ldc + col];
                float2 r1 = *(const float2*)&res[(long)(row+8)*ldc + col];
                v0.x += r0.x; v0.y += r0.y; v1.x += r1.x; v1.y += r1.y;
            }
            if (roundC) {
                v0.x = rtf(v0.x); v0.y = rtf(v0.y);
                v1.x = rtf(v1.x); v1.y = rtf(v1.y);
            }
            *(float2*)&C[(long)row*ldc + col] = v0;
            *(float2*)&C[(long)(row+8)*ldc + col] = v1;
        }
    }
}

// ---------------- RoPE (rounds q,k,v) ----------------
__global__ void rope_kernel() {
    int t = blockIdx.x, tid = threadIdx.x;
    __shared__ float cs[64], sn[64];
    if (tid < 64) {
        float inv = powf(10000.0f, -(float)tid / 64.0f);
        float fr = (float)t * inv;
        cs[tid] = cosf(fr); sn[tid] = sinf(fr);
    }
    __syncthreads();
    for (int idx = tid; idx < NH*64; idx += 256) {
        int hh = idx >> 6, j = idx & 63;
        long b = (long)t*H + hh*HD;
        float c = cs[j], s = sn[j];
        float q1 = g_q[b+j], q2 = g_q[b+j+64];
        g_q[b+j]    = rtf(q1*c - q2*s);
        g_q[b+j+64] = rtf(q2*c + q1*s);
        float k1 = g_k[b+j], k2 = g_k[b+j+64];
        g_k[b+j]    = rtf(k1*c - k2*s);
        g_k[b+j+64] = rtf(k2*c + k1*s);
    }
    for (int i = tid; i < H; i += 256) {
        long b = (long)t*H + i;
        g_v[b] = rtf(g_v[b]);
    }
}

// ---------------- causal softmax (zeros to next 64-boundary) ----------------
__global__ void attn_softmax() {
    int t = blockIdx.x, hh = blockIdx.y, tid = threadIdx.x;
    float* row = g_scores + ((long)hh*T + t)*(long)T;
    int len = t + 1;
    int zend = ((t >> 6) + 1) << 6;
    __shared__ float red[256];
    float mx = -3.0e38f;
    for (int i = tid; i < len; i += 256) mx = fmaxf(mx, row[i]);
    red[tid] = mx; __syncthreads();
    for (int s = 128; s > 0; s >>= 1) { if (tid < s) red[tid] = fmaxf(red[tid], red[tid+s]); __syncthreads(); }
    mx = red[0]; __syncthreads();
    float sum = 0.f;
    for (int i = tid; i < len; i += 256) { float e = __expf(row[i]-mx); row[i] = e; sum += e; }
    red[tid] = sum; __syncthreads();
    for (int s = 128; s > 0; s >>= 1) { if (tid < s) red[tid] += red[tid+s]; __syncthreads(); }
    float inv = 1.0f / red[0];
    for (int i = tid; i < len; i += 256) row[i] = rtf(row[i] * inv);
    for (int i = len + tid; i < zend; i += 256) row[i] = 0.f;
}

// ------- expert transpose -> bf16 [e][k][n], vectorized ------------------------------
// in[R][C][64] fp32 (expert innermost). Block: 1 k-row x 32 n-cols x 64 experts.
// Same value pairing/rounding as before -> byte-identical output.
__global__ void __launch_bounds__(256) transpose_eb(const float* __restrict__ in,
                                                    unsigned* __restrict__ out,
                                                    int R, int C) {
    int r = blockIdx.y;
    int c0 = blockIdx.x * 32;
    __shared__ unsigned sm[16][68];
    int tid = threadIdx.x;
    {
        int cpair = tid >> 4;          // 0..15 (pair of n columns)
        int e4 = (tid & 15) << 2;      // 0..60 (expert quad)
        const float* basep = in + ((long)r*C + c0 + 2*cpair) * 64 + e4;
        float4 a = *(const float4*)basep;          // n = c0+2cpair,   e4..e4+3
        float4 b = *(const float4*)(basep + 64);   // n = c0+2cpair+1, e4..e4+3
        __nv_bfloat162 t0 = __floats2bfloat162_rn(a.x, b.x);
        __nv_bfloat162 t1 = __floats2bfloat162_rn(a.y, b.y);
        __nv_bfloat162 t2 = __floats2bfloat162_rn(a.z, b.z);
        __nv_bfloat162 t3 = __floats2bfloat162_rn(a.w, b.w);
        uint4 u = { *(unsigned*)&t0, *(unsigned*)&t1, *(unsigned*)&t2, *(unsigned*)&t3 };
        *(uint4*)&sm[cpair][e4] = u;
    }
    __syncthreads();
    {
        int e = tid >> 2;              // 0..63
        int grp = (tid & 3) << 2;      // 0,4,8,12
        uint4 v;
        v.x = sm[grp+0][e];
        v.y = sm[grp+1][e];
        v.z = sm[grp+2][e];
        v.w = sm[grp+3][e];
        long C2 = C >> 1;
        *(uint4*)&out[(long)e*R*C2 + (long)r*C2 + (c0 >> 1) + grp] = v;
    }
}

// ---------------- router ----------------
__global__ void zero_cnt_kernel() { if (threadIdx.x < NEXP) g_cnt[threadIdx.x] = 0; }

__global__ void router_kernel(const float* __restrict__ gw) {
    int t = blockIdx.x, e = threadIdx.x;
    const float* hr = g_h2u + (long)t*H;
    float s = 0.f;
    for (int h = 0; h < H; h++) s += hr[h] * gw[h*NEXP + e];
    __shared__ float probs[NEXP];
    probs[e] = s;
    __syncthreads();
    if (e == 0) {
        float mx = -3e38f;
        for (int i = 0; i < NEXP; i++) mx = fmaxf(mx, probs[i]);
        float sum = 0.f;
        for (int i = 0; i < NEXP; i++) { probs[i] = __expf(probs[i]-mx); sum += probs[i]; }
        float inv = 1.f/sum;
        for (int i = 0; i < NEXP; i++) probs[i] *= inv;
        int ti[TOPK]; float tw[TOPK]; float ws = 0.f;
        for (int j = 0; j < TOPK; j++) {
            int bi = 0; float bv = -1.f;
            for (int i = 0; i < NEXP; i++) if (probs[i] > bv) { bv = probs[i]; bi = i; }
            ti[j] = bi; tw[j] = bv; ws += bv; probs[bi] = -2.f;
        }
        float wi = 1.f/ws;
        for (int j = 0; j < TOPK; j++) {
            g_tokE[t*TOPK+j] = ti[j];
            g_tokW[t*TOPK+j] = tw[j]*wi;
            atomicAdd(&g_cnt[ti[j]], 1);
        }
    }
}

__global__ void prefix_kernel() {
    if (threadIdx.x == 0) {
        int s = 0;
        for (int e = 0; e < NEXP; e++) { g_off[e] = s; g_cur[e] = s; s += g_cnt[e]; }
    }
}

__global__ void scatter_kernel() {
    int i = blockIdx.x*256 + threadIdx.x;
    if (i < NPAIR) {
        int e = g_tokE[i];
        int pos = atomicAdd(&g_cur[e], 1);
        g_pairTok[pos] = i / TOPK;
        g_pairW[pos]   = g_tokW[i];
        g_pairPos[i]   = pos;
    }
}

// -------- bf16 dual GEMM + SiLU epilogue (MoE pass1): CTA 128x64, 256 thr, LDSM -------
__global__ void __launch_bounds__(256)
gemm_bf16_dual(const __nv_bfloat16* __restrict__ A, int lda,
               const __nv_bfloat16* __restrict__ B1g, const __nv_bfloat16* __restrict__ B2g,
               long sB, int ldb,
               __nv_bfloat16* __restrict__ Cout, int ldc,
               int K) {
    int e = blockIdx.z;
    int m0 = blockIdx.y * 128;
    int cnt = g_cnt[e], base = g_off[e];
    if (m0 >= cnt) return;
    const __nv_bfloat16* B1 = B1g + (long)e*sB;
    const __nv_bfloat16* B2 = B2g + (long)e*sB;
    int n0 = blockIdx.x * 64;

    __shared__ int stok[128];
    __shared__ unsigned As[3][128][12];    // 48B rows: 16 bf16 + 16B pad
    __shared__ unsigned Bs1[3][16][36];    // 144B rows: 64 bf16 + 16B pad
    __shared__ unsigned Bs2[3][16][36];
    int tid = threadIdx.x;
    int lane = tid & 31, warpId = tid >> 5;
    int g = lane >> 2, tig = lane & 3;
    int warp_m = (warpId & 3) * 32, warp_n = (warpId >> 2) * 32;
    if (tid < 128) stok[tid] = (m0 + tid < cnt) ? g_pairTok[base + m0 + tid] : 0;
    __syncthreads();
    float4 accG[2][4], accU[2][4];
    #pragma unroll
    for (int i = 0; i < 2; i++)
        #pragma unroll
        for (int j = 0; j < 4; j++) { accG[i][j] = make_float4(0,0,0,0); accU[i][j] = make_float4(0,0,0,0); }

#define D_LOAD(sidx, k0v) do { int _k0 = (k0v); if (_k0 < K) { \
    { int r = tid >> 1, ch = tid & 1; \
      cp16(&As[sidx][r][ch*4], &A[(long)stok[r]*lda + _k0 + ch*8]); } \
    if (tid < 128) { int r = tid >> 3, ch = tid & 7; \
      cp16(&Bs1[sidx][r][ch*4], &B1[(long)(_k0+r)*ldb + n0 + ch*8]); } \
    else { int t2 = tid - 128; int r = t2 >> 3, ch = t2 & 7; \
      cp16(&Bs2[sidx][r][ch*4], &B2[(long)(_k0+r)*ldb + n0 + ch*8]); } \
    } CP_COMMIT; } while(0)

    const int nIter = K >> 4;
    D_LOAD(0, 0);
    D_LOAD(1, 16);
    int st = 0;
    int half16 = (lane >> 4) * 16;
    for (int it = 0; it < nIter; it++) {
        CP_WAIT1;
        __syncthreads();
        unsigned aBase = (unsigned)__cvta_generic_to_shared(&As[st][0][0]);
        unsigned b1Base = (unsigned)__cvta_generic_to_shared(&Bs1[st][0][0]);
        unsigned b2Base = (unsigned)__cvta_generic_to_shared(&Bs2[st][0][0]);
        unsigned a[2][4], b1[4][2], b2[4][2];
        #pragma unroll
        for (int mi = 0; mi < 2; mi++) {
            int row = warp_m + mi*16 + (lane & 15);
            ldsm4(a[mi][0], a[mi][1], a[mi][2], a[mi][3], aBase + row*48 + half16);
        }
        #pragma unroll
        for (int nh = 0; nh < 2; nh++) {
            int krow = lane & 15;
            int col = warp_n + nh*16 + (lane >> 4) * 8;
            ldsm4t(b1[nh*2][0], b1[nh*2][1], b1[nh*2+1][0], b1[nh*2+1][1],
                   b1Base + krow*144 + col*2);
            ldsm4t(b2[nh*2][0], b2[nh*2][1], b2[nh*2+1][0], b2[nh*2+1][1],
                   b2Base + krow*144 + col*2);
        }
        #pragma unroll
        for (int mi = 0; mi < 2; mi++)
            #pragma unroll
            for (int ni = 0; ni < 4; ni++) {
                mma_bf16(accG[mi][ni], a[mi], b1[ni]);
                mma_bf16(accU[mi][ni], a[mi], b2[ni]);
            }
        int wst = st + 2; if (wst >= 3) wst -= 3;
        D_LOAD(wst, (it + 2) << 4);
        if (++st == 3) st = 0;
    }
#undef D_LOAD
    #pragma unroll
    for (int mi = 0; mi < 2; mi++) {
        #pragma unroll
        for (int ni = 0; ni < 4; ni++) {
            int mrow = warp_m + mi*16 + g;
            int col = n0 + warp_n + ni*8 + 2*tig;
            float4 cg = accG[mi][ni], cu = accU[mi][ni];
            if (m0 + mrow < cnt) {
                float g0 = cg.x, g1 = cg.y;
                __nv_bfloat162 v = __floats2bfloat162_rn((g0/(1.f+__expf(-g0)))*cu.x,
                                                         (g1/(1.f+__expf(-g1)))*cu.y);
                *(__nv_bfloat162*)&Cout[(long)(base+m0+mrow)*ldc + col] = v;
            }
            if (m0 + mrow + 8 < cnt) {
                float g0 = cg.z, g1 = cg.w;
                __nv_bfloat162 v = __floats2bfloat162_rn((g0/(1.f+__expf(-g0)))*cu.z,
                                                         (g1/(1.f+__expf(-g1)))*cu.w);
                *(__nv_bfloat162*)&Cout[(long)(base+m0+mrow+8)*ldc + col] = v;
            }
        }
    }
}

// -------- bf16 single GEMM (MoE pass2): CTA 128x64, 128 thr, warp 64x32, LDSM --------
__global__ void __launch_bounds__(128)
gemm_bf16_one(const __nv_bfloat16* __restrict__ A, int lda,
              const __nv_bfloat16* __restrict__ Bg, long sB, int ldb,
              float* __restrict__ Cout, int ldc,
              int K) {
    int e = blockIdx.z;
    int m0 = blockIdx.y * 128;
    int cnt = g_cnt[e], base = g_off[e];
    if (m0 >= cnt) return;
    const __nv_bfloat16* B = Bg + (long)e*sB;
    int n0 = blockIdx.x * 64;

    __shared__ unsigned As[3][128][12];
    __shared__ unsigned Bs[3][16][36];
    int tid = threadIdx.x;
    int lane = tid & 31, warpId = tid >> 5;
    int g = lane >> 2, tig = lane & 3;
    int warp_m = (warpId & 1) * 64, warp_n = (warpId >> 1) * 32;
    float4 acc[4][4];
    #pragma unroll
    for (int i = 0; i < 4; i++)
        #pragma unroll
        for (int j = 0; j < 4; j++) acc[i][j] = make_float4(0,0,0,0);

#define S_LOAD(sidx, k0v) do { int _k0 = (k0v); if (_k0 < K) { \
    _Pragma("unroll") for (int i = 0; i < 2; i++) { int idx = tid + i*128; int r = idx >> 1, ch = idx & 1; \
      int rr = m0 + r; if (rr >= cnt) rr = cnt - 1; \
      cp16(&As[sidx][r][ch*4], &A[(long)(base + rr)*lda + _k0 + ch*8]); } \
    { int r = tid >> 3, ch = tid & 7; \
      cp16(&Bs[sidx][r][ch*4], &B[(long)(_k0+r)*ldb + n0 + ch*8]); } \
    } CP_COMMIT; } while(0)

    const int nIter = K >> 4;
    S_LOAD(0, 0);
    S_LOAD(1, 16);
    int st = 0;
    int half16 = (lane >> 4) * 16;
    for (int it = 0; it < nIter; it++) {
        CP_WAIT1;
        __syncthreads();
        unsigned aBase = (unsigned)__cvta_generic_to_shared(&As[st][0][0]);
        unsigned bBase = (unsigned)__cvta_generic_to_shared(&Bs[st][0][0]);
        unsigned a[4][4], b[4][2];
        #pragma unroll
        for (int mi = 0; mi < 4; mi++) {
            int row = warp_m + mi*16 + (lane & 15);
            ldsm4(a[mi][0], a[mi][1], a[mi][2], a[mi][3], aBase + row*48 + half16);
        }
        #pragma unroll
        for (int nh = 0; nh < 2; nh++) {
            int krow = lane & 15;
            int col = warp_n + nh*16 + (lane >> 4) * 8;
            ldsm4t(b[nh*2][0], b[nh*2][1], b[nh*2+1][0], b[nh*2+1][1],
                   bBase + krow*144 + col*2);
        }
        #pragma unroll
        for (int mi = 0; mi < 4; mi++)
            #pragma unroll
            for (int ni = 0; ni < 4; ni++) mma_bf16(acc[mi][ni], a[mi], b[ni]);
        int wst = st + 2; if (wst >= 3) wst -= 3;
        S_LOAD(wst, (it + 2) << 4);
        if (++st == 3) st = 0;
    }
#undef S_LOAD
    #pragma unroll
    for (int mi = 0; mi < 4; mi++) {
        #pragma unroll
        for (int ni = 0; ni < 4; ni++) {
            int mrow = warp_m + mi*16 + g;
            int col = n0 + warp_n + ni*8 + 2*tig;
            float4 c = acc[mi][ni];
            if (m0 + mrow < cnt)
                *(float2*)&Cout[(long)(base+m0+mrow)*ldc + col] = make_float2(c.x, c.y);
            if (m0 + mrow + 8 < cnt)
                *(float2*)&Cout[(long)(base+m0+mrow+8)*ldc + col] = make_float2(c.z, c.w);
        }
    }
}

// ---------------- shared-FFN activation (vectorized, rounds output) ----------------
__global__ void silumul_kernel(float4* __restrict__ g, const float4* __restrict__ u, int n4) {
    int i = blockIdx.x*256 + threadIdx.x;
    if (i < n4) {
        float4 x = g[i];
        float4 y = u[i];
        x.x = rtf((x.x / (1.f + __expf(-x.x))) * y.x);
        x.y = rtf((x.y / (1.f + __expf(-x.y))) * y.y);
        x.z = rtf((x.z / (1.f + __expf(-x.z))) * y.z);
        x.w = rtf((x.w / (1.f + __expf(-x.w))) * y.w);
        g[i] = x;
    }
}

// ---------------- final combine ----------------
__global__ void combine_kernel(float* __restrict__ out) {
    int t = blockIdx.x;
    int pos[TOPK]; float w[TOPK];
    #pragma unroll
    for (int j = 0; j < TOPK; j++) {
        pos[j] = g_pairPos[t*TOPK + j];
        w[j]   = g_pairW[pos[j]];
    }
    for (int h = threadIdx.x; h < H; h += 256) {
        float s = g_hres[(long)t*H + h] + g_shared[(long)t*H + h];
        #pragma unroll
        for (int j = 0; j < TOPK; j++)
            s += w[j] * g_pairout[(long)pos[j]*H + h];
        out[(long)t*H + h] = s;
    }
}

// ---------------- launch ----------------
extern "C" void kernel_launch(void* const* d_in, const int* in_sizes, int n_in,
                              void* d_out, int out_size) {
    (void)in_sizes; (void)n_in; (void)out_size;
    const float* x       = (const float*)d_in[0];
    const float* ln1     = (const float*)d_in[1];
    const float* ln2     = (const float*)d_in[2];
    const float* Wq      = (const float*)d_in[3];
    const float* Wk      = (const float*)d_in[4];
    const float* Wv      = (const float*)d_in[5];
    const float* Wo      = (const float*)d_in[6];
    const float* gate_w  = (const float*)d_in[7];
    const float* gpe     = (const float*)d_in[8];
    const float* upe     = (const float*)d_in[9];
    const float* dpe     = (const float*)d_in[10];
    const float* sh_gate = (const float*)d_in[11];
    const float* sh_up   = (const float*)d_in[12];
    const float* sh_down = (const float*)d_in[13];
    float* out = (float*)d_out;

    float *h1p,*qp,*kp,*vp,*scoresp,*attnp,*hresp,*h2p,*h2up,*sgp,*sup,*sharedp,*pairoutp;
    __nv_bfloat16 *h2bp,*actBp,*gpeBp,*upeBp,*dpeBp;
    float *wqr,*wkr,*wvr,*wor,*shgr,*shur,*shdr;
    cudaGetSymbolAddress((void**)&h1p,     g_h1);
    cudaGetSymbolAddress((void**)&qp,      g_q);
    cudaGetSymbolAddress((void**)&kp,      g_k);
    cudaGetSymbolAddress((void**)&vp,      g_v);
    cudaGetSymbolAddress((void**)&scoresp, g_scores);
    cudaGetSymbolAddress((void**)&attnp,   g_attnout);
    cudaGetSymbolAddress((void**)&hresp,   g_hres);
    cudaGetSymbolAddress((void**)&h2p,     g_h2);
    cudaGetSymbolAddress((void**)&h2up,    g_h2u);
    cudaGetSymbolAddress((void**)&h2bp,    g_h2b);
    cudaGetSymbolAddress((void**)&sgp,     g_sg);
    cudaGetSymbolAddress((void**)&sup,     g_su);
    cudaGetSymbolAddress((void**)&sharedp, g_shared);
    cudaGetSymbolAddress((void**)&actBp,   g_actB);
    cudaGetSymbolAddress((void**)&pairoutp,g_pairout);
    cudaGetSymbolAddress((void**)&gpeBp,   g_gpeB);
    cudaGetSymbolAddress((void**)&upeBp,   g_upeB);
    cudaGetSymbolAddress((void**)&dpeBp,   g_dpeB);
    cudaGetSymbolAddress((void**)&wqr,     g_WqR);
    cudaGetSymbolAddress((void**)&wkr,     g_WkR);
    cudaGetSymbolAddress((void**)&wvr,     g_WvR);
    cudaGetSymbolAddress((void**)&wor,     g_WoR);
    cudaGetSymbolAddress((void**)&shgr,    g_shgR);
    cudaGetSymbolAddress((void**)&shur,    g_shuR);
    cudaGetSymbolAddress((void**)&shdr,    g_shdR);

    const float inv_sqrt_hd = 0.08838834764831845f;

    // side stream + fork/join events (host objects; created per call, leaked —
    // only ~2 calls ever happen: correctness + capture)
    cudaStream_t s2;
    cudaStreamCreateWithFlags(&s2, cudaStreamNonBlocking);
    cudaEvent_t evFork, evSide, evH2, evShared;
    cudaEventCreateWithFlags(&evFork,   cudaEventDisableTiming);
    cudaEventCreateWithFlags(&evSide,   cudaEventDisableTiming);
    cudaEventCreateWithFlags(&evH2,     cudaEventDisableTiming);
    cudaEventCreateWithFlags(&evShared, cudaEventDisableTiming);

    // fork: side stream handles input-only work (shared-weight rounding + transposes)
    cudaEventRecord(evFork, 0);
    cudaStreamWaitEvent(s2, evFork, 0);
    round_shared<<<dim3((H*SHF/4 + 255)/256, 3), 256, 0, s2>>>(
        (const float4*)sh_gate, (float4*)shgr, (const float4*)sh_up, (float4*)shur,
        (const float4*)sh_down, (float4*)shdr);
    transpose_eb<<<dim3(EI/32, H), 256, 0, s2>>>(gpe, (unsigned*)gpeBp, H, EI);
    transpose_eb<<<dim3(EI/32, H), 256, 0, s2>>>(upe, (unsigned*)upeBp, H, EI);
    transpose_eb<<<dim3(H/32, EI), 256, 0, s2>>>(dpe, (unsigned*)dpeBp, EI, H);
    cudaEventRecord(evSide, s2);

    // main stream: attention weight rounding + attention chain (tf32)
    round_attn<<<dim3((H*NH*HD/4 + 255)/256, 4), 256>>>(
        (const float4*)Wq, (float4*)wqr, (const float4*)Wk, (float4*)wkr,
        (const float4*)Wv, (float4*)wvr, (const float4*)Wo, (float4*)wor);
    rms_kernel<<<T, 256>>>(x, ln1, h1p, nullptr, nullptr);
    gemm_tc<<<dim3(H/64, T/64, 3), 128>>>(h1p, H, 0, wqr, wkr, wvr, H, 0, 0,
                                          qp, kp, vp, H, 0, nullptr, 0,
                                          H, 1.f, 0, 0);
    rope_kernel<<<T, 256>>>();
    gemm_tc<<<dim3(T/64, T/64, NH), 128>>>(qp, H, HD, kp, nullptr, nullptr, H, HD, 1,
                                           scoresp, nullptr, nullptr, T, (long)T*T, nullptr, 0,
                                           HD, inv_sqrt_hd, 1, 0);
    attn_softmax<<<dim3(T, NH), 256>>>();
    gemm_tc<<<dim3(HD/64, T/64, NH), 128>>>(scoresp, T, (long)T*T, vp, nullptr, nullptr, H, HD, 0,
                                            attnp, nullptr, nullptr, H, HD, nullptr, 0,
                                            T, 1.f, 2, 1);
    gemm_tc<<<dim3(H/64, T/64, 1), 128>>>(attnp, H, 0, wor, nullptr, nullptr, H, 0, 0,
                                          hresp, nullptr, nullptr, H, 0, x, 0,
                                          H, 1.f, 0, 0);

    // h2 (all three variants)
    rms_kernel<<<T, 256>>>(hresp, ln2, h2p, h2up, h2bp);
    cudaEventRecord(evH2, 0);

    // side stream: shared FFN (tf32) overlaps router + MoE on main
    cudaStreamWaitEvent(s2, evH2, 0);
    gemm_tc<<<dim3(SHF/64, T/64, 2), 128, 0, s2>>>(h2p, H, 0, shgr, shur, nullptr, SHF, 0, 0,
                                                   sgp, sup, nullptr, SHF, 0, nullptr, 0,
                                                   H, 1.f, 0, 0);
    silumul_kernel<<<(T*SHF/4 + 255)/256, 256, 0, s2>>>((float4*)sgp, (const float4*)sup, T*SHF/4);
    gemm_tc<<<dim3(H/64, T/64, 1), 128, 0, s2>>>(sgp, SHF, 0, shdr, nullptr, nullptr, H, 0, 0,
                                                 sharedp, nullptr, nullptr, H, 0, nullptr, 0,
                                                 SHF, 1.f, 0, 0);
    cudaEventRecord(evShared, s2);

    // main: router + MoE (bf16 LDSM)
    zero_cnt_kernel<<<1, 64>>>();
    router_kernel<<<T, 64>>>(gate_w);
    prefix_kernel<<<1, 32>>>();
    scatter_kernel<<<(NPAIR + 255)/256, 256>>>();
    cudaStreamWaitEvent(0, evSide, 0);   // transposed expert weights ready
    gemm_bf16_dual<<<dim3(EI/64, T/128, NEXP), 256>>>(
        h2bp, H, gpeBp, upeBp, (long)H*EI, EI, actBp, EI, H);
    gemm_bf16_one<<<dim3(H/64, T/128, NEXP), 128>>>(
        actBp, EI, dpeBp, (long)EI*H, H, pairoutp, H, EI);

    // join shared FFN, then combine
    cudaStreamWaitEvent(0, evShared, 0);
    combine_kernel<<<T, 256>>>(out);
}

// round 13
// speedup vs baseline: 1.7655x; 1.0834x over previous
#include <cuda_runtime.h>
#include <cuda_bf16.h>
#include <math.h>

#define T 1024
#define H 1280
#define NH 10
#define HD 128
#define EI 896
#define NEXP 64
#define TOPK 6
#define SHF 1792
#define NPAIR (T*TOPK)

// ---------------- device scratch ----------------
static __device__ float g_h1[T*H];
static __device__ float g_q[T*H];
static __device__ float g_k[T*H];
static __device__ float g_v[T*H];
static __device__ float g_scores[NH*T*T];
static __device__ float g_attnout[T*H];
static __device__ float g_hres[T*H];
static __device__ float g_h2[T*H];              // tf32-rounded fp32 (shared FFN)
static __device__ float g_h2u[T*H];             // unrounded fp32 (router)
static __device__ __nv_bfloat16 g_h2b[T*H];     // bf16 (MoE pass1 A)
static __device__ float g_sg[T*SHF];
static __device__ float g_su[T*SHF];
static __device__ float g_shared[T*H];
// bf16 expert weights, [e][k][n] plain bf16
static __device__ __nv_bfloat16 g_gpeB[(size_t)NEXP*H*EI];
static __device__ __nv_bfloat16 g_upeB[(size_t)NEXP*H*EI];
static __device__ __nv_bfloat16 g_dpeB[(size_t)NEXP*EI*H];
static __device__ __nv_bfloat16 g_actB[(size_t)(NPAIR+128)*EI];
static __device__ float g_pairout[(size_t)NPAIR*H];
// rounded fp32 weight copies (tf32 GEMMs)
static __device__ float g_WqR[H*NH*HD];
static __device__ float g_WkR[H*NH*HD];
static __device__ float g_WvR[H*NH*HD];
static __device__ float g_WoR[NH*HD*H];
static __device__ float g_shgR[H*SHF];
static __device__ float g_shuR[H*SHF];
static __device__ float g_shdR[SHF*H];
static __device__ int   g_cnt[NEXP];
static __device__ int   g_off[NEXP];
static __device__ int   g_cur[NEXP];
static __device__ int   g_tokE[NPAIR];
static __device__ float g_tokW[NPAIR];
static __device__ int   g_pairTok[NPAIR];
static __device__ float g_pairW[NPAIR];
static __device__ int   g_pairPos[NPAIR];

// ---------------- helpers ----------------
__device__ __forceinline__ void mma_tf32(float4& c, const unsigned a[4], const unsigned b[2]) {
    asm volatile("mma.sync.aligned.m16n8k8.row.col.f32.tf32.tf32.f32 "
        "{%0,%1,%2,%3}, {%4,%5,%6,%7}, {%8,%9}, {%0,%1,%2,%3};"
        : "+f"(c.x), "+f"(c.y), "+f"(c.z), "+f"(c.w)
        : "r"(a[0]), "r"(a[1]), "r"(a[2]), "r"(a[3]), "r"(b[0]), "r"(b[1]));
}
__device__ __forceinline__ void mma_bf16(float4& c, const unsigned a[4], const unsigned b[2]) {
    asm volatile("mma.sync.aligned.m16n8k16.row.col.f32.bf16.bf16.f32 "
        "{%0,%1,%2,%3}, {%4,%5,%6,%7}, {%8,%9}, {%0,%1,%2,%3};"
        : "+f"(c.x), "+f"(c.y), "+f"(c.z), "+f"(c.w)
        : "r"(a[0]), "r"(a[1]), "r"(a[2]), "r"(a[3]), "r"(b[0]), "r"(b[1]));
}
__device__ __forceinline__ float rtf(float f) {
    unsigned r; asm("cvt.rna.tf32.f32 %0, %1;" : "=r"(r) : "f"(f));
    return __uint_as_float(r);
}
__device__ __forceinline__ void cp16(const void* smem, const void* gmem) {
    unsigned sa = (unsigned)__cvta_generic_to_shared(smem);
    asm volatile("cp.async.cg.shared.global [%0], [%1], 16;" :: "r"(sa), "l"(gmem));
}
__device__ __forceinline__ void ldsm4(unsigned& r0, unsigned& r1, unsigned& r2, unsigned& r3,
                                      unsigned addr) {
    asm volatile("ldmatrix.sync.aligned.m8n8.x4.shared.b16 {%0,%1,%2,%3}, [%4];"
        : "=r"(r0), "=r"(r1), "=r"(r2), "=r"(r3) : "r"(addr));
}
__device__ __forceinline__ void ldsm4t(unsigned& r0, unsigned& r1, unsigned& r2, unsigned& r3,
                                       unsigned addr) {
    asm volatile("ldmatrix.sync.aligned.m8n8.x4.trans.shared.b16 {%0,%1,%2,%3}, [%4];"
        : "=r"(r0), "=r"(r1), "=r"(r2), "=r"(r3) : "r"(addr));
}
#define CP_COMMIT asm volatile("cp.async.commit_group;")
#define CP_WAIT1  asm volatile("cp.async.wait_group 1;")

#define AST 36    // tf32 A/transB row stride (32k + 4 pad) words
#define BST 72    // tf32 B row stride (64n + 8 pad) words

// ---------------- weight rounding: attention mats (z 0..3) ----------------
__global__ void round_attn(const float4* w0, float4* o0, const float4* w1, float4* o1,
                           const float4* w2, float4* o2, const float4* w3, float4* o3) {
    int z = blockIdx.y;
    const float4* in; float4* out;
    switch (z) { case 0: in=w0; out=o0; break; case 1: in=w1; out=o1; break;
                 case 2: in=w2; out=o2; break; default: in=w3; out=o3; }
    int i = blockIdx.x*256 + threadIdx.x;
    if (i < H*NH*HD/4) {
        float4 v = in[i];
        v.x = rtf(v.x); v.y = rtf(v.y); v.z = rtf(v.z); v.w = rtf(v.w);
        out[i] = v;
    }
}

// ---------------- weight rounding: shared-FFN mats (z 0..2) ----------------
__global__ void round_shared(const float4* w4, float4* o4, const float4* w5, float4* o5,
                             const float4* w6, float4* o6) {
    int z = blockIdx.y;
    const float4* in; float4* out; int n4;
    switch (z) { case 0: in=w4; out=o4; n4=H*SHF/4; break;
                 case 1: in=w5; out=o5; n4=H*SHF/4; break;
                 default: in=w6; out=o6; n4=SHF*H/4; }
    int i = blockIdx.x*256 + threadIdx.x;
    if (i < n4) {
        float4 v = in[i];
        v.x = rtf(v.x); v.y = rtf(v.y); v.z = rtf(v.z); v.w = rtf(v.w);
        out[i] = v;
    }
}

// ---------------- RMSNorm ----------------
__global__ void rms_kernel(const float* __restrict__ x, const float* __restrict__ w,
                           float* __restrict__ out, float* __restrict__ outu,
                           __nv_bfloat16* __restrict__ outb) {
    int t = blockIdx.x;
    const float* xr = x + (long)t*H;
    __shared__ float red[256];
    float s = 0.f;
    for (int i = threadIdx.x; i < H; i += 256) { float v = xr[i]; s += v*v; }
    red[threadIdx.x] = s; __syncthreads();
    for (int k = 128; k > 0; k >>= 1) {
        if (threadIdx.x < k) red[threadIdx.x] += red[threadIdx.x + k];
        __syncthreads();
    }
    float r = rsqrtf(red[0]/(float)H + 1e-6f);
    for (int i = threadIdx.x; i < H; i += 256) {
        float v = w[i]*xr[i]*r;
        if (out)  out[(long)t*H + i] = rtf(v);
        if (outu) outu[(long)t*H + i] = v;
        if (outb) outb[(long)t*H + i] = __float2bfloat16(v);
    }
}

// ---------------- tf32 GEMM (R3-proven core): 64x64, BK32, 2-stage, 128 thr ----------
// mode: 0 none, 1 causal block skip, 2 K capped at m0+64.
__global__ void __launch_bounds__(128)
gemm_tc(const float* __restrict__ A, int lda, long sA,
        const float* __restrict__ B, const float* __restrict__ Bb, const float* __restrict__ Bc,
        int ldb, long sB, int transB,
        float* __restrict__ C, float* __restrict__ Cb, float* __restrict__ Cc,
        int ldc, long sC,
        const float* __restrict__ res, long sR,
        int K, float alpha, int mode, int roundC) {
    int m0 = blockIdx.y*64, n0 = blockIdx.x*64;
    if (mode == 1 && n0 >= m0 + 64) return;
    int bz = blockIdx.z;
    A += (long)bz*sA;
    if (Bb) {
        if (bz == 1) { B = Bb; C = Cb; }
        else if (bz == 2) { B = Bc; C = Cc; }
    } else {
        B += (long)bz*sB; C += (long)bz*sC; if (res) res += (long)bz*sR;
    }
    int Klim = (mode == 2) ? (m0 + 64 < K ? m0 + 64 : K) : K;

    __shared__ float As[2][64*AST];
    __shared__ float Bs[2][2304];
    int tid = threadIdx.x;
    int lane = tid & 31, warpId = tid >> 5;
    int g = lane >> 2, tig = lane & 3;
    int warp_m = (warpId & 1) * 32, warp_n = (warpId >> 1) * 32;
    float4 acc[2][4];
    #pragma unroll
    for (int i = 0; i < 2; i++)
        #pragma unroll
        for (int j = 0; j < 4; j++) acc[i][j] = make_float4(0.f,0.f,0.f,0.f);

#define G_LOAD(sidx, k0v) do { int _k0 = (k0v); if (_k0 < Klim) { \
    _Pragma("unroll") for (int i = 0; i < 4; i++) { int idx = tid + i*128; int r = idx >> 3, c4 = (idx & 7) << 2; \
        cp16(&As[sidx][r*AST + c4], &A[(long)(m0+r)*lda + _k0 + c4]); } \
    if (!transB) { \
        _Pragma("unroll") for (int i = 0; i < 4; i++) { int idx = tid + i*128; int r = idx >> 4, c4 = (idx & 15) << 2; \
            cp16(&Bs[sidx][r*BST + c4], &B[(long)(_k0+r)*ldb + n0 + c4]); } \
    } else { \
        _Pragma("unroll") for (int i = 0; i < 4; i++) { int idx = tid + i*128; int r = idx >> 3, c4 = (idx & 7) << 2; \
            cp16(&Bs[sidx][r*AST + c4], &B[(long)(n0+r)*ldb + _k0 + c4]); } \
    } } CP_COMMIT; } while(0)

    int nIter = Klim >> 5;
    G_LOAD(0, 0);
    for (int it = 0; it < nIter; it++) {
        int s = it & 1;
        G_LOAD(s ^ 1, (it + 1) << 5);
        CP_WAIT1;
        __syncthreads();
        #pragma unroll
        for (int kk = 0; kk < 32; kk += 8) {
            unsigned a[2][4], b[4][2];
            #pragma unroll
            for (int mi = 0; mi < 2; mi++) {
                const float* ap = &As[s][(warp_m + mi*16 + g)*AST + kk + tig];
                a[mi][0] = __float_as_uint(ap[0]);
                a[mi][1] = __float_as_uint(ap[8*AST]);
                a[mi][2] = __float_as_uint(ap[4]);
                a[mi][3] = __float_as_uint(ap[8*AST + 4]);
            }
            if (!transB) {
                #pragma unroll
                for (int ni = 0; ni < 4; ni++) {
                    int col = warp_n + ni*8 + g;
                    b[ni][0] = __float_as_uint(Bs[s][(kk+tig)*BST + col]);
                    b[ni][1] = __float_as_uint(Bs[s][(kk+tig+4)*BST + col]);
                }
            } else {
                #pragma unroll
                for (int ni = 0; ni < 4; ni++) {
                    const float* bp = &Bs[s][(warp_n + ni*8 + g)*AST + kk + tig];
                    b[ni][0] = __float_as_uint(bp[0]);
                    b[ni][1] = __float_as_uint(bp[4]);
                }
            }
            #pragma unroll
            for (int mi = 0; mi < 2; mi++)
                #pragma unroll
                for (int ni = 0; ni < 4; ni++) mma_tf32(acc[mi][ni], a[mi], b[ni]);
        }
        __syncthreads();
    }
#undef G_LOAD
    #pragma unroll
    for (int mi = 0; mi < 2; mi++) {
        #pragma unroll
        for (int ni = 0; ni < 4; ni++) {
            int row = m0 + warp_m + mi*16 + g;
            int col = n0 + warp_n + ni*8 + 2*tig;
            float4 c = acc[mi][ni];
            float2 v0 = { alpha*c.x, alpha*c.y };
            float2 v1 = { alpha*c.z, alpha*c.w };
            if (res) {
                float2 r0 = *(const float2*)&res[(long)row*ldc + col];
                float2 r1 = *(const float2*)&res[(long)(row+8)*ldc + col];
                v0.x += r0.x; v0.y += r0.y; v1.x += r1.x; v1.y += r1.y;
            }
            if (roundC) {
                v0.x = rtf(v0.x); v0.y = rtf(v0.y);
                v1.x = rtf(v1.x); v1.y = rtf(v1.y);
            }
            *(float2*)&C[(long)row*ldc + col] = v0;
            *(float2*)&C[(long)(row+8)*ldc + col] = v1;
        }
    }
}

// ---------------- RoPE (rounds q,k only; v rounded at Wv GEMM epilogue) ---------------
__global__ void rope_kernel() {
    int t = blockIdx.x, tid = threadIdx.x;
    __shared__ float cs[64], sn[64];
    if (tid < 64) {
        float inv = powf(10000.0f, -(float)tid / 64.0f);
        float fr = (float)t * inv;
        cs[tid] = cosf(fr); sn[tid] = sinf(fr);
    }
    __syncthreads();
    for (int idx = tid; idx < NH*64; idx += 256) {
        int hh = idx >> 6, j = idx & 63;
        long b = (long)t*H + hh*HD;
        float c = cs[j], s = sn[j];
        float q1 = g_q[b+j], q2 = g_q[b+j+64];
        g_q[b+j]    = rtf(q1*c - q2*s);
        g_q[b+j+64] = rtf(q2*c + q1*s);
        float k1 = g_k[b+j], k2 = g_k[b+j+64];
        g_k[b+j]    = rtf(k1*c - k2*s);
        g_k[b+j+64] = rtf(k2*c + k1*s);
    }
}

// ---------------- causal softmax (zeros to next 64-boundary) ----------------
__global__ void attn_softmax() {
    int t = blockIdx.x, hh = blockIdx.y, tid = threadIdx.x;
    float* row = g_scores + ((long)hh*T + t)*(long)T;
    int len = t + 1;
    int zend = ((t >> 6) + 1) << 6;
    __shared__ float red[256];
    float mx = -3.0e38f;
    for (int i = tid; i < len; i += 256) mx = fmaxf(mx, row[i]);
    red[tid] = mx; __syncthreads();
    for (int s = 128; s > 0; s >>= 1) { if (tid < s) red[tid] = fmaxf(red[tid], red[tid+s]); __syncthreads(); }
    mx = red[0]; __syncthreads();
    float sum = 0.f;
    for (int i = tid; i < len; i += 256) { float e = __expf(row[i]-mx); row[i] = e; sum += e; }
    red[tid] = sum; __syncthreads();
    for (int s = 128; s > 0; s >>= 1) { if (tid < s) red[tid] += red[tid+s]; __syncthreads(); }
    float inv = 1.0f / red[0];
    for (int i = tid; i < len; i += 256) row[i] = rtf(row[i] * inv);
    for (int i = len + tid; i < zend; i += 256) row[i] = 0.f;
}

// ------- expert transpose -> bf16 [e][k][n], vectorized ------------------------------
__global__ void __launch_bounds__(256) transpose_eb(const float* __restrict__ in,
                                                    unsigned* __restrict__ out,
                                                    int R, int C) {
    int r = blockIdx.y;
    int c0 = blockIdx.x * 32;
    __shared__ unsigned sm[16][68];
    int tid = threadIdx.x;
    {
        int cpair = tid >> 4;
        int e4 = (tid & 15) << 2;
        const float* basep = in + ((long)r*C + c0 + 2*cpair) * 64 + e4;
        float4 a = *(const float4*)basep;
        float4 b = *(const float4*)(basep + 64);
        __nv_bfloat162 t0 = __floats2bfloat162_rn(a.x, b.x);
        __nv_bfloat162 t1 = __floats2bfloat162_rn(a.y, b.y);
        __nv_bfloat162 t2 = __floats2bfloat162_rn(a.z, b.z);
        __nv_bfloat162 t3 = __floats2bfloat162_rn(a.w, b.w);
        uint4 u = { *(unsigned*)&t0, *(unsigned*)&t1, *(unsigned*)&t2, *(unsigned*)&t3 };
        *(uint4*)&sm[cpair][e4] = u;
    }
    __syncthreads();
    {
        int e = tid >> 2;
        int grp = (tid & 3) << 2;
        uint4 v;
        v.x = sm[grp+0][e];
        v.y = sm[grp+1][e];
        v.z = sm[grp+2][e];
        v.w = sm[grp+3][e];
        long C2 = C >> 1;
        *(uint4*)&out[(long)e*R*C2 + (long)r*C2 + (c0 >> 1) + grp] = v;
    }
}

// ---------------- router ----------------
__global__ void zero_cnt_kernel() { if (threadIdx.x < NEXP) g_cnt[threadIdx.x] = 0; }

__global__ void router_kernel(const float* __restrict__ gw) {
    int t = blockIdx.x, e = threadIdx.x;
    const float* hr = g_h2u + (long)t*H;
    float s = 0.f;
    for (int h = 0; h < H; h++) s += hr[h] * gw[h*NEXP + e];
    __shared__ float probs[NEXP];
    probs[e] = s;
    __syncthreads();
    if (e == 0) {
        float mx = -3e38f;
        for (int i = 0; i < NEXP; i++) mx = fmaxf(mx, probs[i]);
        float sum = 0.f;
        for (int i = 0; i < NEXP; i++) { probs[i] = __expf(probs[i]-mx); sum += probs[i]; }
        float inv = 1.f/sum;
        for (int i = 0; i < NEXP; i++) probs[i] *= inv;
        int ti[TOPK]; float tw[TOPK]; float ws = 0.f;
        for (int j = 0; j < TOPK; j++) {
            int bi = 0; float bv = -1.f;
            for (int i = 0; i < NEXP; i++) if (probs[i] > bv) { bv = probs[i]; bi = i; }
            ti[j] = bi; tw[j] = bv; ws += bv; probs[bi] = -2.f;
        }
        float wi = 1.f/ws;
        for (int j = 0; j < TOPK; j++) {
            g_tokE[t*TOPK+j] = ti[j];
            g_tokW[t*TOPK+j] = tw[j]*wi;
            atomicAdd(&g_cnt[ti[j]], 1);
        }
    }
}

__global__ void prefix_kernel() {
    if (threadIdx.x == 0) {
        int s = 0;
        for (int e = 0; e < NEXP; e++) { g_off[e] = s; g_cur[e] = s; s += g_cnt[e]; }
    }
}

__global__ void scatter_kernel() {
    int i = blockIdx.x*256 + threadIdx.x;
    if (i < NPAIR) {
        int e = g_tokE[i];
        int pos = atomicAdd(&g_cur[e], 1);
        g_pairTok[pos] = i / TOPK;
        g_pairW[pos]   = g_tokW[i];
        g_pairPos[i]   = pos;
    }
}

// -------- bf16 dual GEMM + SiLU (MoE pass1): CTA 128x128, 512 thr, warp 32x32, LDSM --
__global__ void __launch_bounds__(512)
gemm_bf16_dual(const __nv_bfloat16* __restrict__ A, int lda,
               const __nv_bfloat16* __restrict__ B1g, const __nv_bfloat16* __restrict__ B2g,
               long sB, int ldb,
               __nv_bfloat16* __restrict__ Cout, int ldc,
               int K) {
    int e = blockIdx.z;
    int m0 = blockIdx.y * 128;
    int cnt = g_cnt[e], base = g_off[e];
    if (m0 >= cnt) return;
    const __nv_bfloat16* B1 = B1g + (long)e*sB;
    const __nv_bfloat16* B2 = B2g + (long)e*sB;
    int n0 = blockIdx.x * 128;

    __shared__ int stok[128];
    __shared__ unsigned As[3][128][12];    // 48B rows
    __shared__ unsigned Bs1[3][16][68];    // 272B rows: 128 bf16 + 16B pad
    __shared__ unsigned Bs2[3][16][68];
    int tid = threadIdx.x;
    int lane = tid & 31, warpId = tid >> 5;          // 16 warps
    int g = lane >> 2, tig = lane & 3;
    int warp_m = (warpId & 3) * 32, warp_n = (warpId >> 2) * 32;
    if (tid < 128) stok[tid] = (m0 + tid < cnt) ? g_pairTok[base + m0 + tid] : 0;
    __syncthreads();
    float4 accG[2][4], accU[2][4];
    #pragma unroll
    for (int i = 0; i < 2; i++)
        #pragma unroll
        for (int j = 0; j < 4; j++) { accG[i][j] = make_float4(0,0,0,0); accU[i][j] = make_float4(0,0,0,0); }

#define D_LOAD(sidx, k0v) do { int _k0 = (k0v); if (_k0 < K) { \
    if (tid < 256) { int r = tid >> 1, ch = tid & 1; \
      cp16(&As[sidx][r][ch*4], &A[(long)stok[r]*lda + _k0 + ch*8]); } \
    else { int t2 = tid - 256; int r = t2 >> 4, ch = t2 & 15; \
      cp16(&Bs1[sidx][r][ch*4], &B1[(long)(_k0+r)*ldb + n0 + ch*8]); \
      cp16(&Bs2[sidx][r][ch*4], &B2[(long)(_k0+r)*ldb + n0 + ch*8]); } \
    } CP_COMMIT; } while(0)

    const int nIter = K >> 4;
    D_LOAD(0, 0);
    D_LOAD(1, 16);
    int st = 0;
    int half16 = (lane >> 4) * 16;
    for (int it = 0; it < nIter; it++) {
        CP_WAIT1;
        __syncthreads();
        unsigned aBase = (unsigned)__cvta_generic_to_shared(&As[st][0][0]);
        unsigned b1Base = (unsigned)__cvta_generic_to_shared(&Bs1[st][0][0]);
        unsigned b2Base = (unsigned)__cvta_generic_to_shared(&Bs2[st][0][0]);
        unsigned a[2][4], b1[4][2], b2[4][2];
        #pragma unroll
        for (int mi = 0; mi < 2; mi++) {
            int row = warp_m + mi*16 + (lane & 15);
            ldsm4(a[mi][0], a[mi][1], a[mi][2], a[mi][3], aBase + row*48 + half16);
        }
        #pragma unroll
        for (int nh = 0; nh < 2; nh++) {
            int krow = lane & 15;
            int col = warp_n + nh*16 + (lane >> 4) * 8;
            ldsm4t(b1[nh*2][0], b1[nh*2][1], b1[nh*2+1][0], b1[nh*2+1][1],
                   b1Base + krow*272 + col*2);
            ldsm4t(b2[nh*2][0], b2[nh*2][1], b2[nh*2+1][0], b2[nh*2+1][1],
                   b2Base + krow*272 + col*2);
        }
        #pragma unroll
        for (int mi = 0; mi < 2; mi++)
            #pragma unroll
            for (int ni = 0; ni < 4; ni++) {
                mma_bf16(accG[mi][ni], a[mi], b1[ni]);
                mma_bf16(accU[mi][ni], a[mi], b2[ni]);
            }
        int wst = st + 2; if (wst >= 3) wst -= 3;
        D_LOAD(wst, (it + 2) << 4);
        if (++st == 3) st = 0;
    }
#undef D_LOAD
    #pragma unroll
    for (int mi = 0; mi < 2; mi++) {
        #pragma unroll
        for (int ni = 0; ni < 4; ni++) {
            int mrow = warp_m + mi*16 + g;
            int col = n0 + warp_n + ni*8 + 2*tig;
            float4 cg = accG[mi][ni], cu = accU[mi][ni];
            if (m0 + mrow < cnt) {
                float g0 = cg.x, g1 = cg.y;
                __nv_bfloat162 v = __floats2bfloat162_rn((g0/(1.f+__expf(-g0)))*cu.x,
                                                         (g1/(1.f+__expf(-g1)))*cu.y);
                *(__nv_bfloat162*)&Cout[(long)(base+m0+mrow)*ldc + col] = v;
            }
            if (m0 + mrow + 8 < cnt) {
                float g0 = cg.z, g1 = cg.w;
                __nv_bfloat162 v = __floats2bfloat162_rn((g0/(1.f+__expf(-g0)))*cu.z,
                                                         (g1/(1.f+__expf(-g1)))*cu.w);
                *(__nv_bfloat162*)&Cout[(long)(base+m0+mrow+8)*ldc + col] = v;
            }
        }
    }
}

// -------- bf16 single GEMM (MoE pass2): CTA 128x128, 256 thr, warp 64x32, LDSM -------
__global__ void __launch_bounds__(256)
gemm_bf16_one(const __nv_bfloat16* __restrict__ A, int lda,
              const __nv_bfloat16* __restrict__ Bg, long sB, int ldb,
              float* __restrict__ Cout, int ldc,
              int K) {
    int e = blockIdx.z;
    int m0 = blockIdx.y * 128;
    int cnt = g_cnt[e], base = g_off[e];
    if (m0 >= cnt) return;
    const __nv_bfloat16* B = Bg + (long)e*sB;
    int n0 = blockIdx.x * 128;

    __shared__ unsigned As[3][128][12];
    __shared__ unsigned Bs[3][16][68];
    int tid = threadIdx.x;
    int lane = tid & 31, warpId = tid >> 5;          // 8 warps
    int g = lane >> 2, tig = lane & 3;
    int warp_m = (warpId & 1) * 64, warp_n = (warpId >> 1) * 32;
    float4 acc[4][4];
    #pragma unroll
    for (int i = 0; i < 4; i++)
        #pragma unroll
        for (int j = 0; j < 4; j++) acc[i][j] = make_float4(0,0,0,0);

#define S_LOAD(sidx, k0v) do { int _k0 = (k0v); if (_k0 < K) { \
    { int r = tid >> 1, ch = tid & 1; \
      int rr = m0 + r; if (rr >= cnt) rr = cnt - 1; \
      cp16(&As[sidx][r][ch*4], &A[(long)(base + rr)*lda + _k0 + ch*8]); } \
    { int r = tid >> 4, ch = tid & 15; \
      cp16(&Bs[sidx][r][ch*4], &B[(long)(_k0+r)*ldb + n0 + ch*8]); } \
    } CP_COMMIT; } while(0)

    const int nIter = K >> 4;
    S_LOAD(0, 0);
    S_LOAD(1, 16);
    int st = 0;
    int half16 = (lane >> 4) * 16;
    for (int it = 0; it < nIter; it++) {
        CP_WAIT1;
        __syncthreads();
        unsigned aBase = (unsigned)__cvta_generic_to_shared(&As[st][0][0]);
        unsigned bBase = (unsigned)__cvta_generic_to_shared(&Bs[st][0][0]);
        unsigned a[4][4], b[4][2];
        #pragma unroll
        for (int mi = 0; mi < 4; mi++) {
            int row = warp_m + mi*16 + (lane & 15);
            ldsm4(a[mi][0], a[mi][1], a[mi][2], a[mi][3], aBase + row*48 + half16);
        }
        #pragma unroll
        for (int nh = 0; nh < 2; nh++) {
            int krow = lane & 15;
            int col = warp_n + nh*16 + (lane >> 4) * 8;
            ldsm4t(b[nh*2][0], b[nh*2][1], b[nh*2+1][0], b[nh*2+1][1],
                   bBase + krow*272 + col*2);
        }
        #pragma unroll
        for (int mi = 0; mi < 4; mi++)
            #pragma unroll
            for (int ni = 0; ni < 4; ni++) mma_bf16(acc[mi][ni], a[mi], b[ni]);
        int wst = st + 2; if (wst >= 3) wst -= 3;
        S_LOAD(wst, (it + 2) << 4);
        if (++st == 3) st = 0;
    }
#undef S_LOAD
    #pragma unroll
    for (int mi = 0; mi < 4; mi++) {
        #pragma unroll
        for (int ni = 0; ni < 4; ni++) {
            int mrow = warp_m + mi*16 + g;
            int col = n0 + warp_n + ni*8 + 2*tig;
            float4 c = acc[mi][ni];
            if (m0 + mrow < cnt)
                *(float2*)&Cout[(long)(base+m0+mrow)*ldc + col] = make_float2(c.x, c.y);
            if (m0 + mrow + 8 < cnt)
                *(float2*)&Cout[(long)(base+m0+mrow+8)*ldc + col] = make_float2(c.z, c.w);
        }
    }
}

// ---------------- shared-FFN activation (vectorized, rounds output) ----------------
__global__ void silumul_kernel(float4* __restrict__ g, const float4* __restrict__ u, int n4) {
    int i = blockIdx.x*256 + threadIdx.x;
    if (i < n4) {
        float4 x = g[i];
        float4 y = u[i];
        x.x = rtf((x.x / (1.f + __expf(-x.x))) * y.x);
        x.y = rtf((x.y / (1.f + __expf(-x.y))) * y.y);
        x.z = rtf((x.z / (1.f + __expf(-x.z))) * y.z);
        x.w = rtf((x.w / (1.f + __expf(-x.w))) * y.w);
        g[i] = x;
    }
}

// ---------------- final combine ----------------
__global__ void combine_kernel(float* __restrict__ out) {
    int t = blockIdx.x;
    int pos[TOPK]; float w[TOPK];
    #pragma unroll
    for (int j = 0; j < TOPK; j++) {
        pos[j] = g_pairPos[t*TOPK + j];
        w[j]   = g_pairW[pos[j]];
    }
    for (int h = threadIdx.x; h < H; h += 256) {
        float s = g_hres[(long)t*H + h] + g_shared[(long)t*H + h];
        #pragma unroll
        for (int j = 0; j < TOPK; j++)
            s += w[j] * g_pairout[(long)pos[j]*H + h];
        out[(long)t*H + h] = s;
    }
}

// ---------------- launch ----------------
extern "C" void kernel_launch(void* const* d_in, const int* in_sizes, int n_in,
                              void* d_out, int out_size) {
    (void)in_sizes; (void)n_in; (void)out_size;
    const float* x       = (const float*)d_in[0];
    const float* ln1     = (const float*)d_in[1];
    const float* ln2     = (const float*)d_in[2];
    const float* Wq      = (const float*)d_in[3];
    const float* Wk      = (const float*)d_in[4];
    const float* Wv      = (const float*)d_in[5];
    const float* Wo      = (const float*)d_in[6];
    const float* gate_w  = (const float*)d_in[7];
    const float* gpe     = (const float*)d_in[8];
    const float* upe     = (const float*)d_in[9];
    const float* dpe     = (const float*)d_in[10];
    const float* sh_gate = (const float*)d_in[11];
    const float* sh_up   = (const float*)d_in[12];
    const float* sh_down = (const float*)d_in[13];
    float* out = (float*)d_out;

    float *h1p,*qp,*kp,*vp,*scoresp,*attnp,*hresp,*h2p,*h2up,*sgp,*sup,*sharedp,*pairoutp;
    __nv_bfloat16 *h2bp,*actBp,*gpeBp,*upeBp,*dpeBp;
    float *wqr,*wkr,*wvr,*wor,*shgr,*shur,*shdr;
    cudaGetSymbolAddress((void**)&h1p,     g_h1);
    cudaGetSymbolAddress((void**)&qp,      g_q);
    cudaGetSymbolAddress((void**)&kp,      g_k);
    cudaGetSymbolAddress((void**)&vp,      g_v);
    cudaGetSymbolAddress((void**)&scoresp, g_scores);
    cudaGetSymbolAddress((void**)&attnp,   g_attnout);
    cudaGetSymbolAddress((void**)&hresp,   g_hres);
    cudaGetSymbolAddress((void**)&h2p,     g_h2);
    cudaGetSymbolAddress((void**)&h2up,    g_h2u);
    cudaGetSymbolAddress((void**)&h2bp,    g_h2b);
    cudaGetSymbolAddress((void**)&sgp,     g_sg);
    cudaGetSymbolAddress((void**)&sup,     g_su);
    cudaGetSymbolAddress((void**)&sharedp, g_shared);
    cudaGetSymbolAddress((void**)&actBp,   g_actB);
    cudaGetSymbolAddress((void**)&pairoutp,g_pairout);
    cudaGetSymbolAddress((void**)&gpeBp,   g_gpeB);
    cudaGetSymbolAddress((void**)&upeBp,   g_upeB);
    cudaGetSymbolAddress((void**)&dpeBp,   g_dpeB);
    cudaGetSymbolAddress((void**)&wqr,     g_WqR);
    cudaGetSymbolAddress((void**)&wkr,     g_WkR);
    cudaGetSymbolAddress((void**)&wvr,     g_WvR);
    cudaGetSymbolAddress((void**)&wor,     g_WoR);
    cudaGetSymbolAddress((void**)&shgr,    g_shgR);
    cudaGetSymbolAddress((void**)&shur,    g_shuR);
    cudaGetSymbolAddress((void**)&shdr,    g_shdR);

    const float inv_sqrt_hd = 0.08838834764831845f;

    cudaStream_t s2;
    cudaStreamCreateWithFlags(&s2, cudaStreamNonBlocking);
    cudaEvent_t evFork, evH1, evV, evSide, evH2, evShared;
    cudaEventCreateWithFlags(&evFork,   cudaEventDisableTiming);
    cudaEventCreateWithFlags(&evH1,     cudaEventDisableTiming);
    cudaEventCreateWithFlags(&evV,      cudaEventDisableTiming);
    cudaEventCreateWithFlags(&evSide,   cudaEventDisableTiming);
    cudaEventCreateWithFlags(&evH2,     cudaEventDisableTiming);
    cudaEventCreateWithFlags(&evShared, cudaEventDisableTiming);

    // fork: side stream starts with shared-weight rounding
    cudaEventRecord(evFork, 0);
    cudaStreamWaitEvent(s2, evFork, 0);
    round_shared<<<dim3((H*SHF/4 + 255)/256, 3), 256, 0, s2>>>(
        (const float4*)sh_gate, (float4*)shgr, (const float4*)sh_up, (float4*)shur,
        (const float4*)sh_down, (float4*)shdr);

    // main: attention weight rounding + rms1
    round_attn<<<dim3((H*NH*HD/4 + 255)/256, 4), 256>>>(
        (const float4*)Wq, (float4*)wqr, (const float4*)Wk, (float4*)wkr,
        (const float4*)Wv, (float4*)wvr, (const float4*)Wo, (float4*)wor);
    rms_kernel<<<T, 256>>>(x, ln1, h1p, nullptr, nullptr);
    cudaEventRecord(evH1, 0);

    // side: Wv projection (rounded output = rope's old v-rounding), then transposes
    cudaStreamWaitEvent(s2, evH1, 0);
    gemm_tc<<<dim3(H/64, T/64, 1), 128, 0, s2>>>(h1p, H, 0, wvr, nullptr, nullptr, H, 0, 0,
                                                 vp, nullptr, nullptr, H, 0, nullptr, 0,
                                                 H, 1.f, 0, 1);
    cudaEventRecord(evV, s2);
    transpose_eb<<<dim3(EI/32, H), 256, 0, s2>>>(gpe, (unsigned*)gpeBp, H, EI);
    transpose_eb<<<dim3(EI/32, H), 256, 0, s2>>>(upe, (unsigned*)upeBp, H, EI);
    transpose_eb<<<dim3(H/32, EI), 256, 0, s2>>>(dpe, (unsigned*)dpeBp, EI, H);
    cudaEventRecord(evSide, s2);

    // main: Q,K projections + attention chain (tf32)
    gemm_tc<<<dim3(H/64, T/64, 2), 128>>>(h1p, H, 0, wqr, wkr, nullptr, H, 0, 0,
                                          qp, kp, nullptr, H, 0, nullptr, 0,
                                          H, 1.f, 0, 0);
    rope_kernel<<<T, 256>>>();
    gemm_tc<<<dim3(T/64, T/64, NH), 128>>>(qp, H, HD, kp, nullptr, nullptr, H, HD, 1,
                                           scoresp, nullptr, nullptr, T, (long)T*T, nullptr, 0,
                                           HD, inv_sqrt_hd, 1, 0);
    attn_softmax<<<dim3(T, NH), 256>>>();
    cudaStreamWaitEvent(0, evV, 0);   // v ready (side)
    gemm_tc<<<dim3(HD/64, T/64, NH), 128>>>(scoresp, T, (long)T*T, vp, nullptr, nullptr, H, HD, 0,
                                            attnp, nullptr, nullptr, H, HD, nullptr, 0,
                                            T, 1.f, 2, 1);
    gemm_tc<<<dim3(H/64, T/64, 1), 128>>>(attnp, H, 0, wor, nullptr, nullptr, H, 0, 0,
                                          hresp, nullptr, nullptr, H, 0, x, 0,
                                          H, 1.f, 0, 0);

    // h2 (all three variants)
    rms_kernel<<<T, 256>>>(hresp, ln2, h2p, h2up, h2bp);
    cudaEventRecord(evH2, 0);

    // side: shared FFN (tf32) overlaps router + MoE on main
    cudaStreamWaitEvent(s2, evH2, 0);
    gemm_tc<<<dim3(SHF/64, T/64, 2), 128, 0, s2>>>(h2p, H, 0, shgr, shur, nullptr, SHF, 0, 0,
                                                   sgp, sup, nullptr, SHF, 0, nullptr, 0,
                                                   H, 1.f, 0, 0);
    silumul_kernel<<<(T*SHF/4 + 255)/256, 256, 0, s2>>>((float4*)sgp, (const float4*)sup, T*SHF/4);
    gemm_tc<<<dim3(H/64, T/64, 1), 128, 0, s2>>>(sgp, SHF, 0, shdr, nullptr, nullptr, H, 0, 0,
                                                 sharedp, nullptr, nullptr, H, 0, nullptr, 0,
                                                 SHF, 1.f, 0, 0);
    cudaEventRecord(evShared, s2);

    // main: router + MoE (bf16 LDSM, 128x128 tiles)
    zero_cnt_kernel<<<1, 64>>>();
    router_kernel<<<T, 64>>>(gate_w);
    prefix_kernel<<<1, 32>>>();
    scatter_kernel<<<(NPAIR + 255)/256, 256>>>();
    cudaStreamWaitEvent(0, evSide, 0);
    gemm_bf16_dual<<<dim3(EI/128, T/128, NEXP), 512>>>(
        h2bp, H, gpeBp, upeBp, (long)H*EI, EI, actBp, EI, H);
    gemm_bf16_one<<<dim3(H/128, T/128, NEXP), 256>>>(
        actBp, EI, dpeBp, (long)EI*H, H, pairoutp, H, EI);

    // join shared FFN, then combine
    cudaStreamWaitEvent(0, evShared, 0);
    combine_kernel<<<T, 256>>>(out);
}

// round 15
// speedup vs baseline: 1.8137x; 1.0273x over previous
#include <cuda_runtime.h>
#include <cuda_bf16.h>
#include <math.h>

#define T 1024
#define H 1280
#define NH 10
#define HD 128
#define EI 896
#define NEXP 64
#define TOPK 6
#define SHF 1792
#define NPAIR (T*TOPK)

// ---------------- device scratch ----------------
static __device__ float g_h1[T*H];
static __device__ float g_q[T*H];
static __device__ float g_k[T*H];
static __device__ float g_v[T*H];
static __device__ float g_scores[NH*T*T];
static __device__ float g_attnout[T*H];
static __device__ float g_hres[T*H];
static __device__ float g_h2[T*H];
static __device__ float g_h2u[T*H];
static __device__ __nv_bfloat16 g_h2b[T*H];
static __device__ float g_sg[T*SHF];
static __device__ float g_su[T*SHF];
static __device__ float g_shared[T*H];
static __device__ __nv_bfloat16 g_gpeB[(size_t)NEXP*H*EI];
static __device__ __nv_bfloat16 g_upeB[(size_t)NEXP*H*EI];
static __device__ __nv_bfloat16 g_dpeB[(size_t)NEXP*EI*H];
static __device__ __nv_bfloat16 g_actB[(size_t)(NPAIR+128)*EI];
static __device__ float g_pairout[(size_t)NPAIR*H];
static __device__ float g_WqR[H*NH*HD];
static __device__ float g_WkR[H*NH*HD];
static __device__ float g_WvR[H*NH*HD];
static __device__ float g_WoR[NH*HD*H];
static __device__ float g_shgR[H*SHF];
static __device__ float g_shuR[H*SHF];
static __device__ float g_shdR[SHF*H];
static __device__ int   g_cnt[NEXP];
static __device__ int   g_off[NEXP];
static __device__ int   g_cur[NEXP];
static __device__ int   g_tokE[NPAIR];
static __device__ float g_tokW[NPAIR];
static __device__ int   g_pairTok[NPAIR];
static __device__ float g_pairW[NPAIR];
static __device__ int   g_pairPos[NPAIR];

// ---------------- helpers ----------------
__device__ __forceinline__ void mma_tf32(float4& c, const unsigned a[4], const unsigned b[2]) {
    asm volatile("mma.sync.aligned.m16n8k8.row.col.f32.tf32.tf32.f32 "
        "{%0,%1,%2,%3}, {%4,%5,%6,%7}, {%8,%9}, {%0,%1,%2,%3};"
        : "+f"(c.x), "+f"(c.y), "+f"(c.z), "+f"(c.w)
        : "r"(a[0]), "r"(a[1]), "r"(a[2]), "r"(a[3]), "r"(b[0]), "r"(b[1]));
}
__device__ __forceinline__ void mma_bf16(float4& c, const unsigned a[4], const unsigned b[2]) {
    asm volatile("mma.sync.aligned.m16n8k16.row.col.f32.bf16.bf16.f32 "
        "{%0,%1,%2,%3}, {%4,%5,%6,%7}, {%8,%9}, {%0,%1,%2,%3};"
        : "+f"(c.x), "+f"(c.y), "+f"(c.z), "+f"(c.w)
        : "r"(a[0]), "r"(a[1]), "r"(a[2]), "r"(a[3]), "r"(b[0]), "r"(b[1]));
}
__device__ __forceinline__ float rtf(float f) {
    unsigned r; asm("cvt.rna.tf32.f32 %0, %1;" : "=r"(r) : "f"(f));
    return __uint_as_float(r);
}
__device__ __forceinline__ void cp16(const void* smem, const void* gmem) {
    unsigned sa = (unsigned)__cvta_generic_to_shared(smem);
    asm volatile("cp.async.cg.shared.global [%0], [%1], 16;" :: "r"(sa), "l"(gmem));
}
__device__ __forceinline__ void ldsm4(unsigned& r0, unsigned& r1, unsigned& r2, unsigned& r3,
                                      unsigned addr) {
    asm volatile("ldmatrix.sync.aligned.m8n8.x4.shared.b16 {%0,%1,%2,%3}, [%4];"
        : "=r"(r0), "=r"(r1), "=r"(r2), "=r"(r3) : "r"(addr));
}
__device__ __forceinline__ void ldsm4t(unsigned& r0, unsigned& r1, unsigned& r2, unsigned& r3,
                                       unsigned addr) {
    asm volatile("ldmatrix.sync.aligned.m8n8.x4.trans.shared.b16 {%0,%1,%2,%3}, [%4];"
        : "=r"(r0), "=r"(r1), "=r"(r2), "=r"(r3) : "r"(addr));
}
#define CP_COMMIT asm volatile("cp.async.commit_group;")
#define CP_WAIT1  asm volatile("cp.async.wait_group 1;")

#define AST 36
#define BST 72

// ---------------- weight rounding: 2 attention mats (z 0..1) ----------------
__global__ void round_pair(const float4* w0, float4* o0, const float4* w1, float4* o1) {
    int z = blockIdx.y;
    const float4* in = z ? w1 : w0;
    float4* out = z ? o1 : o0;
    int i = blockIdx.x*256 + threadIdx.x;
    if (i < H*NH*HD/4) {
        float4 v = in[i];
        v.x = rtf(v.x); v.y = rtf(v.y); v.z = rtf(v.z); v.w = rtf(v.w);
        out[i] = v;
    }
}

// ---------------- weight rounding: shared-FFN mats (z 0..2) ----------------
__global__ void round_shared(const float4* w4, float4* o4, const float4* w5, float4* o5,
                             const float4* w6, float4* o6) {
    int z = blockIdx.y;
    const float4* in; float4* out; int n4;
    switch (z) { case 0: in=w4; out=o4; n4=H*SHF/4; break;
                 case 1: in=w5; out=o5; n4=H*SHF/4; break;
                 default: in=w6; out=o6; n4=SHF*H/4; }
    int i = blockIdx.x*256 + threadIdx.x;
    if (i < n4) {
        float4 v = in[i];
        v.x = rtf(v.x); v.y = rtf(v.y); v.z = rtf(v.z); v.w = rtf(v.w);
        out[i] = v;
    }
}

// ---------------- RMSNorm ----------------
__global__ void rms_kernel(const float* __restrict__ x, const float* __restrict__ w,
                           float* __restrict__ out, float* __restrict__ outu,
                           __nv_bfloat16* __restrict__ outb) {
    int t = blockIdx.x;
    const float* xr = x + (long)t*H;
    __shared__ float red[256];
    float s = 0.f;
    for (int i = threadIdx.x; i < H; i += 256) { float v = xr[i]; s += v*v; }
    red[threadIdx.x] = s; __syncthreads();
    for (int k = 128; k > 0; k >>= 1) {
        if (threadIdx.x < k) red[threadIdx.x] += red[threadIdx.x + k];
        __syncthreads();
    }
    float r = rsqrtf(red[0]/(float)H + 1e-6f);
    for (int i = threadIdx.x; i < H; i += 256) {
        float v = w[i]*xr[i]*r;
        if (out)  out[(long)t*H + i] = rtf(v);
        if (outu) outu[(long)t*H + i] = v;
        if (outb) outb[(long)t*H + i] = __float2bfloat16(v);
    }
}

// ---------------- tf32 GEMM (proven core): 64x64, BK32, 2-stage, 128 thr ----------
__global__ void __launch_bounds__(128)
gemm_tc(const float* __restrict__ A, int lda, long sA,
        const float* __restrict__ B, const float* __restrict__ Bb, const float* __restrict__ Bc,
        int ldb, long sB, int transB,
        float* __restrict__ C, float* __restrict__ Cb, float* __restrict__ Cc,
        int ldc, long sC,
        const float* __restrict__ res, long sR,
        int K, float alpha, int mode, int roundC) {
    int m0 = blockIdx.y*64, n0 = blockIdx.x*64;
    if (mode == 1 && n0 >= m0 + 64) return;
    int bz = blockIdx.z;
    A += (long)bz*sA;
    if (Bb) {
        if (bz == 1) { B = Bb; C = Cb; }
        else if (bz == 2) { B = Bc; C = Cc; }
    } else {
        B += (long)bz*sB; C += (long)bz*sC; if (res) res += (long)bz*sR;
    }
    int Klim = (mode == 2) ? (m0 + 64 < K ? m0 + 64 : K) : K;

    __shared__ float As[2][64*AST];
    __shared__ float Bs[2][2304];
    int tid = threadIdx.x;
    int lane = tid & 31, warpId = tid >> 5;
    int g = lane >> 2, tig = lane & 3;
    int warp_m = (warpId & 1) * 32, warp_n = (warpId >> 1) * 32;
    float4 acc[2][4];
    #pragma unroll
    for (int i = 0; i < 2; i++)
        #pragma unroll
        for (int j = 0; j < 4; j++) acc[i][j] = make_float4(0.f,0.f,0.f,0.f);

#define G_LOAD(sidx, k0v) do { int _k0 = (k0v); if (_k0 < Klim) { \
    _Pragma("unroll") for (int i = 0; i < 4; i++) { int idx = tid + i*128; int r = idx >> 3, c4 = (idx & 7) << 2; \
        cp16(&As[sidx][r*AST + c4], &A[(long)(m0+r)*lda + _k0 + c4]); } \
    if (!transB) { \
        _Pragma("unroll") for (int i = 0; i < 4; i++) { int idx = tid + i*128; int r = idx >> 4, c4 = (idx & 15) << 2; \
            cp16(&Bs[sidx][r*BST + c4], &B[(long)(_k0+r)*ldb + n0 + c4]); } \
    } else { \
        _Pragma("unroll") for (int i = 0; i < 4; i++) { int idx = tid + i*128; int r = idx >> 3, c4 = (idx & 7) << 2; \
            cp16(&Bs[sidx][r*AST + c4], &B[(long)(n0+r)*ldb + _k0 + c4]); } \
    } } CP_COMMIT; } while(0)

    int nIter = Klim >> 5;
    G_LOAD(0, 0);
    for (int it = 0; it < nIter; it++) {
        int s = it & 1;
        G_LOAD(s ^ 1, (it + 1) << 5);
        CP_WAIT1;
        __syncthreads();
        #pragma unroll
        for (int kk = 0; kk < 32; kk += 8) {
            unsigned a[2][4], b[4][2];
            #pragma unroll
            for (int mi = 0; mi < 2; mi++) {
                const float* ap = &As[s][(warp_m + mi*16 + g)*AST + kk + tig];
                a[mi][0] = __float_as_uint(ap[0]);
                a[mi][1] = __float_as_uint(ap[8*AST]);
                a[mi][2] = __float_as_uint(ap[4]);
                a[mi][3] = __float_as_uint(ap[8*AST + 4]);
            }
            if (!transB) {
                #pragma unroll
                for (int ni = 0; ni < 4; ni++) {
                    int col = warp_n + ni*8 + g;
                    b[ni][0] = __float_as_uint(Bs[s][(kk+tig)*BST + col]);
                    b[ni][1] = __float_as_uint(Bs[s][(kk+tig+4)*BST + col]);
                }
            } else {
                #pragma unroll
                for (int ni = 0; ni < 4; ni++) {
                    const float* bp = &Bs[s][(warp_n + ni*8 + g)*AST + kk + tig];
                    b[ni][0] = __float_as_uint(bp[0]);
                    b[ni][1] = __float_as_uint(bp[4]);
                }
            }
            #pragma unroll
            for (int mi = 0; mi < 2; mi++)
                #pragma unroll
                for (int ni = 0; ni < 4; ni++) mma_tf32(acc[mi][ni], a[mi], b[ni]);
        }
        __syncthreads();
    }
#undef G_LOAD
    #pragma unroll
    for (int mi = 0; mi < 2; mi++) {
        #pragma unroll
        for (int ni = 0; ni < 4; ni++) {
            int row = m0 + warp_m + mi*16 + g;
            int col = n0 + warp_n + ni*8 + 2*tig;
            float4 c = acc[mi][ni];
            float2 v0 = { alpha*c.x, alpha*c.y };
            float2 v1 = { alpha*c.z, alpha*c.w };
            if (res) {
                float2 r0 = *(const float2*)&res[(long)row*ldc + col];
                float2 r1 = *(const float2*)&res[(long)(row+8)*ldc + col];
                v0.x += r0.x; v0.y += r0.y; v1.x += r1.x; v1.y += r1.y;
            }
            if (roundC) {
                v0.x = rtf(v0.x); v0.y = rtf(v0.y);
                v1.x = rtf(v1.x); v1.y = rtf(v1.y);
            }
            *(float2*)&C[(long)row*ldc + col] = v0;
            *(float2*)&C[(long)(row+8)*ldc + col] = v1;
        }
    }
}

// ---------------- RoPE (rounds q,k only) ----------------
__global__ void rope_kernel() {
    int t = blockIdx.x, tid = threadIdx.x;
    __shared__ float cs[64], sn[64];
    if (tid < 64) {
        float inv = powf(10000.0f, -(float)tid / 64.0f);
        float fr = (float)t * inv;
        cs[tid] = cosf(fr); sn[tid] = sinf(fr);
    }
    __syncthreads();
    for (int idx = tid; idx < NH*64; idx += 256) {
        int hh = idx >> 6, j = idx & 63;
        long b = (long)t*H + hh*HD;
        float c = cs[j], s = sn[j];
        float q1 = g_q[b+j], q2 = g_q[b+j+64];
        g_q[b+j]    = rtf(q1*c - q2*s);
        g_q[b+j+64] = rtf(q2*c + q1*s);
        float k1 = g_k[b+j], k2 = g_k[b+j+64];
        g_k[b+j]    = rtf(k1*c - k2*s);
        g_k[b+j+64] = rtf(k2*c + k1*s);
    }
}

// ---------------- causal softmax: single vectorized read, in-register ----------------
__global__ void attn_softmax() {
    int t = blockIdx.x, hh = blockIdx.y, tid = threadIdx.x;
    float* row = g_scores + ((long)hh*T + t)*(long)T;
    int len = t + 1;
    int zend = ((t >> 6) + 1) << 6;
    int base = tid * 4;
    float4 v = make_float4(0.f, 0.f, 0.f, 0.f);
    bool act = base < zend;
    if (act) v = *(const float4*)&row[base];

    float mx = -3.0e38f;
    if (base + 0 < len) mx = fmaxf(mx, v.x);
    if (base + 1 < len) mx = fmaxf(mx, v.y);
    if (base + 2 < len) mx = fmaxf(mx, v.z);
    if (base + 3 < len) mx = fmaxf(mx, v.w);
    #pragma unroll
    for (int o = 16; o > 0; o >>= 1) mx = fmaxf(mx, __shfl_xor_sync(~0u, mx, o));
    __shared__ float smx[8], ssm[8];
    int w = tid >> 5, l = tid & 31;
    if (l == 0) smx[w] = mx;
    __syncthreads();
    if (w == 0) {
        float m = (l < 8) ? smx[l] : -3.0e38f;
        #pragma unroll
        for (int o = 4; o > 0; o >>= 1) m = fmaxf(m, __shfl_xor_sync(~0u, m, o));
        if (l == 0) smx[0] = m;
    }
    __syncthreads();
    mx = smx[0];

    float e0 = (base + 0 < len) ? __expf(v.x - mx) : 0.f;
    float e1 = (base + 1 < len) ? __expf(v.y - mx) : 0.f;
    float e2 = (base + 2 < len) ? __expf(v.z - mx) : 0.f;
    float e3 = (base + 3 < len) ? __expf(v.w - mx) : 0.f;
    float s = (e0 + e1) + (e2 + e3);
    #pragma unroll
    for (int o = 16; o > 0; o >>= 1) s += __shfl_xor_sync(~0u, s, o);
    if (l == 0) ssm[w] = s;
    __syncthreads();
    if (w == 0) {
        float m = (l < 8) ? ssm[l] : 0.f;
        #pragma unroll
        for (int o = 4; o > 0; o >>= 1) m += __shfl_xor_sync(~0u, m, o);
        if (l == 0) ssm[0] = m;
    }
    __syncthreads();
    float inv = 1.0f / ssm[0];
    if (act) {
        float4 ov;
        ov.x = rtf(e0 * inv);
        ov.y = rtf(e1 * inv);
        ov.z = rtf(e2 * inv);
        ov.w = rtf(e3 * inv);
        *(float4*)&row[base] = ov;
    }
}

// ------- expert transpose -> bf16 [e][k][n], vectorized ------------------------------
__global__ void __launch_bounds__(256) transpose_eb(const float* __restrict__ in,
                                                    unsigned* __restrict__ out,
                                                    int R, int C) {
    int r = blockIdx.y;
    int c0 = blockIdx.x * 32;
    __shared__ unsigned sm[16][68];
    int tid = threadIdx.x;
    {
        int cpair = tid >> 4;
        int e4 = (tid & 15) << 2;
        const float* basep = in + ((long)r*C + c0 + 2*cpair) * 64 + e4;
        float4 a = *(const float4*)basep;
        float4 b = *(const float4*)(basep + 64);
        __nv_bfloat162 t0 = __floats2bfloat162_rn(a.x, b.x);
        __nv_bfloat162 t1 = __floats2bfloat162_rn(a.y, b.y);
        __nv_bfloat162 t2 = __floats2bfloat162_rn(a.z, b.z);
        __nv_bfloat162 t3 = __floats2bfloat162_rn(a.w, b.w);
        uint4 u = { *(unsigned*)&t0, *(unsigned*)&t1, *(unsigned*)&t2, *(unsigned*)&t3 };
        *(uint4*)&sm[cpair][e4] = u;
    }
    __syncthreads();
    {
        int e = tid >> 2;
        int grp = (tid & 3) << 2;
        uint4 v;
        v.x = sm[grp+0][e];
        v.y = sm[grp+1][e];
        v.z = sm[grp+2][e];
        v.w = sm[grp+3][e];
        long C2 = C >> 1;
        *(uint4*)&out[(long)e*R*C2 + (long)r*C2 + (c0 >> 1) + grp] = v;
    }
}

// ---------------- router ----------------
__global__ void zero_cnt_kernel() { if (threadIdx.x < NEXP) g_cnt[threadIdx.x] = 0; }

__global__ void router_kernel(const float* __restrict__ gw) {
    int t = blockIdx.x, e = threadIdx.x;
    const float* hr = g_h2u + (long)t*H;
    float s = 0.f;
    for (int h = 0; h < H; h++) s += hr[h] * gw[h*NEXP + e];
    __shared__ float probs[NEXP];
    probs[e] = s;
    __syncthreads();
    if (e == 0) {
        float mx = -3e38f;
        for (int i = 0; i < NEXP; i++) mx = fmaxf(mx, probs[i]);
        float sum = 0.f;
        for (int i = 0; i < NEXP; i++) { probs[i] = __expf(probs[i]-mx); sum += probs[i]; }
        float inv = 1.f/sum;
        for (int i = 0; i < NEXP; i++) probs[i] *= inv;
        int ti[TOPK]; float tw[TOPK]; float ws = 0.f;
        for (int j = 0; j < TOPK; j++) {
            int bi = 0; float bv = -1.f;
            for (int i = 0; i < NEXP; i++) if (probs[i] > bv) { bv = probs[i]; bi = i; }
            ti[j] = bi; tw[j] = bv; ws += bv; probs[bi] = -2.f;
        }
        float wi = 1.f/ws;
        for (int j = 0; j < TOPK; j++) {
            g_tokE[t*TOPK+j] = ti[j];
            g_tokW[t*TOPK+j] = tw[j]*wi;
            atomicAdd(&g_cnt[ti[j]], 1);
        }
    }
}

__global__ void prefix_kernel() {
    if (threadIdx.x == 0) {
        int s = 0;
        for (int e = 0; e < NEXP; e++) { g_off[e] = s; g_cur[e] = s; s += g_cnt[e]; }
    }
}

__global__ void scatter_kernel() {
    int i = blockIdx.x*256 + threadIdx.x;
    if (i < NPAIR) {
        int e = g_tokE[i];
        int pos = atomicAdd(&g_cur[e], 1);
        g_pairTok[pos] = i / TOPK;
        g_pairW[pos]   = g_tokW[i];
        g_pairPos[i]   = pos;
    }
}

// -------- bf16 dual GEMM + SiLU (MoE pass1): CTA 128x128, 512 thr, warp 32x32, LDSM --
__global__ void __launch_bounds__(512)
gemm_bf16_dual(const __nv_bfloat16* __restrict__ A, int lda,
               const __nv_bfloat16* __restrict__ B1g, const __nv_bfloat16* __restrict__ B2g,
               long sB, int ldb,
               __nv_bfloat16* __restrict__ Cout, int ldc,
               int K) {
    int e = blockIdx.z;
    int m0 = blockIdx.y * 128;
    int cnt = g_cnt[e], base = g_off[e];
    if (m0 >= cnt) return;
    const __nv_bfloat16* B1 = B1g + (long)e*sB;
    const __nv_bfloat16* B2 = B2g + (long)e*sB;
    int n0 = blockIdx.x * 128;

    __shared__ int stok[128];
    __shared__ unsigned As[3][128][12];
    __shared__ unsigned Bs1[3][16][68];
    __shared__ unsigned Bs2[3][16][68];
    int tid = threadIdx.x;
    int lane = tid & 31, warpId = tid >> 5;
    int g = lane >> 2, tig = lane & 3;
    int warp_m = (warpId & 3) * 32, warp_n = (warpId >> 2) * 32;
    if (tid < 128) stok[tid] = (m0 + tid < cnt) ? g_pairTok[base + m0 + tid] : 0;
    __syncthreads();
    float4 accG[2][4], accU[2][4];
    #pragma unroll
    for (int i = 0; i < 2; i++)
        #pragma unroll
        for (int j = 0; j < 4; j++) { accG[i][j] = make_float4(0,0,0,0); accU[i][j] = make_float4(0,0,0,0); }

#define D_LOAD(sidx, k0v) do { int _k0 = (k0v); if (_k0 < K) { \
    if (tid < 256) { int r = tid >> 1, ch = tid & 1; \
      cp16(&As[sidx][r][ch*4], &A[(long)stok[r]*lda + _k0 + ch*8]); } \
    else { int t2 = tid - 256; int r = t2 >> 4, ch = t2 & 15; \
      cp16(&Bs1[sidx][r][ch*4], &B1[(long)(_k0+r)*ldb + n0 + ch*8]); \
      cp16(&Bs2[sidx][r][ch*4], &B2[(long)(_k0+r)*ldb + n0 + ch*8]); } \
    } CP_COMMIT; } while(0)

    const int nIter = K >> 4;
    D_LOAD(0, 0);
    D_LOAD(1, 16);
    int st = 0;
    int half16 = (lane >> 4) * 16;
    for (int it = 0; it < nIter; it++) {
        CP_WAIT1;
        __syncthreads();
        unsigned aBase = (unsigned)__cvta_generic_to_shared(&As[st][0][0]);
        unsigned b1Base = (unsigned)__cvta_generic_to_shared(&Bs1[st][0][0]);
        unsigned b2Base = (unsigned)__cvta_generic_to_shared(&Bs2[st][0][0]);
        unsigned a[2][4], b1[4][2], b2[4][2];
        #pragma unroll
        for (int mi = 0; mi < 2; mi++) {
            int row = warp_m + mi*16 + (lane & 15);
            ldsm4(a[mi][0], a[mi][1], a[mi][2], a[mi][3], aBase + row*48 + half16);
        }
        #pragma unroll
        for (int nh = 0; nh < 2; nh++) {
            int krow = lane & 15;
            int col = warp_n + nh*16 + (lane >> 4) * 8;
            ldsm4t(b1[nh*2][0], b1[nh*2][1], b1[nh*2+1][0], b1[nh*2+1][1],
                   b1Base + krow*272 + col*2);
            ldsm4t(b2[nh*2][0], b2[nh*2][1], b2[nh*2+1][0], b2[nh*2+1][1],
                   b2Base + krow*272 + col*2);
        }
        #pragma unroll
        for (int mi = 0; mi < 2; mi++)
            #pragma unroll
            for (int ni = 0; ni < 4; ni++) {
                mma_bf16(accG[mi][ni], a[mi], b1[ni]);
                mma_bf16(accU[mi][ni], a[mi], b2[ni]);
            }
        int wst = st + 2; if (wst >= 3) wst -= 3;
        D_LOAD(wst, (it + 2) << 4);
        if (++st == 3) st = 0;
    }
#undef D_LOAD
    #pragma unroll
    for (int mi = 0; mi < 2; mi++) {
        #pragma unroll
        for (int ni = 0; ni < 4; ni++) {
            int mrow = warp_m + mi*16 + g;
            int col = n0 + warp_n + ni*8 + 2*tig;
            float4 cg = accG[mi][ni], cu = accU[mi][ni];
            if (m0 + mrow < cnt) {
                float g0 = cg.x, g1 = cg.y;
                __nv_bfloat162 v = __floats2bfloat162_rn((g0/(1.f+__expf(-g0)))*cu.x,
                                                         (g1/(1.f+__expf(-g1)))*cu.y);
                *(__nv_bfloat162*)&Cout[(long)(base+m0+mrow)*ldc + col] = v;
            }
            if (m0 + mrow + 8 < cnt) {
                float g0 = cg.z, g1 = cg.w;
                __nv_bfloat162 v = __floats2bfloat162_rn((g0/(1.f+__expf(-g0)))*cu.z,
                                                         (g1/(1.f+__expf(-g1)))*cu.w);
                *(__nv_bfloat162*)&Cout[(long)(base+m0+mrow+8)*ldc + col] = v;
            }
        }
    }
}

// -------- bf16 single GEMM (MoE pass2): CTA 128x128, 256 thr, warp 64x32, LDSM -------
__global__ void __launch_bounds__(256)
gemm_bf16_one(const __nv_bfloat16* __restrict__ A, int lda,
              const __nv_bfloat16* __restrict__ Bg, long sB, int ldb,
              float* __restrict__ Cout, int ldc,
              int K) {
    int e = blockIdx.z;
    int m0 = blockIdx.y * 128;
    int cnt = g_cnt[e], base = g_off[e];
    if (m0 >= cnt) return;
    const __nv_bfloat16* B = Bg + (long)e*sB;
    int n0 = blockIdx.x * 128;

    __shared__ unsigned As[3][128][12];
    __shared__ unsigned Bs[3][16][68];
    int tid = threadIdx.x;
    int lane = tid & 31, warpId = tid >> 5;
    int g = lane >> 2, tig = lane & 3;
    int warp_m = (warpId & 1) * 64, warp_n = (warpId >> 1) * 32;
    float4 acc[4][4];
    #pragma unroll
    for (int i = 0; i < 4; i++)
        #pragma unroll
        for (int j = 0; j < 4; j++) acc[i][j] = make_float4(0,0,0,0);

#define S_LOAD(sidx, k0v) do { int _k0 = (k0v); if (_k0 < K) { \
    { int r = tid >> 1, ch = tid & 1; \
      int rr = m0 + r; if (rr >= cnt) rr = cnt - 1; \
      cp16(&As[sidx][r][ch*4], &A[(long)(base + rr)*lda + _k0 + ch*8]); } \
    { int r = tid >> 4, ch = tid & 15; \
      cp16(&Bs[sidx][r][ch*4], &B[(long)(_k0+r)*ldb + n0 + ch*8]); } \
    } CP_COMMIT; } while(0)

    const int nIter = K >> 4;
    S_LOAD(0, 0);
    S_LOAD(1, 16);
    int st = 0;
    int half16 = (lane >> 4) * 16;
    for (int it = 0; it < nIter; it++) {
        CP_WAIT1;
        __syncthreads();
        unsigned aBase = (unsigned)__cvta_generic_to_shared(&As[st][0][0]);
        unsigned bBase = (unsigned)__cvta_generic_to_shared(&Bs[st][0][0]);
        unsigned a[4][4], b[4][2];
        #pragma unroll
        for (int mi = 0; mi < 4; mi++) {
            int row = warp_m + mi*16 + (lane & 15);
            ldsm4(a[mi][0], a[mi][1], a[mi][2], a[mi][3], aBase + row*48 + half16);
        }
        #pragma unroll
        for (int nh = 0; nh < 2; nh++) {
            int krow = lane & 15;
            int col = warp_n + nh*16 + (lane >> 4) * 8;
            ldsm4t(b[nh*2][0], b[nh*2][1], b[nh*2+1][0], b[nh*2+1][1],
                   bBase + krow*272 + col*2);
        }
        #pragma unroll
        for (int mi = 0; mi < 4; mi++)
            #pragma unroll
            for (int ni = 0; ni < 4; ni++) mma_bf16(acc[mi][ni], a[mi], b[ni]);
        int wst = st + 2; if (wst >= 3) wst -= 3;
        S_LOAD(wst, (it + 2) << 4);
        if (++st == 3) st = 0;
    }
#undef S_LOAD
    #pragma unroll
    for (int mi = 0; mi < 4; mi++) {
        #pragma unroll
        for (int ni = 0; ni < 4; ni++) {
            int mrow = warp_m + mi*16 + g;
            int col = n0 + warp_n + ni*8 + 2*tig;
            float4 c = acc[mi][ni];
            if (m0 + mrow < cnt)
                *(float2*)&Cout[(long)(base+m0+mrow)*ldc + col] = make_float2(c.x, c.y);
            if (m0 + mrow + 8 < cnt)
                *(float2*)&Cout[(long)(base+m0+mrow+8)*ldc + col] = make_float2(c.z, c.w);
        }
    }
}

// ---------------- shared-FFN activation (vectorized, rounds output) ----------------
__global__ void silumul_kernel(float4* __restrict__ g, const float4* __restrict__ u, int n4) {
    int i = blockIdx.x*256 + threadIdx.x;
    if (i < n4) {
        float4 x = g[i];
        float4 y = u[i];
        x.x = rtf((x.x / (1.f + __expf(-x.x))) * y.x);
        x.y = rtf((x.y / (1.f + __expf(-x.y))) * y.y);
        x.z = rtf((x.z / (1.f + __expf(-x.z))) * y.z);
        x.w = rtf((x.w / (1.f + __expf(-x.w))) * y.w);
        g[i] = x;
    }
}

// ---------------- final combine ----------------
__global__ void combine_kernel(float* __restrict__ out) {
    int t = blockIdx.x;
    int pos[TOPK]; float w[TOPK];
    #pragma unroll
    for (int j = 0; j < TOPK; j++) {
        pos[j] = g_pairPos[t*TOPK + j];
        w[j]   = g_pairW[pos[j]];
    }
    for (int h = threadIdx.x; h < H; h += 256) {
        float s = g_hres[(long)t*H + h] + g_shared[(long)t*H + h];
        #pragma unroll
        for (int j = 0; j < TOPK; j++)
            s += w[j] * g_pairout[(long)pos[j]*H + h];
        out[(long)t*H + h] = s;
    }
}

// ---------------- launch ----------------
extern "C" void kernel_launch(void* const* d_in, const int* in_sizes, int n_in,
                              void* d_out, int out_size) {
    (void)in_sizes; (void)n_in; (void)out_size;
    const float* x       = (const float*)d_in[0];
    const float* ln1     = (const float*)d_in[1];
    const float* ln2     = (const float*)d_in[2];
    const float* Wq      = (const float*)d_in[3];
    const float* Wk      = (const float*)d_in[4];
    const float* Wv      = (const float*)d_in[5];
    const float* Wo      = (const float*)d_in[6];
    const float* gate_w  = (const float*)d_in[7];
    const float* gpe     = (const float*)d_in[8];
    const float* upe     = (const float*)d_in[9];
    const float* dpe     = (const float*)d_in[10];
    const float* sh_gate = (const float*)d_in[11];
    const float* sh_up   = (const float*)d_in[12];
    const float* sh_down = (const float*)d_in[13];
    float* out = (float*)d_out;

    float *h1p,*qp,*kp,*vp,*scoresp,*attnp,*hresp,*h2p,*h2up,*sgp,*sup,*sharedp,*pairoutp;
    __nv_bfloat16 *h2bp,*actBp,*gpeBp,*upeBp,*dpeBp;
    float *wqr,*wkr,*wvr,*wor,*shgr,*shur,*shdr;
    cudaGetSymbolAddress((void**)&h1p,     g_h1);
    cudaGetSymbolAddress((void**)&qp,      g_q);
    cudaGetSymbolAddress((void**)&kp,      g_k);
    cudaGetSymbolAddress((void**)&vp,      g_v);
    cudaGetSymbolAddress((void**)&scoresp, g_scores);
    cudaGetSymbolAddress((void**)&attnp,   g_attnout);
    cudaGetSymbolAddress((void**)&hresp,   g_hres);
    cudaGetSymbolAddress((void**)&h2p,     g_h2);
    cudaGetSymbolAddress((void**)&h2up,    g_h2u);
    cudaGetSymbolAddress((void**)&h2bp,    g_h2b);
    cudaGetSymbolAddress((void**)&sgp,     g_sg);
    cudaGetSymbolAddress((void**)&sup,     g_su);
    cudaGetSymbolAddress((void**)&sharedp, g_shared);
    cudaGetSymbolAddress((void**)&actBp,   g_actB);
    cudaGetSymbolAddress((void**)&pairoutp,g_pairout);
    cudaGetSymbolAddress((void**)&gpeBp,   g_gpeB);
    cudaGetSymbolAddress((void**)&upeBp,   g_upeB);
    cudaGetSymbolAddress((void**)&dpeBp,   g_dpeB);
    cudaGetSymbolAddress((void**)&wqr,     g_WqR);
    cudaGetSymbolAddress((void**)&wkr,     g_WkR);
    cudaGetSymbolAddress((void**)&wvr,     g_WvR);
    cudaGetSymbolAddress((void**)&wor,     g_WoR);
    cudaGetSymbolAddress((void**)&shgr,    g_shgR);
    cudaGetSymbolAddress((void**)&shur,    g_shuR);
    cudaGetSymbolAddress((void**)&shdr,    g_shdR);

    const float inv_sqrt_hd = 0.08838834764831845f;

    // Exactly one side stream + six events (R9-R12 proven resource footprint).
    cudaStream_t s2;
    cudaStreamCreateWithFlags(&s2, cudaStreamNonBlocking);
    cudaEvent_t evFork, evH1, evV, evSide, evH2, evShared;
    cudaEventCreateWithFlags(&evFork,   cudaEventDisableTiming);
    cudaEventCreateWithFlags(&evH1,     cudaEventDisableTiming);
    cudaEventCreateWithFlags(&evV,      cudaEventDisableTiming);
    cudaEventCreateWithFlags(&evSide,   cudaEventDisableTiming);
    cudaEventCreateWithFlags(&evH2,     cudaEventDisableTiming);
    cudaEventCreateWithFlags(&evShared, cudaEventDisableTiming);

    cudaEventRecord(evFork, 0);
    cudaStreamWaitEvent(s2, evFork, 0);

    // s2: Wv/Wo rounding first (so the Wv GEMM can start right after rms1)
    round_pair<<<dim3((H*NH*HD/4 + 255)/256, 2), 256, 0, s2>>>(
        (const float4*)Wv, (float4*)wvr, (const float4*)Wo, (float4*)wor);

    // main: Wq/Wk rounding + rms1
    round_pair<<<dim3((H*NH*HD/4 + 255)/256, 2), 256>>>(
        (const float4*)Wq, (float4*)wqr, (const float4*)Wk, (float4*)wkr);
    rms_kernel<<<T, 256>>>(x, ln1, h1p, nullptr, nullptr);
    cudaEventRecord(evH1, 0);

    // s2: Wv projection (rounded output), then transposes + shared-weight rounding
    cudaStreamWaitEvent(s2, evH1, 0);
    gemm_tc<<<dim3(H/64, T/64, 1), 128, 0, s2>>>(h1p, H, 0, wvr, nullptr, nullptr, H, 0, 0,
                                                 vp, nullptr, nullptr, H, 0, nullptr, 0,
                                                 H, 1.f, 0, 1);
    cudaEventRecord(evV, s2);   // also implies wor ready (s2 in-order)
    transpose_eb<<<dim3(EI/32, H), 256, 0, s2>>>(gpe, (unsigned*)gpeBp, H, EI);
    transpose_eb<<<dim3(EI/32, H), 256, 0, s2>>>(upe, (unsigned*)upeBp, H, EI);
    transpose_eb<<<dim3(H/32, EI), 256, 0, s2>>>(dpe, (unsigned*)dpeBp, EI, H);
    round_shared<<<dim3((H*SHF/4 + 255)/256, 3), 256, 0, s2>>>(
        (const float4*)sh_gate, (float4*)shgr, (const float4*)sh_up, (float4*)shur,
        (const float4*)sh_down, (float4*)shdr);
    cudaEventRecord(evSide, s2);

    // main: Q,K projections + attention chain (tf32)
    gemm_tc<<<dim3(H/64, T/64, 2), 128>>>(h1p, H, 0, wqr, wkr, nullptr, H, 0, 0,
                                          qp, kp, nullptr, H, 0, nullptr, 0,
                                          H, 1.f, 0, 0);
    rope_kernel<<<T, 256>>>();
    gemm_tc<<<dim3(T/64, T/64, NH), 128>>>(qp, H, HD, kp, nullptr, nullptr, H, HD, 1,
                                           scoresp, nullptr, nullptr, T, (long)T*T, nullptr, 0,
                                           HD, inv_sqrt_hd, 1, 0);
    attn_softmax<<<dim3(T, NH), 256>>>();
    cudaStreamWaitEvent(0, evV, 0);   // v + wor ready
    gemm_tc<<<dim3(HD/64, T/64, NH), 128>>>(scoresp, T, (long)T*T, vp, nullptr, nullptr, H, HD, 0,
                                            attnp, nullptr, nullptr, H, HD, nullptr, 0,
                                            T, 1.f, 2, 1);
    gemm_tc<<<dim3(H/64, T/64, 1), 128>>>(attnp, H, 0, wor, nullptr, nullptr, H, 0, 0,
                                          hresp, nullptr, nullptr, H, 0, x, 0,
                                          H, 1.f, 0, 0);

    // h2 (all three variants)
    rms_kernel<<<T, 256>>>(hresp, ln2, h2p, h2up, h2bp);
    cudaEventRecord(evH2, 0);

    // s2: shared FFN (tf32) overlaps router + MoE on main
    cudaStreamWaitEvent(s2, evH2, 0);
    gemm_tc<<<dim3(SHF/64, T/64, 2), 128, 0, s2>>>(h2p, H, 0, shgr, shur, nullptr, SHF, 0, 0,
                                                   sgp, sup, nullptr, SHF, 0, nullptr, 0,
                                                   H, 1.f, 0, 0);
    silumul_kernel<<<(T*SHF/4 + 255)/256, 256, 0, s2>>>((float4*)sgp, (const float4*)sup, T*SHF/4);
    gemm_tc<<<dim3(H/64, T/64, 1), 128, 0, s2>>>(sgp, SHF, 0, shdr, nullptr, nullptr, H, 0, 0,
                                                 sharedp, nullptr, nullptr, H, 0, nullptr, 0,
                                                 SHF, 1.f, 0, 0);
    cudaEventRecord(evShared, s2);

    // main: router + MoE (bf16 LDSM, 128x128 tiles)
    zero_cnt_kernel<<<1, 64>>>();
    router_kernel<<<T, 64>>>(gate_w);
    prefix_kernel<<<1, 32>>>();
    scatter_kernel<<<(NPAIR + 255)/256, 256>>>();
    cudaStreamWaitEvent(0, evSide, 0);
    gemm_bf16_dual<<<dim3(EI/128, T/128, NEXP), 512>>>(
        h2bp, H, gpeBp, upeBp, (long)H*EI, EI, actBp, EI, H);
    gemm_bf16_one<<<dim3(H/128, T/128, NEXP), 256>>>(
        actBp, EI, dpeBp, (long)EI*H, H, pairoutp, H, EI);

    // join shared FFN, then combine
    cudaStreamWaitEvent(0, evShared, 0);
    combine_kernel<<<T, 256>>>(out);
}

// round 16
// speedup vs baseline: 1.8422x; 1.0157x over previous
#include <cuda_runtime.h>
#include <cuda_bf16.h>
#include <math.h>

#define T 1024
#define H 1280
#define NH 10
#define HD 128
#define EI 896
#define NEXP 64
#define TOPK 6
#define SHF 1792
#define NPAIR (T*TOPK)

// ---------------- device scratch ----------------
static __device__ float g_h1[T*H];
static __device__ float g_q[T*H];
static __device__ float g_k[T*H];
static __device__ float g_v[T*H];
static __device__ float g_scores[NH*T*T];
static __device__ float g_attnout[T*H];
static __device__ float g_hres[T*H];
static __device__ float g_h2[T*H];
static __device__ float g_h2u[T*H];
static __device__ __nv_bfloat16 g_h2b[T*H];
static __device__ float g_sg[T*SHF];
static __device__ float g_su[T*SHF];
static __device__ float g_shared[T*H];
static __device__ __nv_bfloat16 g_gpeB[(size_t)NEXP*H*EI];
static __device__ __nv_bfloat16 g_upeB[(size_t)NEXP*H*EI];
static __device__ __nv_bfloat16 g_dpeB[(size_t)NEXP*EI*H];
static __device__ __nv_bfloat16 g_actB[(size_t)(NPAIR+128)*EI];
static __device__ float g_pairout[(size_t)NPAIR*H];
static __device__ float g_WqR[H*NH*HD];
static __device__ float g_WkR[H*NH*HD];
static __device__ float g_WvR[H*NH*HD];
static __device__ float g_WoR[NH*HD*H];
static __device__ float g_shgR[H*SHF];
static __device__ float g_shuR[H*SHF];
static __device__ float g_shdR[SHF*H];
static __device__ int   g_cnt[NEXP];
static __device__ int   g_off[NEXP];
static __device__ int   g_cur[NEXP];
static __device__ int   g_tokE[NPAIR];
static __device__ float g_tokW[NPAIR];
static __device__ int   g_pairTok[NPAIR];
static __device__ float g_pairW[NPAIR];
static __device__ int   g_pairPos[NPAIR];

// ---------------- helpers ----------------
__device__ __forceinline__ void mma_tf32(float4& c, const unsigned a[4], const unsigned b[2]) {
    asm volatile("mma.sync.aligned.m16n8k8.row.col.f32.tf32.tf32.f32 "
        "{%0,%1,%2,%3}, {%4,%5,%6,%7}, {%8,%9}, {%0,%1,%2,%3};"
        : "+f"(c.x), "+f"(c.y), "+f"(c.z), "+f"(c.w)
        : "r"(a[0]), "r"(a[1]), "r"(a[2]), "r"(a[3]), "r"(b[0]), "r"(b[1]));
}
__device__ __forceinline__ void mma_bf16(float4& c, const unsigned a[4], const unsigned b[2]) {
    asm volatile("mma.sync.aligned.m16n8k16.row.col.f32.bf16.bf16.f32 "
        "{%0,%1,%2,%3}, {%4,%5,%6,%7}, {%8,%9}, {%0,%1,%2,%3};"
        : "+f"(c.x), "+f"(c.y), "+f"(c.z), "+f"(c.w)
        : "r"(a[0]), "r"(a[1]), "r"(a[2]), "r"(a[3]), "r"(b[0]), "r"(b[1]));
}
__device__ __forceinline__ float rtf(float f) {
    unsigned r; asm("cvt.rna.tf32.f32 %0, %1;" : "=r"(r) : "f"(f));
    return __uint_as_float(r);
}
__device__ __forceinline__ void cp16(const void* smem, const void* gmem) {
    unsigned sa = (unsigned)__cvta_generic_to_shared(smem);
    asm volatile("cp.async.cg.shared.global [%0], [%1], 16;" :: "r"(sa), "l"(gmem));
}
__device__ __forceinline__ void ldsm4(unsigned& r0, unsigned& r1, unsigned& r2, unsigned& r3,
                                      unsigned addr) {
    asm volatile("ldmatrix.sync.aligned.m8n8.x4.shared.b16 {%0,%1,%2,%3}, [%4];"
        : "=r"(r0), "=r"(r1), "=r"(r2), "=r"(r3) : "r"(addr));
}
__device__ __forceinline__ void ldsm4t(unsigned& r0, unsigned& r1, unsigned& r2, unsigned& r3,
                                       unsigned addr) {
    asm volatile("ldmatrix.sync.aligned.m8n8.x4.trans.shared.b16 {%0,%1,%2,%3}, [%4];"
        : "=r"(r0), "=r"(r1), "=r"(r2), "=r"(r3) : "r"(addr));
}
#define CP_COMMIT asm volatile("cp.async.commit_group;")
#define CP_WAIT1  asm volatile("cp.async.wait_group 1;")

#define AST 36
#define BST 72

// ---------------- weight rounding: 2 attention mats (z 0..1) ----------------
__global__ void round_pair(const float4* w0, float4* o0, const float4* w1, float4* o1) {
    int z = blockIdx.y;
    const float4* in = z ? w1 : w0;
    float4* out = z ? o1 : o0;
    int i = blockIdx.x*256 + threadIdx.x;
    if (i < H*NH*HD/4) {
        float4 v = in[i];
        v.x = rtf(v.x); v.y = rtf(v.y); v.z = rtf(v.z); v.w = rtf(v.w);
        out[i] = v;
    }
}

// ---------------- weight rounding: shared-FFN mats (z 0..2) ----------------
__global__ void round_shared(const float4* w4, float4* o4, const float4* w5, float4* o5,
                             const float4* w6, float4* o6) {
    int z = blockIdx.y;
    const float4* in; float4* out; int n4;
    switch (z) { case 0: in=w4; out=o4; n4=H*SHF/4; break;
                 case 1: in=w5; out=o5; n4=H*SHF/4; break;
                 default: in=w6; out=o6; n4=SHF*H/4; }
    int i = blockIdx.x*256 + threadIdx.x;
    if (i < n4) {
        float4 v = in[i];
        v.x = rtf(v.x); v.y = rtf(v.y); v.z = rtf(v.z); v.w = rtf(v.w);
        out[i] = v;
    }
}

// ---------------- RMSNorm ----------------
__global__ void rms_kernel(const float* __restrict__ x, const float* __restrict__ w,
                           float* __restrict__ out, float* __restrict__ outu,
                           __nv_bfloat16* __restrict__ outb) {
    int t = blockIdx.x;
    const float* xr = x + (long)t*H;
    __shared__ float red[256];
    float s = 0.f;
    for (int i = threadIdx.x; i < H; i += 256) { float v = xr[i]; s += v*v; }
    red[threadIdx.x] = s; __syncthreads();
    for (int k = 128; k > 0; k >>= 1) {
        if (threadIdx.x < k) red[threadIdx.x] += red[threadIdx.x + k];
        __syncthreads();
    }
    float r = rsqrtf(red[0]/(float)H + 1e-6f);
    for (int i = threadIdx.x; i < H; i += 256) {
        float v = w[i]*xr[i]*r;
        if (out)  out[(long)t*H + i] = rtf(v);
        if (outu) outu[(long)t*H + i] = v;
        if (outb) outb[(long)t*H + i] = __float2bfloat16(v);
    }
}

// ---------------- tf32 GEMM (proven core): 64x64, BK32, 2-stage, 128 thr ----------
__global__ void __launch_bounds__(128)
gemm_tc(const float* __restrict__ A, int lda, long sA,
        const float* __restrict__ B, const float* __restrict__ Bb, const float* __restrict__ Bc,
        int ldb, long sB, int transB,
        float* __restrict__ C, float* __restrict__ Cb, float* __restrict__ Cc,
        int ldc, long sC,
        const float* __restrict__ res, long sR,
        int K, float alpha, int mode, int roundC) {
    int m0 = blockIdx.y*64, n0 = blockIdx.x*64;
    if (mode == 1 && n0 >= m0 + 64) return;
    int bz = blockIdx.z;
    A += (long)bz*sA;
    if (Bb) {
        if (bz == 1) { B = Bb; C = Cb; }
        else if (bz == 2) { B = Bc; C = Cc; }
    } else {
        B += (long)bz*sB; C += (long)bz*sC; if (res) res += (long)bz*sR;
    }
    int Klim = (mode == 2) ? (m0 + 64 < K ? m0 + 64 : K) : K;

    __shared__ float As[2][64*AST];
    __shared__ float Bs[2][2304];
    int tid = threadIdx.x;
    int lane = tid & 31, warpId = tid >> 5;
    int g = lane >> 2, tig = lane & 3;
    int warp_m = (warpId & 1) * 32, warp_n = (warpId >> 1) * 32;
    float4 acc[2][4];
    #pragma unroll
    for (int i = 0; i < 2; i++)
        #pragma unroll
        for (int j = 0; j < 4; j++) acc[i][j] = make_float4(0.f,0.f,0.f,0.f);

#define G_LOAD(sidx, k0v) do { int _k0 = (k0v); if (_k0 < Klim) { \
    _Pragma("unroll") for (int i = 0; i < 4; i++) { int idx = tid + i*128; int r = idx >> 3, c4 = (idx & 7) << 2; \
        cp16(&As[sidx][r*AST + c4], &A[(long)(m0+r)*lda + _k0 + c4]); } \
    if (!transB) { \
        _Pragma("unroll") for (int i = 0; i < 4; i++) { int idx = tid + i*128; int r = idx >> 4, c4 = (idx & 15) << 2; \
            cp16(&Bs[sidx][r*BST + c4], &B[(long)(_k0+r)*ldb + n0 + c4]); } \
    } else { \
        _Pragma("unroll") for (int i = 0; i < 4; i++) { int idx = tid + i*128; int r = idx >> 3, c4 = (idx & 7) << 2; \
            cp16(&Bs[sidx][r*AST + c4], &B[(long)(n0+r)*ldb + _k0 + c4]); } \
    } } CP_COMMIT; } while(0)

    int nIter = Klim >> 5;
    G_LOAD(0, 0);
    for (int it = 0; it < nIter; it++) {
        int s = it & 1;
        G_LOAD(s ^ 1, (it + 1) << 5);
        CP_WAIT1;
        __syncthreads();
        #pragma unroll
        for (int kk = 0; kk < 32; kk += 8) {
            unsigned a[2][4], b[4][2];
            #pragma unroll
            for (int mi = 0; mi < 2; mi++) {
                const float* ap = &As[s][(warp_m + mi*16 + g)*AST + kk + tig];
                a[mi][0] = __float_as_uint(ap[0]);
                a[mi][1] = __float_as_uint(ap[8*AST]);
                a[mi][2] = __float_as_uint(ap[4]);
                a[mi][3] = __float_as_uint(ap[8*AST + 4]);
            }
            if (!transB) {
                #pragma unroll
                for (int ni = 0; ni < 4; ni++) {
                    int col = warp_n + ni*8 + g;
                    b[ni][0] = __float_as_uint(Bs[s][(kk+tig)*BST + col]);
                    b[ni][1] = __float_as_uint(Bs[s][(kk+tig+4)*BST + col]);
                }
            } else {
                #pragma unroll
                for (int ni = 0; ni < 4; ni++) {
                    const float* bp = &Bs[s][(warp_n + ni*8 + g)*AST + kk + tig];
                    b[ni][0] = __float_as_uint(bp[0]);
                    b[ni][1] = __float_as_uint(bp[4]);
                }
            }
            #pragma unroll
            for (int mi = 0; mi < 2; mi++)
                #pragma unroll
                for (int ni = 0; ni < 4; ni++) mma_tf32(acc[mi][ni], a[mi], b[ni]);
        }
        __syncthreads();
    }
#undef G_LOAD
    #pragma unroll
    for (int mi = 0; mi < 2; mi++) {
        #pragma unroll
        for (int ni = 0; ni < 4; ni++) {
            int row = m0 + warp_m + mi*16 + g;
            int col = n0 + warp_n + ni*8 + 2*tig;
            float4 c = acc[mi][ni];
            float2 v0 = { alpha*c.x, alpha*c.y };
            float2 v1 = { alpha*c.z, alpha*c.w };
            if (res) {
                float2 r0 = *(const float2*)&res[(long)row*ldc + col];
                float2 r1 = *(const float2*)&res[(long)(row+8)*ldc + col];
                v0.x += r0.x; v0.y += r0.y; v1.x += r1.x; v1.y += r1.y;
            }
            if (roundC) {
                v0.x = rtf(v0.x); v0.y = rtf(v0.y);
                v1.x = rtf(v1.x); v1.y = rtf(v1.y);
            }
            *(float2*)&C[(long)row*ldc + col] = v0;
            *(float2*)&C[(long)(row+8)*ldc + col] = v1;
        }
    }
}

// ---------------- RoPE (rounds q,k only) ----------------
__global__ void rope_kernel() {
    int t = blockIdx.x, tid = threadIdx.x;
    __shared__ float cs[64], sn[64];
    if (tid < 64) {
        float inv = powf(10000.0f, -(float)tid / 64.0f);
        float fr = (float)t * inv;
        cs[tid] = cosf(fr); sn[tid] = sinf(fr);
    }
    __syncthreads();
    for (int idx = tid; idx < NH*64; idx += 256) {
        int hh = idx >> 6, j = idx & 63;
        long b = (long)t*H + hh*HD;
        float c = cs[j], s = sn[j];
        float q1 = g_q[b+j], q2 = g_q[b+j+64];
        g_q[b+j]    = rtf(q1*c - q2*s);
        g_q[b+j+64] = rtf(q2*c + q1*s);
        float k1 = g_k[b+j], k2 = g_k[b+j+64];
        g_k[b+j]    = rtf(k1*c - k2*s);
        g_k[b+j+64] = rtf(k2*c + k1*s);
    }
}

// ---------------- causal softmax: single vectorized read, in-register ----------------
__global__ void attn_softmax() {
    int t = blockIdx.x, hh = blockIdx.y, tid = threadIdx.x;
    float* row = g_scores + ((long)hh*T + t)*(long)T;
    int len = t + 1;
    int zend = ((t >> 6) + 1) << 6;
    int base = tid * 4;
    float4 v = make_float4(0.f, 0.f, 0.f, 0.f);
    bool act = base < zend;
    if (act) v = *(const float4*)&row[base];

    float mx = -3.0e38f;
    if (base + 0 < len) mx = fmaxf(mx, v.x);
    if (base + 1 < len) mx = fmaxf(mx, v.y);
    if (base + 2 < len) mx = fmaxf(mx, v.z);
    if (base + 3 < len) mx = fmaxf(mx, v.w);
    #pragma unroll
    for (int o = 16; o > 0; o >>= 1) mx = fmaxf(mx, __shfl_xor_sync(~0u, mx, o));
    __shared__ float smx[8], ssm[8];
    int w = tid >> 5, l = tid & 31;
    if (l == 0) smx[w] = mx;
    __syncthreads();
    if (w == 0) {
        float m = (l < 8) ? smx[l] : -3.0e38f;
        #pragma unroll
        for (int o = 4; o > 0; o >>= 1) m = fmaxf(m, __shfl_xor_sync(~0u, m, o));
        if (l == 0) smx[0] = m;
    }
    __syncthreads();
    mx = smx[0];

    float e0 = (base + 0 < len) ? __expf(v.x - mx) : 0.f;
    float e1 = (base + 1 < len) ? __expf(v.y - mx) : 0.f;
    float e2 = (base + 2 < len) ? __expf(v.z - mx) : 0.f;
    float e3 = (base + 3 < len) ? __expf(v.w - mx) : 0.f;
    float s = (e0 + e1) + (e2 + e3);
    #pragma unroll
    for (int o = 16; o > 0; o >>= 1) s += __shfl_xor_sync(~0u, s, o);
    if (l == 0) ssm[w] = s;
    __syncthreads();
    if (w == 0) {
        float m = (l < 8) ? ssm[l] : 0.f;
        #pragma unroll
        for (int o = 4; o > 0; o >>= 1) m += __shfl_xor_sync(~0u, m, o);
        if (l == 0) ssm[0] = m;
    }
    __syncthreads();
    float inv = 1.0f / ssm[0];
    if (act) {
        float4 ov;
        ov.x = rtf(e0 * inv);
        ov.y = rtf(e1 * inv);
        ov.z = rtf(e2 * inv);
        ov.w = rtf(e3 * inv);
        *(float4*)&row[base] = ov;
    }
}

// ------- expert transpose -> bf16 [e][k][n], vectorized ------------------------------
__global__ void __launch_bounds__(256) transpose_eb(const float* __restrict__ in,
                                                    unsigned* __restrict__ out,
                                                    int R, int C) {
    int r = blockIdx.y;
    int c0 = blockIdx.x * 32;
    __shared__ unsigned sm[16][68];
    int tid = threadIdx.x;
    {
        int cpair = tid >> 4;
        int e4 = (tid & 15) << 2;
        const float* basep = in + ((long)r*C + c0 + 2*cpair) * 64 + e4;
        float4 a = *(const float4*)basep;
        float4 b = *(const float4*)(basep + 64);
        __nv_bfloat162 t0 = __floats2bfloat162_rn(a.x, b.x);
        __nv_bfloat162 t1 = __floats2bfloat162_rn(a.y, b.y);
        __nv_bfloat162 t2 = __floats2bfloat162_rn(a.z, b.z);
        __nv_bfloat162 t3 = __floats2bfloat162_rn(a.w, b.w);
        uint4 u = { *(unsigned*)&t0, *(unsigned*)&t1, *(unsigned*)&t2, *(unsigned*)&t3 };
        *(uint4*)&sm[cpair][e4] = u;
    }
    __syncthreads();
    {
        int e = tid >> 2;
        int grp = (tid & 3) << 2;
        uint4 v;
        v.x = sm[grp+0][e];
        v.y = sm[grp+1][e];
        v.z = sm[grp+2][e];
        v.w = sm[grp+3][e];
        long C2 = C >> 1;
        *(uint4*)&out[(long)e*R*C2 + (long)r*C2 + (c0 >> 1) + grp] = v;
    }
}

// ---------------- router (parallel dot: 256 thr = 64 experts x 4 parts) ---------------
__global__ void zero_cnt_kernel() { if (threadIdx.x < NEXP) g_cnt[threadIdx.x] = 0; }

__global__ void __launch_bounds__(256) router_kernel(const float* __restrict__ gw) {
    int t = blockIdx.x, tid = threadIdx.x;
    int e = tid & 63, part = tid >> 6;           // 4 parts of 320
    const float* hr = g_h2u + (long)t*H;
    float s = 0.f;
    int h0 = part * 320;
    for (int h = h0; h < h0 + 320; h++) s += hr[h] * gw[h*NEXP + e];
    __shared__ float partial[4][NEXP];
    partial[part][e] = s;
    __syncthreads();
    __shared__ float probs[NEXP];
    if (tid < NEXP) {
        probs[tid] = ((partial[0][tid] + partial[1][tid]) + partial[2][tid]) + partial[3][tid];
    }
    __syncthreads();
    if (tid == 0) {
        float mx = -3e38f;
        for (int i = 0; i < NEXP; i++) mx = fmaxf(mx, probs[i]);
        float sum = 0.f;
        for (int i = 0; i < NEXP; i++) { probs[i] = __expf(probs[i]-mx); sum += probs[i]; }
        float inv = 1.f/sum;
        for (int i = 0; i < NEXP; i++) probs[i] *= inv;
        int ti[TOPK]; float tw[TOPK]; float ws = 0.f;
        for (int j = 0; j < TOPK; j++) {
            int bi = 0; float bv = -1.f;
            for (int i = 0; i < NEXP; i++) if (probs[i] > bv) { bv = probs[i]; bi = i; }
            ti[j] = bi; tw[j] = bv; ws += bv; probs[bi] = -2.f;
        }
        float wi = 1.f/ws;
        for (int j = 0; j < TOPK; j++) {
            g_tokE[t*TOPK+j] = ti[j];
            g_tokW[t*TOPK+j] = tw[j]*wi;
            atomicAdd(&g_cnt[ti[j]], 1);
        }
    }
}

__global__ void prefix_kernel() {
    if (threadIdx.x == 0) {
        int s = 0;
        for (int e = 0; e < NEXP; e++) { g_off[e] = s; g_cur[e] = s; s += g_cnt[e]; }
    }
}

__global__ void scatter_kernel() {
    int i = blockIdx.x*256 + threadIdx.x;
    if (i < NPAIR) {
        int e = g_tokE[i];
        int pos = atomicAdd(&g_cur[e], 1);
        g_pairTok[pos] = i / TOPK;
        g_pairW[pos]   = g_tokW[i];
        g_pairPos[i]   = pos;
    }
}

// -------- bf16 dual GEMM + SiLU (MoE pass1): CTA 128x128, 512 thr, warp 32x32, LDSM --
__global__ void __launch_bounds__(512)
gemm_bf16_dual(const __nv_bfloat16* __restrict__ A, int lda,
               const __nv_bfloat16* __restrict__ B1g, const __nv_bfloat16* __restrict__ B2g,
               long sB, int ldb,
               __nv_bfloat16* __restrict__ Cout, int ldc,
               int K) {
    int e = blockIdx.z;
    int m0 = blockIdx.y * 128;
    int cnt = g_cnt[e], base = g_off[e];
    if (m0 >= cnt) return;
    const __nv_bfloat16* B1 = B1g + (long)e*sB;
    const __nv_bfloat16* B2 = B2g + (long)e*sB;
    int n0 = blockIdx.x * 128;

    __shared__ int stok[128];
    __shared__ unsigned As[3][128][12];
    __shared__ unsigned Bs1[3][16][68];
    __shared__ unsigned Bs2[3][16][68];
    int tid = threadIdx.x;
    int lane = tid & 31, warpId = tid >> 5;
    int g = lane >> 2, tig = lane & 3;
    int warp_m = (warpId & 3) * 32, warp_n = (warpId >> 2) * 32;
    if (tid < 128) stok[tid] = (m0 + tid < cnt) ? g_pairTok[base + m0 + tid] : 0;
    __syncthreads();
    float4 accG[2][4], accU[2][4];
    #pragma unroll
    for (int i = 0; i < 2; i++)
        #pragma unroll
        for (int j = 0; j < 4; j++) { accG[i][j] = make_float4(0,0,0,0); accU[i][j] = make_float4(0,0,0,0); }

#define D_LOAD(sidx, k0v) do { int _k0 = (k0v); if (_k0 < K) { \
    if (tid < 256) { int r = tid >> 1, ch = tid & 1; \
      cp16(&As[sidx][r][ch*4], &A[(long)stok[r]*lda + _k0 + ch*8]); } \
    else { int t2 = tid - 256; int r = t2 >> 4, ch = t2 & 15; \
      cp16(&Bs1[sidx][r][ch*4], &B1[(long)(_k0+r)*ldb + n0 + ch*8]); \
      cp16(&Bs2[sidx][r][ch*4], &B2[(long)(_k0+r)*ldb + n0 + ch*8]); } \
    } CP_COMMIT; } while(0)

    const int nIter = K >> 4;
    D_LOAD(0, 0);
    D_LOAD(1, 16);
    int st = 0;
    int half16 = (lane >> 4) * 16;
    for (int it = 0; it < nIter; it++) {
        CP_WAIT1;
        __syncthreads();
        unsigned aBase = (unsigned)__cvta_generic_to_shared(&As[st][0][0]);
        unsigned b1Base = (unsigned)__cvta_generic_to_shared(&Bs1[st][0][0]);
        unsigned b2Base = (unsigned)__cvta_generic_to_shared(&Bs2[st][0][0]);
        unsigned a[2][4], b1[4][2], b2[4][2];
        #pragma unroll
        for (int mi = 0; mi < 2; mi++) {
            int row = warp_m + mi*16 + (lane & 15);
            ldsm4(a[mi][0], a[mi][1], a[mi][2], a[mi][3], aBase + row*48 + half16);
        }
        #pragma unroll
        for (int nh = 0; nh < 2; nh++) {
            int krow = lane & 15;
            int col = warp_n + nh*16 + (lane >> 4) * 8;
            ldsm4t(b1[nh*2][0], b1[nh*2][1], b1[nh*2+1][0], b1[nh*2+1][1],
                   b1Base + krow*272 + col*2);
            ldsm4t(b2[nh*2][0], b2[nh*2][1], b2[nh*2+1][0], b2[nh*2+1][1],
                   b2Base + krow*272 + col*2);
        }
        #pragma unroll
        for (int mi = 0; mi < 2; mi++)
            #pragma unroll
            for (int ni = 0; ni < 4; ni++) {
                mma_bf16(accG[mi][ni], a[mi], b1[ni]);
                mma_bf16(accU[mi][ni], a[mi], b2[ni]);
            }
        int wst = st + 2; if (wst >= 3) wst -= 3;
        D_LOAD(wst, (it + 2) << 4);
        if (++st == 3) st = 0;
    }
#undef D_LOAD
    #pragma unroll
    for (int mi = 0; mi < 2; mi++) {
        #pragma unroll
        for (int ni = 0; ni < 4; ni++) {
            int mrow = warp_m + mi*16 + g;
            int col = n0 + warp_n + ni*8 + 2*tig;
            float4 cg = accG[mi][ni], cu = accU[mi][ni];
            if (m0 + mrow < cnt) {
                float g0 = cg.x, g1 = cg.y;
                __nv_bfloat162 v = __floats2bfloat162_rn((g0/(1.f+__expf(-g0)))*cu.x,
                                                         (g1/(1.f+__expf(-g1)))*cu.y);
                *(__nv_bfloat162*)&Cout[(long)(base+m0+mrow)*ldc + col] = v;
            }
            if (m0 + mrow + 8 < cnt) {
                float g0 = cg.z, g1 = cg.w;
                __nv_bfloat162 v = __floats2bfloat162_rn((g0/(1.f+__expf(-g0)))*cu.z,
                                                         (g1/(1.f+__expf(-g1)))*cu.w);
                *(__nv_bfloat162*)&Cout[(long)(base+m0+mrow+8)*ldc + col] = v;
            }
        }
    }
}

// -------- bf16 single GEMM (MoE pass2): CTA 128x128, 256 thr, warp 64x32, LDSM -------
__global__ void __launch_bounds__(256)
gemm_bf16_one(const __nv_bfloat16* __restrict__ A, int lda,
              const __nv_bfloat16* __restrict__ Bg, long sB, int ldb,
              float* __restrict__ Cout, int ldc,
              int K) {
    int e = blockIdx.z;
    int m0 = blockIdx.y * 128;
    int cnt = g_cnt[e], base = g_off[e];
    if (m0 >= cnt) return;
    const __nv_bfloat16* B = Bg + (long)e*sB;
    int n0 = blockIdx.x * 128;

    __shared__ unsigned As[3][128][12];
    __shared__ unsigned Bs[3][16][68];
    int tid = threadIdx.x;
    int lane = tid & 31, warpId = tid >> 5;
    int g = lane >> 2, tig = lane & 3;
    int warp_m = (warpId & 1) * 64, warp_n = (warpId >> 1) * 32;
    float4 acc[4][4];
    #pragma unroll
    for (int i = 0; i < 4; i++)
        #pragma unroll
        for (int j = 0; j < 4; j++) acc[i][j] = make_float4(0,0,0,0);

#define S_LOAD(sidx, k0v) do { int _k0 = (k0v); if (_k0 < K) { \
    { int r = tid >> 1, ch = tid & 1; \
      int rr = m0 + r; if (rr >= cnt) rr = cnt - 1; \
      cp16(&As[sidx][r][ch*4], &A[(long)(base + rr)*lda + _k0 + ch*8]); } \
    { int r = tid >> 4, ch = tid & 15; \
      cp16(&Bs[sidx][r][ch*4], &B[(long)(_k0+r)*ldb + n0 + ch*8]); } \
    } CP_COMMIT; } while(0)

    const int nIter = K >> 4;
    S_LOAD(0, 0);
    S_LOAD(1, 16);
    int st = 0;
    int half16 = (lane >> 4) * 16;
    for (int it = 0; it < nIter; it++) {
        CP_WAIT1;
        __syncthreads();
        unsigned aBase = (unsigned)__cvta_generic_to_shared(&As[st][0][0]);
        unsigned bBase = (unsigned)__cvta_generic_to_shared(&Bs[st][0][0]);
        unsigned a[4][4], b[4][2];
        #pragma unroll
        for (int mi = 0; mi < 4; mi++) {
            int row = warp_m + mi*16 + (lane & 15);
            ldsm4(a[mi][0], a[mi][1], a[mi][2], a[mi][3], aBase + row*48 + half16);
        }
        #pragma unroll
        for (int nh = 0; nh < 2; nh++) {
            int krow = lane & 15;
            int col = warp_n + nh*16 + (lane >> 4) * 8;
            ldsm4t(b[nh*2][0], b[nh*2][1], b[nh*2+1][0], b[nh*2+1][1],
                   bBase + krow*272 + col*2);
        }
        #pragma unroll
        for (int mi = 0; mi < 4; mi++)
            #pragma unroll
            for (int ni = 0; ni < 4; ni++) mma_bf16(acc[mi][ni], a[mi], b[ni]);
        int wst = st + 2; if (wst >= 3) wst -= 3;
        S_LOAD(wst, (it + 2) << 4);
        if (++st == 3) st = 0;
    }
#undef S_LOAD
    #pragma unroll
    for (int mi = 0; mi < 4; mi++) {
        #pragma unroll
        for (int ni = 0; ni < 4; ni++) {
            int mrow = warp_m + mi*16 + g;
            int col = n0 + warp_n + ni*8 + 2*tig;
            float4 c = acc[mi][ni];
            if (m0 + mrow < cnt)
                *(float2*)&Cout[(long)(base+m0+mrow)*ldc + col] = make_float2(c.x, c.y);
            if (m0 + mrow + 8 < cnt)
                *(float2*)&Cout[(long)(base+m0+mrow+8)*ldc + col] = make_float2(c.z, c.w);
        }
    }
}

// ---------------- shared-FFN activation (vectorized, rounds output) ----------------
__global__ void silumul_kernel(float4* __restrict__ g, const float4* __restrict__ u, int n4) {
    int i = blockIdx.x*256 + threadIdx.x;
    if (i < n4) {
        float4 x = g[i];
        float4 y = u[i];
        x.x = rtf((x.x / (1.f + __expf(-x.x))) * y.x);
        x.y = rtf((x.y / (1.f + __expf(-x.y))) * y.y);
        x.z = rtf((x.z / (1.f + __expf(-x.z))) * y.z);
        x.w = rtf((x.w / (1.f + __expf(-x.w))) * y.w);
        g[i] = x;
    }
}

// ---------------- final combine (vectorized: 320 thr, float4) ----------------
__global__ void __launch_bounds__(320) combine_kernel(float* __restrict__ out) {
    int t = blockIdx.x;
    int pos[TOPK]; float w[TOPK];
    #pragma unroll
    for (int j = 0; j < TOPK; j++) {
        pos[j] = g_pairPos[t*TOPK + j];
        w[j]   = g_pairW[pos[j]];
    }
    int h = threadIdx.x * 4;
    float4 s  = *(const float4*)&g_hres[(long)t*H + h];
    float4 sh = *(const float4*)&g_shared[(long)t*H + h];
    s.x += sh.x; s.y += sh.y; s.z += sh.z; s.w += sh.w;
    #pragma unroll
    for (int j = 0; j < TOPK; j++) {
        float4 p = *(const float4*)&g_pairout[(long)pos[j]*H + h];
        s.x += w[j]*p.x; s.y += w[j]*p.y; s.z += w[j]*p.z; s.w += w[j]*p.w;
    }
    *(float4*)&out[(long)t*H + h] = s;
}

// ---------------- launch ----------------
extern "C" void kernel_launch(void* const* d_in, const int* in_sizes, int n_in,
                              void* d_out, int out_size) {
    (void)in_sizes; (void)n_in; (void)out_size;
    const float* x       = (const float*)d_in[0];
    const float* ln1     = (const float*)d_in[1];
    const float* ln2     = (const float*)d_in[2];
    const float* Wq      = (const float*)d_in[3];
    const float* Wk      = (const float*)d_in[4];
    const float* Wv      = (const float*)d_in[5];
    const float* Wo      = (const float*)d_in[6];
    const float* gate_w  = (const float*)d_in[7];
    const float* gpe     = (const float*)d_in[8];
    const float* upe     = (const float*)d_in[9];
    const float* dpe     = (const float*)d_in[10];
    const float* sh_gate = (const float*)d_in[11];
    const float* sh_up   = (const float*)d_in[12];
    const float* sh_down = (const float*)d_in[13];
    float* out = (float*)d_out;

    float *h1p,*qp,*kp,*vp,*scoresp,*attnp,*hresp,*h2p,*h2up,*sgp,*sup,*sharedp,*pairoutp;
    __nv_bfloat16 *h2bp,*actBp,*gpeBp,*upeBp,*dpeBp;
    float *wqr,*wkr,*wvr,*wor,*shgr,*shur,*shdr;
    cudaGetSymbolAddress((void**)&h1p,     g_h1);
    cudaGetSymbolAddress((void**)&qp,      g_q);
    cudaGetSymbolAddress((void**)&kp,      g_k);
    cudaGetSymbolAddress((void**)&vp,      g_v);
    cudaGetSymbolAddress((void**)&scoresp, g_scores);
    cudaGetSymbolAddress((void**)&attnp,   g_attnout);
    cudaGetSymbolAddress((void**)&hresp,   g_hres);
    cudaGetSymbolAddress((void**)&h2p,     g_h2);
    cudaGetSymbolAddress((void**)&h2up,    g_h2u);
    cudaGetSymbolAddress((void**)&h2bp,    g_h2b);
    cudaGetSymbolAddress((void**)&sgp,     g_sg);
    cudaGetSymbolAddress((void**)&sup,     g_su);
    cudaGetSymbolAddress((void**)&sharedp, g_shared);
    cudaGetSymbolAddress((void**)&actBp,   g_actB);
    cudaGetSymbolAddress((void**)&pairoutp,g_pairout);
    cudaGetSymbolAddress((void**)&gpeBp,   g_gpeB);
    cudaGetSymbolAddress((void**)&upeBp,   g_upeB);
    cudaGetSymbolAddress((void**)&dpeBp,   g_dpeB);
    cudaGetSymbolAddress((void**)&wqr,     g_WqR);
    cudaGetSymbolAddress((void**)&wkr,     g_WkR);
    cudaGetSymbolAddress((void**)&wvr,     g_WvR);
    cudaGetSymbolAddress((void**)&wor,     g_WoR);
    cudaGetSymbolAddress((void**)&shgr,    g_shgR);
    cudaGetSymbolAddress((void**)&shur,    g_shuR);
    cudaGetSymbolAddress((void**)&shdr,    g_shdR);

    const float inv_sqrt_hd = 0.08838834764831845f;

    // Exactly one side stream + six events (proven resource footprint).
    cudaStream_t s2;
    cudaStreamCreateWithFlags(&s2, cudaStreamNonBlocking);
    cudaEvent_t evFork, evH1, evV, evSide, evH2, evShared;
    cudaEventCreateWithFlags(&evFork,   cudaEventDisableTiming);
    cudaEventCreateWithFlags(&evH1,     cudaEventDisableTiming);
    cudaEventCreateWithFlags(&evV,      cudaEventDisableTiming);
    cudaEventCreateWithFlags(&evSide,   cudaEventDisableTiming);
    cudaEventCreateWithFlags(&evH2,     cudaEventDisableTiming);
    cudaEventCreateWithFlags(&evShared, cudaEventDisableTiming);

    cudaEventRecord(evFork, 0);
    cudaStreamWaitEvent(s2, evFork, 0);

    // s2: Wv/Wo rounding first (so the Wv GEMM can start right after rms1)
    round_pair<<<dim3((H*NH*HD/4 + 255)/256, 2), 256, 0, s2>>>(
        (const float4*)Wv, (float4*)wvr, (const float4*)Wo, (float4*)wor);

    // main: Wq/Wk rounding + rms1
    round_pair<<<dim3((H*NH*HD/4 + 255)/256, 2), 256>>>(
        (const float4*)Wq, (float4*)wqr, (const float4*)Wk, (float4*)wkr);
    rms_kernel<<<T, 256>>>(x, ln1, h1p, nullptr, nullptr);
    cudaEventRecord(evH1, 0);

    // s2: Wv projection, transposes (evSide ASAP), then shared-weight rounding
    cudaStreamWaitEvent(s2, evH1, 0);
    gemm_tc<<<dim3(H/64, T/64, 1), 128, 0, s2>>>(h1p, H, 0, wvr, nullptr, nullptr, H, 0, 0,
                                                 vp, nullptr, nullptr, H, 0, nullptr, 0,
                                                 H, 1.f, 0, 1);
    cudaEventRecord(evV, s2);   // also implies wor ready (s2 in-order)
    transpose_eb<<<dim3(EI/32, H), 256, 0, s2>>>(gpe, (unsigned*)gpeBp, H, EI);
    transpose_eb<<<dim3(EI/32, H), 256, 0, s2>>>(upe, (unsigned*)upeBp, H, EI);
    transpose_eb<<<dim3(H/32, EI), 256, 0, s2>>>(dpe, (unsigned*)dpeBp, EI, H);
    cudaEventRecord(evSide, s2);
    round_shared<<<dim3((H*SHF/4 + 255)/256, 3), 256, 0, s2>>>(
        (const float4*)sh_gate, (float4*)shgr, (const float4*)sh_up, (float4*)shur,
        (const float4*)sh_down, (float4*)shdr);

    // main: Q,K projections + attention chain (tf32)
    gemm_tc<<<dim3(H/64, T/64, 2), 128>>>(h1p, H, 0, wqr, wkr, nullptr, H, 0, 0,
                                          qp, kp, nullptr, H, 0, nullptr, 0,
                                          H, 1.f, 0, 0);
    rope_kernel<<<T, 256>>>();
    gemm_tc<<<dim3(T/64, T/64, NH), 128>>>(qp, H, HD, kp, nullptr, nullptr, H, HD, 1,
                                           scoresp, nullptr, nullptr, T, (long)T*T, nullptr, 0,
                                           HD, inv_sqrt_hd, 1, 0);
    attn_softmax<<<dim3(T, NH), 256>>>();
    cudaStreamWaitEvent(0, evV, 0);   // v + wor ready
    gemm_tc<<<dim3(HD/64, T/64, NH), 128>>>(scoresp, T, (long)T*T, vp, nullptr, nullptr, H, HD, 0,
                                            attnp, nullptr, nullptr, H, HD, nullptr, 0,
                                            T, 1.f, 2, 1);
    gemm_tc<<<dim3(H/64, T/64, 1), 128>>>(attnp, H, 0, wor, nullptr, nullptr, H, 0, 0,
                                          hresp, nullptr, nullptr, H, 0, x, 0,
                                          H, 1.f, 0, 0);

    // h2 (all three variants)
    rms_kernel<<<T, 256>>>(hresp, ln2, h2p, h2up, h2bp);
    cudaEventRecord(evH2, 0);

    // s2: shared FFN (tf32) overlaps router + MoE on main
    cudaStreamWaitEvent(s2, evH2, 0);
    gemm_tc<<<dim3(SHF/64, T/64, 2), 128, 0, s2>>>(h2p, H, 0, shgr, shur, nullptr, SHF, 0, 0,
                                                   sgp, sup, nullptr, SHF, 0, nullptr, 0,
                                                   H, 1.f, 0, 0);
    silumul_kernel<<<(T*SHF/4 + 255)/256, 256, 0, s2>>>((float4*)sgp, (const float4*)sup, T*SHF/4);
    gemm_tc<<<dim3(H/64, T/64, 1), 128, 0, s2>>>(sgp, SHF, 0, shdr, nullptr, nullptr, H, 0, 0,
                                                 sharedp, nullptr, nullptr, H, 0, nullptr, 0,
                                                 SHF, 1.f, 0, 0);
    cudaEventRecord(evShared, s2);

    // main: router + MoE (bf16 LDSM, 128x128 tiles)
    zero_cnt_kernel<<<1, 64>>>();
    router_kernel<<<T, 256>>>(gate_w);
    prefix_kernel<<<1, 32>>>();
    scatter_kernel<<<(NPAIR + 255)/256, 256>>>();
    cudaStreamWaitEvent(0, evSide, 0);
    gemm_bf16_dual<<<dim3(EI/128, T/128, NEXP), 512>>>(
        h2bp, H, gpeBp, upeBp, (long)H*EI, EI, actBp, EI, H);
    gemm_bf16_one<<<dim3(H/128, T/128, NEXP), 256>>>(
        actBp, EI, dpeBp, (long)EI*H, H, pairoutp, H, EI);

    // join shared FFN, then combine
    cudaStreamWaitEvent(0, evShared, 0);
    combine_kernel<<<T, 320>>>(out);
}

// round 17
// speedup vs baseline: 1.8808x; 1.0209x over previous
#include <cuda_runtime.h>
#include <cuda_bf16.h>
#include <cuda_fp16.h>
#include <math.h>

#define T 1024
#define H 1280
#define NH 10
#define HD 128
#define EI 896
#define NEXP 64
#define TOPK 6
#define SHF 1792
#define NPAIR (T*TOPK)

// ---------------- device scratch ----------------
static __device__ __half g_h1H[T*H];
static __device__ __half g_qH[T*H];
static __device__ __half g_kH[T*H];
static __device__ __half g_vH[T*H];
static __device__ __half g_qRH[T*H];
static __device__ __half g_kTH[NH*HD*T];
static __device__ float g_scores[NH*T*T];
static __device__ __half g_probsH[(size_t)NH*T*T];
static __device__ __half g_attnH[T*H];
static __device__ float g_hres[T*H];
static __device__ float g_h2[T*H];
static __device__ float g_h2u[T*H];
static __device__ __nv_bfloat16 g_h2b[T*H];
static __device__ float g_sg[T*SHF];
static __device__ float g_su[T*SHF];
static __device__ float g_shared[T*H];
static __device__ __nv_bfloat16 g_gpeB[(size_t)NEXP*H*EI];
static __device__ __nv_bfloat16 g_upeB[(size_t)NEXP*H*EI];
static __device__ __nv_bfloat16 g_dpeB[(size_t)NEXP*EI*H];
static __device__ __nv_bfloat16 g_actB[(size_t)(NPAIR+128)*EI];
static __device__ float g_pairout[(size_t)NPAIR*H];
static __device__ __half g_WqH[H*NH*HD];
static __device__ __half g_WkH[H*NH*HD];
static __device__ __half g_WvH[H*NH*HD];
static __device__ __half g_WoH[NH*HD*H];
static __device__ float g_shgR[H*SHF];
static __device__ float g_shuR[H*SHF];
static __device__ float g_shdR[SHF*H];
static __device__ int   g_cnt[NEXP];
static __device__ int   g_off[NEXP];
static __device__ int   g_cur[NEXP];
static __device__ int   g_tokE[NPAIR];
static __device__ float g_tokW[NPAIR];
static __device__ int   g_pairTok[NPAIR];
static __device__ float g_pairW[NPAIR];
static __device__ int   g_pairPos[NPAIR];

// ---------------- helpers ----------------
__device__ __forceinline__ void mma_tf32(float4& c, const unsigned a[4], const unsigned b[2]) {
    asm volatile("mma.sync.aligned.m16n8k8.row.col.f32.tf32.tf32.f32 "
        "{%0,%1,%2,%3}, {%4,%5,%6,%7}, {%8,%9}, {%0,%1,%2,%3};"
        : "+f"(c.x), "+f"(c.y), "+f"(c.z), "+f"(c.w)
        : "r"(a[0]), "r"(a[1]), "r"(a[2]), "r"(a[3]), "r"(b[0]), "r"(b[1]));
}
__device__ __forceinline__ void mma_bf16(float4& c, const unsigned a[4], const unsigned b[2]) {
    asm volatile("mma.sync.aligned.m16n8k16.row.col.f32.bf16.bf16.f32 "
        "{%0,%1,%2,%3}, {%4,%5,%6,%7}, {%8,%9}, {%0,%1,%2,%3};"
        : "+f"(c.x), "+f"(c.y), "+f"(c.z), "+f"(c.w)
        : "r"(a[0]), "r"(a[1]), "r"(a[2]), "r"(a[3]), "r"(b[0]), "r"(b[1]));
}
__device__ __forceinline__ void mma_f16(float4& c, const unsigned a[4], const unsigned b[2]) {
    asm volatile("mma.sync.aligned.m16n8k16.row.col.f32.f16.f16.f32 "
        "{%0,%1,%2,%3}, {%4,%5,%6,%7}, {%8,%9}, {%0,%1,%2,%3};"
        : "+f"(c.x), "+f"(c.y), "+f"(c.z), "+f"(c.w)
        : "r"(a[0]), "r"(a[1]), "r"(a[2]), "r"(a[3]), "r"(b[0]), "r"(b[1]));
}
__device__ __forceinline__ float rtf(float f) {
    unsigned r; asm("cvt.rna.tf32.f32 %0, %1;" : "=r"(r) : "f"(f));
    return __uint_as_float(r);
}
__device__ __forceinline__ void cp16(const void* smem, const void* gmem) {
    unsigned sa = (unsigned)__cvta_generic_to_shared(smem);
    asm volatile("cp.async.cg.shared.global [%0], [%1], 16;" :: "r"(sa), "l"(gmem));
}
__device__ __forceinline__ void ldsm4(unsigned& r0, unsigned& r1, unsigned& r2, unsigned& r3,
                                      unsigned addr) {
    asm volatile("ldmatrix.sync.aligned.m8n8.x4.shared.b16 {%0,%1,%2,%3}, [%4];"
        : "=r"(r0), "=r"(r1), "=r"(r2), "=r"(r3) : "r"(addr));
}
__device__ __forceinline__ void ldsm4t(unsigned& r0, unsigned& r1, unsigned& r2, unsigned& r3,
                                       unsigned addr) {
    asm volatile("ldmatrix.sync.aligned.m8n8.x4.trans.shared.b16 {%0,%1,%2,%3}, [%4];"
        : "=r"(r0), "=r"(r1), "=r"(r2), "=r"(r3) : "r"(addr));
}
#define CP_COMMIT asm volatile("cp.async.commit_group;")
#define CP_WAIT1  asm volatile("cp.async.wait_group 1;")

#define AST 36
#define BST 72

// ---------------- attention weights fp32 -> fp16 (z 0..1) ----------------
__global__ void conv_pair(const float4* w0, uint2* o0, const float4* w1, uint2* o1) {
    int z = blockIdx.y;
    const float4* in = z ? w1 : w0;
    uint2* out = z ? o1 : o0;
    int i = blockIdx.x*256 + threadIdx.x;
    if (i < H*NH*HD/4) {
        float4 v = in[i];
        __half2 lo = __floats2half2_rn(v.x, v.y);
        __half2 hi = __floats2half2_rn(v.z, v.w);
        out[i] = make_uint2(*(unsigned*)&lo, *(unsigned*)&hi);
    }
}

// ---------------- weight rounding: shared-FFN mats (z 0..2) ----------------
__global__ void round_shared(const float4* w4, float4* o4, const float4* w5, float4* o5,
                             const float4* w6, float4* o6) {
    int z = blockIdx.y;
    const float4* in; float4* out; int n4;
    switch (z) { case 0: in=w4; out=o4; n4=H*SHF/4; break;
                 case 1: in=w5; out=o5; n4=H*SHF/4; break;
                 default: in=w6; out=o6; n4=SHF*H/4; }
    int i = blockIdx.x*256 + threadIdx.x;
    if (i < n4) {
        float4 v = in[i];
        v.x = rtf(v.x); v.y = rtf(v.y); v.z = rtf(v.z); v.w = rtf(v.w);
        out[i] = v;
    }
}

// ---------------- RMSNorm (fp32/unrounded/bf16/fp16 outputs optional) ----------------
__global__ void rms_kernel(const float* __restrict__ x, const float* __restrict__ w,
                           float* __restrict__ out, float* __restrict__ outu,
                           __nv_bfloat16* __restrict__ outb, __half* __restrict__ outh) {
    int t = blockIdx.x;
    const float* xr = x + (long)t*H;
    __shared__ float red[256];
    float s = 0.f;
    for (int i = threadIdx.x; i < H; i += 256) { float v = xr[i]; s += v*v; }
    red[threadIdx.x] = s; __syncthreads();
    for (int k = 128; k > 0; k >>= 1) {
        if (threadIdx.x < k) red[threadIdx.x] += red[threadIdx.x + k];
        __syncthreads();
    }
    float r = rsqrtf(red[0]/(float)H + 1e-6f);
    for (int i = threadIdx.x; i < H; i += 256) {
        float v = w[i]*xr[i]*r;
        if (out)  out[(long)t*H + i] = rtf(v);
        if (outu) outu[(long)t*H + i] = v;
        if (outb) outb[(long)t*H + i] = __float2bfloat16(v);
        if (outh) outh[(long)t*H + i] = __float2half(v);
    }
}

// ---------------- tf32 GEMM (shared FFN only): 64x64, BK32, 2-stage ----------
__global__ void __launch_bounds__(128)
gemm_tc(const float* __restrict__ A, int lda, long sA,
        const float* __restrict__ B, const float* __restrict__ Bb, const float* __restrict__ Bc,
        int ldb, long sB, int transB,
        float* __restrict__ C, float* __restrict__ Cb, float* __restrict__ Cc,
        int ldc, long sC,
        const float* __restrict__ res, long sR,
        int K, float alpha, int mode, int roundC) {
    int m0 = blockIdx.y*64, n0 = blockIdx.x*64;
    if (mode == 1 && n0 >= m0 + 64) return;
    int bz = blockIdx.z;
    A += (long)bz*sA;
    if (Bb) {
        if (bz == 1) { B = Bb; C = Cb; }
        else if (bz == 2) { B = Bc; C = Cc; }
    } else {
        B += (long)bz*sB; C += (long)bz*sC; if (res) res += (long)bz*sR;
    }
    int Klim = (mode == 2) ? (m0 + 64 < K ? m0 + 64 : K) : K;

    __shared__ float As[2][64*AST];
    __shared__ float Bs[2][2304];
    int tid = threadIdx.x;
    int lane = tid & 31, warpId = tid >> 5;
    int g = lane >> 2, tig = lane & 3;
    int warp_m = (warpId & 1) * 32, warp_n = (warpId >> 1) * 32;
    float4 acc[2][4];
    #pragma unroll
    for (int i = 0; i < 2; i++)
        #pragma unroll
        for (int j = 0; j < 4; j++) acc[i][j] = make_float4(0.f,0.f,0.f,0.f);

#define G_LOAD(sidx, k0v) do { int _k0 = (k0v); if (_k0 < Klim) { \
    _Pragma("unroll") for (int i = 0; i < 4; i++) { int idx = tid + i*128; int r = idx >> 3, c4 = (idx & 7) << 2; \
        cp16(&As[sidx][r*AST + c4], &A[(long)(m0+r)*lda + _k0 + c4]); } \
    if (!transB) { \
        _Pragma("unroll") for (int i = 0; i < 4; i++) { int idx = tid + i*128; int r = idx >> 4, c4 = (idx & 15) << 2; \
            cp16(&Bs[sidx][r*BST + c4], &B[(long)(_k0+r)*ldb + n0 + c4]); } \
    } else { \
        _Pragma("unroll") for (int i = 0; i < 4; i++) { int idx = tid + i*128; int r = idx >> 3, c4 = (idx & 7) << 2; \
            cp16(&Bs[sidx][r*AST + c4], &B[(long)(n0+r)*ldb + _k0 + c4]); } \
    } } CP_COMMIT; } while(0)

    int nIter = Klim >> 5;
    G_LOAD(0, 0);
    for (int it = 0; it < nIter; it++) {
        int s = it & 1;
        G_LOAD(s ^ 1, (it + 1) << 5);
        CP_WAIT1;
        __syncthreads();
        #pragma unroll
        for (int kk = 0; kk < 32; kk += 8) {
            unsigned a[2][4], b[4][2];
            #pragma unroll
            for (int mi = 0; mi < 2; mi++) {
                const float* ap = &As[s][(warp_m + mi*16 + g)*AST + kk + tig];
                a[mi][0] = __float_as_uint(ap[0]);
                a[mi][1] = __float_as_uint(ap[8*AST]);
                a[mi][2] = __float_as_uint(ap[4]);
                a[mi][3] = __float_as_uint(ap[8*AST + 4]);
            }
            if (!transB) {
                #pragma unroll
                for (int ni = 0; ni < 4; ni++) {
                    int col = warp_n + ni*8 + g;
                    b[ni][0] = __float_as_uint(Bs[s][(kk+tig)*BST + col]);
                    b[ni][1] = __float_as_uint(Bs[s][(kk+tig+4)*BST + col]);
                }
            } else {
                #pragma unroll
                for (int ni = 0; ni < 4; ni++) {
                    const float* bp = &Bs[s][(warp_n + ni*8 + g)*AST + kk + tig];
                    b[ni][0] = __float_as_uint(bp[0]);
                    b[ni][1] = __float_as_uint(bp[4]);
                }
            }
            #pragma unroll
            for (int mi = 0; mi < 2; mi++)
                #pragma unroll
                for (int ni = 0; ni < 4; ni++) mma_tf32(acc[mi][ni], a[mi], b[ni]);
        }
        __syncthreads();
    }
#undef G_LOAD
    #pragma unroll
    for (int mi = 0; mi < 2; mi++) {
        #pragma unroll
        for (int ni = 0; ni < 4; ni++) {
            int row = m0 + warp_m + mi*16 + g;
            int col = n0 + warp_n + ni*8 + 2*tig;
            float4 c = acc[mi][ni];
            float2 v0 = { alpha*c.x, alpha*c.y };
            float2 v1 = { alpha*c.z, alpha*c.w };
            if (res) {
                float2 r0 = *(const float2*)&res[(long)row*ldc + col];
                float2 r1 = *(const float2*)&res[(long)(row+8)*ldc + col];
                v0.x += r0.x; v0.y += r0.y; v1.x += r1.x; v1.y += r1.y;
            }
            if (roundC) {
                v0.x = rtf(v0.x); v0.y = rtf(v0.y);
                v1.x = rtf(v1.x); v1.y = rtf(v1.y);
            }
            *(float2*)&C[(long)row*ldc + col] = v0;
            *(float2*)&C[(long)(row+8)*ldc + col] = v1;
        }
    }
}

// -------- fp16 general GEMM (attention): CTA 128x64, 128 thr, warp 64x32, LDSM -------
// A[m][k] fp16 (z: A += z*sA). B[k][n] fp16: z-select via Bb/Bc, else B += z*sB.
// Output: outHf ? fp16 : fp32 (z-select with B, or += z*sC). Optional fp32 res (z=0).
// mode: 0 none, 1 causal tile skip (n0 >= m0+128), 2 K capped at m0+128.
__global__ void __launch_bounds__(128)
gemm_hf(const __half* __restrict__ A, int lda, long sA,
        const __half* __restrict__ B, const __half* __restrict__ Bb,
        const __half* __restrict__ Bc, int ldb, long sB,
        void* __restrict__ C, void* __restrict__ Cb, void* __restrict__ Cc,
        int ldc, long sC, int outHf,
        const float* __restrict__ res, float alpha, int K, int mode) {
    int m0 = blockIdx.y * 128, n0 = blockIdx.x * 64;
    if (mode == 1 && n0 >= m0 + 128) return;
    int bz = blockIdx.z;
    A += (long)bz*sA;
    void* Cp = C;
    if (Bb) {
        if (bz == 1) { B = Bb; Cp = Cb; }
        else if (bz == 2) { B = Bc; Cp = Cc; }
    } else {
        B += (long)bz*sB;
        Cp = outHf ? (void*)((__half*)C + (long)bz*sC) : (void*)((float*)C + (long)bz*sC);
    }
    int Klim = (mode == 2) ? (m0 + 128 < K ? m0 + 128 : K) : K;

    __shared__ unsigned As[3][128][12];
    __shared__ unsigned Bs[3][16][36];
    int tid = threadIdx.x;
    int lane = tid & 31, warpId = tid >> 5;
    int g = lane >> 2, tig = lane & 3;
    int warp_m = (warpId & 1) * 64, warp_n = (warpId >> 1) * 32;
    float4 acc[4][4];
    #pragma unroll
    for (int i = 0; i < 4; i++)
        #pragma unroll
        for (int j = 0; j < 4; j++) acc[i][j] = make_float4(0,0,0,0);

#define HF_LOAD(sidx, k0v) do { int _k0 = (k0v); if (_k0 < Klim) { \
    _Pragma("unroll") for (int i = 0; i < 2; i++) { int idx = tid + i*128; int r = idx >> 1, ch = idx & 1; \
      cp16(&As[sidx][r][ch*4], &A[(long)(m0 + r)*lda + _k0 + ch*8]); } \
    { int r = tid >> 3, ch = tid & 7; \
      cp16(&Bs[sidx][r][ch*4], &B[(long)(_k0+r)*ldb + n0 + ch*8]); } \
    } CP_COMMIT; } while(0)

    const int nIter = Klim >> 4;
    HF_LOAD(0, 0);
    HF_LOAD(1, 16);
    int st = 0;
    int half16 = (lane >> 4) * 16;
    for (int it = 0; it < nIter; it++) {
        CP_WAIT1;
        __syncthreads();
        unsigned aBase = (unsigned)__cvta_generic_to_shared(&As[st][0][0]);
        unsigned bBase = (unsigned)__cvta_generic_to_shared(&Bs[st][0][0]);
        unsigned a[4][4], b[4][2];
        #pragma unroll
        for (int mi = 0; mi < 4; mi++) {
            int row = warp_m + mi*16 + (lane & 15);
            ldsm4(a[mi][0], a[mi][1], a[mi][2], a[mi][3], aBase + row*48 + half16);
        }
        #pragma unroll
        for (int nh = 0; nh < 2; nh++) {
            int krow = lane & 15;
            int col = warp_n + nh*16 + (lane >> 4) * 8;
            ldsm4t(b[nh*2][0], b[nh*2][1], b[nh*2+1][0], b[nh*2+1][1],
                   bBase + krow*144 + col*2);
        }
        #pragma unroll
        for (int mi = 0; mi < 4; mi++)
            #pragma unroll
            for (int ni = 0; ni < 4; ni++) mma_f16(acc[mi][ni], a[mi], b[ni]);
        int wst = st + 2; if (wst >= 3) wst -= 3;
        HF_LOAD(wst, (it + 2) << 4);
        if (++st == 3) st = 0;
    }
#undef HF_LOAD
    #pragma unroll
    for (int mi = 0; mi < 4; mi++) {
        #pragma unroll
        for (int ni = 0; ni < 4; ni++) {
            int r0i = m0 + warp_m + mi*16 + g;
            int col = n0 + warp_n + ni*8 + 2*tig;
            float4 c = acc[mi][ni];
            float2 v0 = { alpha*c.x, alpha*c.y };
            float2 v1 = { alpha*c.z, alpha*c.w };
            if (res) {
                float2 q0 = *(const float2*)&res[(long)r0i*ldc + col];
                float2 q1 = *(const float2*)&res[(long)(r0i+8)*ldc + col];
                v0.x += q0.x; v0.y += q0.y; v1.x += q1.x; v1.y += q1.y;
            }
            if (outHf) {
                __half* Co = (__half*)Cp;
                __half2 h0 = __floats2half2_rn(v0.x, v0.y);
                __half2 h1 = __floats2half2_rn(v1.x, v1.y);
                *(__half2*)&Co[(long)r0i*ldc + col]     = h0;
                *(__half2*)&Co[(long)(r0i+8)*ldc + col] = h1;
            } else {
                float* Co = (float*)Cp;
                *(float2*)&Co[(long)r0i*ldc + col]     = v0;
                *(float2*)&Co[(long)(r0i+8)*ldc + col] = v1;
            }
        }
    }
}

// ---------------- RoPE: fp16 q,k -> fp16 qR [T][H], kT [NH][HD][T] ----------------
__global__ void rope_kernel() {
    int t = blockIdx.x, tid = threadIdx.x;
    __shared__ float cs[64], sn[64];
    if (tid < 64) {
        float inv = powf(10000.0f, -(float)tid / 64.0f);
        float fr = (float)t * inv;
        cs[tid] = cosf(fr); sn[tid] = sinf(fr);
    }
    __syncthreads();
    for (int idx = tid; idx < NH*64; idx += 256) {
        int hh = idx >> 6, j = idx & 63;
        long b = (long)t*H + hh*HD;
        float c = cs[j], s = sn[j];
        float q1 = __half2float(g_qH[b+j]), q2 = __half2float(g_qH[b+j+64]);
        g_qRH[b+j]    = __float2half(q1*c - q2*s);
        g_qRH[b+j+64] = __float2half(q2*c + q1*s);
        float k1 = __half2float(g_kH[b+j]), k2 = __half2float(g_kH[b+j+64]);
        g_kTH[((long)hh*HD + j)*T + t]      = __float2half(k1*c - k2*s);
        g_kTH[((long)hh*HD + j + 64)*T + t] = __float2half(k2*c + k1*s);
    }
}

// ------- causal softmax: fp32 scores -> fp16 probs (zero to 128-boundary) ------------
__global__ void attn_softmax() {
    int t = blockIdx.x, hh = blockIdx.y, tid = threadIdx.x;
    const float* row = g_scores + ((long)hh*T + t)*(long)T;
    __half* prow = g_probsH + ((long)hh*T + t)*(long)T;
    int len = t + 1;
    int zend = ((t >> 7) + 1) << 7;
    int base = tid * 4;
    float4 v = make_float4(0.f, 0.f, 0.f, 0.f);
    bool act = base < zend;
    if (act) v = *(const float4*)&row[base];

    float mx = -3.0e38f;
    if (base + 0 < len) mx = fmaxf(mx, v.x);
    if (base + 1 < len) mx = fmaxf(mx, v.y);
    if (base + 2 < len) mx = fmaxf(mx, v.z);
    if (base + 3 < len) mx = fmaxf(mx, v.w);
    #pragma unroll
    for (int o = 16; o > 0; o >>= 1) mx = fmaxf(mx, __shfl_xor_sync(~0u, mx, o));
    __shared__ float smx[8], ssm[8];
    int w = tid >> 5, l = tid & 31;
    if (l == 0) smx[w] = mx;
    __syncthreads();
    if (w == 0) {
        float m = (l < 8) ? smx[l] : -3.0e38f;
        #pragma unroll
        for (int o = 4; o > 0; o >>= 1) m = fmaxf(m, __shfl_xor_sync(~0u, m, o));
        if (l == 0) smx[0] = m;
    }
    __syncthreads();
    mx = smx[0];

    float e0 = (base + 0 < len) ? __expf(v.x - mx) : 0.f;
    float e1 = (base + 1 < len) ? __expf(v.y - mx) : 0.f;
    float e2 = (base + 2 < len) ? __expf(v.z - mx) : 0.f;
    float e3 = (base + 3 < len) ? __expf(v.w - mx) : 0.f;
    float s = (e0 + e1) + (e2 + e3);
    #pragma unroll
    for (int o = 16; o > 0; o >>= 1) s += __shfl_xor_sync(~0u, s, o);
    if (l == 0) ssm[w] = s;
    __syncthreads();
    if (w == 0) {
        float m = (l < 8) ? ssm[l] : 0.f;
        #pragma unroll
        for (int o = 4; o > 0; o >>= 1) m += __shfl_xor_sync(~0u, m, o);
        if (l == 0) ssm[0] = m;
    }
    __syncthreads();
    float inv = 1.0f / ssm[0];
    if (act) {
        __half2 p0 = __floats2half2_rn(e0 * inv, e1 * inv);
        __half2 p1 = __floats2half2_rn(e2 * inv, e3 * inv);
        *(__half2*)&prow[base]     = p0;
        *(__half2*)&prow[base + 2] = p1;
    }
}

// ------- expert transpose -> bf16 [e][k][n], vectorized ------------------------------
__global__ void __launch_bounds__(256) transpose_eb(const float* __restrict__ in,
                                                    unsigned* __restrict__ out,
                                                    int R, int C) {
    int r = blockIdx.y;
    int c0 = blockIdx.x * 32;
    __shared__ unsigned sm[16][68];
    int tid = threadIdx.x;
    {
        int cpair = tid >> 4;
        int e4 = (tid & 15) << 2;
        const float* basep = in + ((long)r*C + c0 + 2*cpair) * 64 + e4;
        float4 a = *(const float4*)basep;
        float4 b = *(const float4*)(basep + 64);
        __nv_bfloat162 t0 = __floats2bfloat162_rn(a.x, b.x);
        __nv_bfloat162 t1 = __floats2bfloat162_rn(a.y, b.y);
        __nv_bfloat162 t2 = __floats2bfloat162_rn(a.z, b.z);
        __nv_bfloat162 t3 = __floats2bfloat162_rn(a.w, b.w);
        uint4 u = { *(unsigned*)&t0, *(unsigned*)&t1, *(unsigned*)&t2, *(unsigned*)&t3 };
        *(uint4*)&sm[cpair][e4] = u;
    }
    __syncthreads();
    {
        int e = tid >> 2;
        int grp = (tid & 3) << 2;
        uint4 v;
        v.x = sm[grp+0][e];
        v.y = sm[grp+1][e];
        v.z = sm[grp+2][e];
        v.w = sm[grp+3][e];
        long C2 = C >> 1;
        *(uint4*)&out[(long)e*R*C2 + (long)r*C2 + (c0 >> 1) + grp] = v;
    }
}

// ---------------- router (parallel dot: 256 thr = 64 experts x 4 parts) ---------------
__global__ void zero_cnt_kernel() { if (threadIdx.x < NEXP) g_cnt[threadIdx.x] = 0; }

__global__ void __launch_bounds__(256) router_kernel(const float* __restrict__ gw) {
    int t = blockIdx.x, tid = threadIdx.x;
    int e = tid & 63, part = tid >> 6;
    const float* hr = g_h2u + (long)t*H;
    float s = 0.f;
    int h0 = part * 320;
    for (int h = h0; h < h0 + 320; h++) s += hr[h] * gw[h*NEXP + e];
    __shared__ float partial[4][NEXP];
    partial[part][e] = s;
    __syncthreads();
    __shared__ float probs[NEXP];
    if (tid < NEXP) {
        probs[tid] = ((partial[0][tid] + partial[1][tid]) + partial[2][tid]) + partial[3][tid];
    }
    __syncthreads();
    if (tid == 0) {
        float mx = -3e38f;
        for (int i = 0; i < NEXP; i++) mx = fmaxf(mx, probs[i]);
        float sum = 0.f;
        for (int i = 0; i < NEXP; i++) { probs[i] = __expf(probs[i]-mx); sum += probs[i]; }
        float inv = 1.f/sum;
        for (int i = 0; i < NEXP; i++) probs[i] *= inv;
        int ti[TOPK]; float tw[TOPK]; float ws = 0.f;
        for (int j = 0; j < TOPK; j++) {
            int bi = 0; float bv = -1.f;
            for (int i = 0; i < NEXP; i++) if (probs[i] > bv) { bv = probs[i]; bi = i; }
            ti[j] = bi; tw[j] = bv; ws += bv; probs[bi] = -2.f;
        }
        float wi = 1.f/ws;
        for (int j = 0; j < TOPK; j++) {
            g_tokE[t*TOPK+j] = ti[j];
            g_tokW[t*TOPK+j] = tw[j]*wi;
            atomicAdd(&g_cnt[ti[j]], 1);
        }
    }
}

__global__ void prefix_kernel() {
    if (threadIdx.x == 0) {
        int s = 0;
        for (int e = 0; e < NEXP; e++) { g_off[e] = s; g_cur[e] = s; s += g_cnt[e]; }
    }
}

__global__ void scatter_kernel() {
    int i = blockIdx.x*256 + threadIdx.x;
    if (i < NPAIR) {
        int e = g_tokE[i];
        int pos = atomicAdd(&g_cur[e], 1);
        g_pairTok[pos] = i / TOPK;
        g_pairW[pos]   = g_tokW[i];
        g_pairPos[i]   = pos;
    }
}

// -------- bf16 dual GEMM + SiLU (MoE pass1): CTA 128x128, 512 thr, warp 32x32, LDSM --
__global__ void __launch_bounds__(512)
gemm_bf16_dual(const __nv_bfloat16* __restrict__ A, int lda,
               const __nv_bfloat16* __restrict__ B1g, const __nv_bfloat16* __restrict__ B2g,
               long sB, int ldb,
               __nv_bfloat16* __restrict__ Cout, int ldc,
               int K) {
    int e = blockIdx.z;
    int m0 = blockIdx.y * 128;
    int cnt = g_cnt[e], base = g_off[e];
    if (m0 >= cnt) return;
    const __nv_bfloat16* B1 = B1g + (long)e*sB;
    const __nv_bfloat16* B2 = B2g + (long)e*sB;
    int n0 = blockIdx.x * 128;

    __shared__ int stok[128];
    __shared__ unsigned As[3][128][12];
    __shared__ unsigned Bs1[3][16][68];
    __shared__ unsigned Bs2[3][16][68];
    int tid = threadIdx.x;
    int lane = tid & 31, warpId = tid >> 5;
    int g = lane >> 2, tig = lane & 3;
    int warp_m = (warpId & 3) * 32, warp_n = (warpId >> 2) * 32;
    if (tid < 128) stok[tid] = (m0 + tid < cnt) ? g_pairTok[base + m0 + tid] : 0;
    __syncthreads();
    float4 accG[2][4], accU[2][4];
    #pragma unroll
    for (int i = 0; i < 2; i++)
        #pragma unroll
        for (int j = 0; j < 4; j++) { accG[i][j] = make_float4(0,0,0,0); accU[i][j] = make_float4(0,0,0,0); }

#define D_LOAD(sidx, k0v) do { int _k0 = (k0v); if (_k0 < K) { \
    if (tid < 256) { int r = tid >> 1, ch = tid & 1; \
      cp16(&As[sidx][r][ch*4], &A[(long)stok[r]*lda + _k0 + ch*8]); } \
    else { int t2 = tid - 256; int r = t2 >> 4, ch = t2 & 15; \
      cp16(&Bs1[sidx][r][ch*4], &B1[(long)(_k0+r)*ldb + n0 + ch*8]); \
      cp16(&Bs2[sidx][r][ch*4], &B2[(long)(_k0+r)*ldb + n0 + ch*8]); } \
    } CP_COMMIT; } while(0)

    const int nIter = K >> 4;
    D_LOAD(0, 0);
    D_LOAD(1, 16);
    int st = 0;
    int half16 = (lane >> 4) * 16;
    for (int it = 0; it < nIter; it++) {
        CP_WAIT1;
        __syncthreads();
        unsigned aBase = (unsigned)__cvta_generic_to_shared(&As[st][0][0]);
        unsigned b1Base = (unsigned)__cvta_generic_to_shared(&Bs1[st][0][0]);
        unsigned b2Base = (unsigned)__cvta_generic_to_shared(&Bs2[st][0][0]);
        unsigned a[2][4], b1[4][2], b2[4][2];
        #pragma unroll
        for (int mi = 0; mi < 2; mi++) {
            int row = warp_m + mi*16 + (lane & 15);
            ldsm4(a[mi][0], a[mi][1], a[mi][2], a[mi][3], aBase + row*48 + half16);
        }
        #pragma unroll
        for (int nh = 0; nh < 2; nh++) {
            int krow = lane & 15;
            int col = warp_n + nh*16 + (lane >> 4) * 8;
            ldsm4t(b1[nh*2][0], b1[nh*2][1], b1[nh*2+1][0], b1[nh*2+1][1],
                   b1Base + krow*272 + col*2);
            ldsm4t(b2[nh*2][0], b2[nh*2][1], b2[nh*2+1][0], b2[nh*2+1][1],
                   b2Base + krow*272 + col*2);
        }
        #pragma unroll
        for (int mi = 0; mi < 2; mi++)
            #pragma unroll
            for (int ni = 0; ni < 4; ni++) {
                mma_bf16(accG[mi][ni], a[mi], b1[ni]);
                mma_bf16(accU[mi][ni], a[mi], b2[ni]);
            }
        int wst = st + 2; if (wst >= 3) wst -= 3;
        D_LOAD(wst, (it + 2) << 4);
        if (++st == 3) st = 0;
    }
#undef D_LOAD
    #pragma unroll
    for (int mi = 0; mi < 2; mi++) {
        #pragma unroll
        for (int ni = 0; ni < 4; ni++) {
            int mrow = warp_m + mi*16 + g;
            int col = n0 + warp_n + ni*8 + 2*tig;
            float4 cg = accG[mi][ni], cu = accU[mi][ni];
            if (m0 + mrow < cnt) {
                float g0 = cg.x, g1 = cg.y;
                __nv_bfloat162 v = __floats2bfloat162_rn((g0/(1.f+__expf(-g0)))*cu.x,
                                                         (g1/(1.f+__expf(-g1)))*cu.y);
                *(__nv_bfloat162*)&Cout[(long)(base+m0+mrow)*ldc + col] = v;
            }
            if (m0 + mrow + 8 < cnt) {
                float g0 = cg.z, g1 = cg.w;
                __nv_bfloat162 v = __floats2bfloat162_rn((g0/(1.f+__expf(-g0)))*cu.z,
                                                         (g1/(1.f+__expf(-g1)))*cu.w);
                *(__nv_bfloat162*)&Cout[(long)(base+m0+mrow+8)*ldc + col] = v;
            }
        }
    }
}

// -------- bf16 single GEMM (MoE pass2): CTA 128x128, 256 thr, warp 64x32, LDSM -------
__global__ void __launch_bounds__(256)
gemm_bf16_one(const __nv_bfloat16* __restrict__ A, int lda,
              const __nv_bfloat16* __restrict__ Bg, long sB, int ldb,
              float* __restrict__ Cout, int ldc,
              int K) {
    int e = blockIdx.z;
    int m0 = blockIdx.y * 128;
    int cnt = g_cnt[e], base = g_off[e];
    if (m0 >= cnt) return;
    const __nv_bfloat16* B = Bg + (long)e*sB;
    int n0 = blockIdx.x * 128;

    __shared__ unsigned As[3][128][12];
    __shared__ unsigned Bs[3][16][68];
    int tid = threadIdx.x;
    int lane = tid & 31, warpId = tid >> 5;
    int g = lane >> 2, tig = lane & 3;
    int warp_m = (warpId & 1) * 64, warp_n = (warpId >> 1) * 32;
    float4 acc[4][4];
    #pragma unroll
    for (int i = 0; i < 4; i++)
        #pragma unroll
        for (int j = 0; j < 4; j++) acc[i][j] = make_float4(0,0,0,0);

#define S_LOAD(sidx, k0v) do { int _k0 = (k0v); if (_k0 < K) { \
    { int r = tid >> 1, ch = tid & 1; \
      int rr = m0 + r; if (rr >= cnt) rr = cnt - 1; \
      cp16(&As[sidx][r][ch*4], &A[(long)(base + rr)*lda + _k0 + ch*8]); } \
    { int r = tid >> 4, ch = tid & 15; \
      cp16(&Bs[sidx][r][ch*4], &B[(long)(_k0+r)*ldb + n0 + ch*8]); } \
    } CP_COMMIT; } while(0)

    const int nIter = K >> 4;
    S_LOAD(0, 0);
    S_LOAD(1, 16);
    int st = 0;
    int half16 = (lane >> 4) * 16;
    for (int it = 0; it < nIter; it++) {
        CP_WAIT1;
        __syncthreads();
        unsigned aBase = (unsigned)__cvta_generic_to_shared(&As[st][0][0]);
        unsigned bBase = (unsigned)__cvta_generic_to_shared(&Bs[st][0][0]);
        unsigned a[4][4], b[4][2];
        #pragma unroll
        for (int mi = 0; mi < 4; mi++) {
            int row = warp_m + mi*16 + (lane & 15);
            ldsm4(a[mi][0], a[mi][1], a[mi][2], a[mi][3], aBase + row*48 + half16);
        }
        #pragma unroll
        for (int nh = 0; nh < 2; nh++) {
            int krow = lane & 15;
            int col = warp_n + nh*16 + (lane >> 4) * 8;
            ldsm4t(b[nh*2][0], b[nh*2][1], b[nh*2+1][0], b[nh*2+1][1],
                   bBase + krow*272 + col*2);
        }
        #pragma unroll
        for (int mi = 0; mi < 4; mi++)
            #pragma unroll
            for (int ni = 0; ni < 4; ni++) mma_bf16(acc[mi][ni], a[mi], b[ni]);
        int wst = st + 2; if (wst >= 3) wst -= 3;
        S_LOAD(wst, (it + 2) << 4);
        if (++st == 3) st = 0;
    }
#undef S_LOAD
    #pragma unroll
    for (int mi = 0; mi < 4; mi++) {
        #pragma unroll
        for (int ni = 0; ni < 4; ni++) {
            int mrow = warp_m + mi*16 + g;
            int col = n0 + warp_n + ni*8 + 2*tig;
            float4 c = acc[mi][ni];
            if (m0 + mrow < cnt)
                *(float2*)&Cout[(long)(base+m0+mrow)*ldc + col] = make_float2(c.x, c.y);
            if (m0 + mrow + 8 < cnt)
                *(float2*)&Cout[(long)(base+m0+mrow+8)*ldc + col] = make_float2(c.z, c.w);
        }
    }
}

// ---------------- shared-FFN activation (vectorized, rounds output) ----------------
__global__ void silumul_kernel(float4* __restrict__ g, const float4* __restrict__ u, int n4) {
    int i = blockIdx.x*256 + threadIdx.x;
    if (i < n4) {
        float4 x = g[i];
        float4 y = u[i];
        x.x = rtf((x.x / (1.f + __expf(-x.x))) * y.x);
        x.y = rtf((x.y / (1.f + __expf(-x.y))) * y.y);
        x.z = rtf((x.z / (1.f + __expf(-x.z))) * y.z);
        x.w = rtf((x.w / (1.f + __expf(-x.w))) * y.w);
        g[i] = x;
    }
}

// ---------------- final combine (vectorized: 320 thr, float4) ----------------
__global__ void __launch_bounds__(320) combine_kernel(float* __restrict__ out) {
    int t = blockIdx.x;
    int pos[TOPK]; float w[TOPK];
    #pragma unroll
    for (int j = 0; j < TOPK; j++) {
        pos[j] = g_pairPos[t*TOPK + j];
        w[j]   = g_pairW[pos[j]];
    }
    int h = threadIdx.x * 4;
    float4 s  = *(const float4*)&g_hres[(long)t*H + h];
    float4 sh = *(const float4*)&g_shared[(long)t*H + h];
    s.x += sh.x; s.y += sh.y; s.z += sh.z; s.w += sh.w;
    #pragma unroll
    for (int j = 0; j < TOPK; j++) {
        float4 p = *(const float4*)&g_pairout[(long)pos[j]*H + h];
        s.x += w[j]*p.x; s.y += w[j]*p.y; s.z += w[j]*p.z; s.w += w[j]*p.w;
    }
    *(float4*)&out[(long)t*H + h] = s;
}

// ---------------- launch ----------------
extern "C" void kernel_launch(void* const* d_in, const int* in_sizes, int n_in,
                              void* d_out, int out_size) {
    (void)in_sizes; (void)n_in; (void)out_size;
    const float* x       = (const float*)d_in[0];
    const float* ln1     = (const float*)d_in[1];
    const float* ln2     = (const float*)d_in[2];
    const float* Wq      = (const float*)d_in[3];
    const float* Wk      = (const float*)d_in[4];
    const float* Wv      = (const float*)d_in[5];
    const float* Wo      = (const float*)d_in[6];
    const float* gate_w  = (const float*)d_in[7];
    const float* gpe     = (const float*)d_in[8];
    const float* upe     = (const float*)d_in[9];
    const float* dpe     = (const float*)d_in[10];
    const float* sh_gate = (const float*)d_in[11];
    const float* sh_up   = (const float*)d_in[12];
    const float* sh_down = (const float*)d_in[13];
    float* out = (float*)d_out;

    float *scoresp,*hresp,*h2p,*h2up,*sgp,*sup,*sharedp,*pairoutp;
    __half *h1Hp,*qHp,*kHp,*vHp,*qRHp,*kTHp,*probsHp,*attnHp,*wqh,*wkh,*wvh,*woh;
    __nv_bfloat16 *h2bp,*actBp,*gpeBp,*upeBp,*dpeBp;
    float *shgr,*shur,*shdr;
    cudaGetSymbolAddress((void**)&h1Hp,    g_h1H);
    cudaGetSymbolAddress((void**)&qHp,     g_qH);
    cudaGetSymbolAddress((void**)&kHp,     g_kH);
    cudaGetSymbolAddress((void**)&vHp,     g_vH);
    cudaGetSymbolAddress((void**)&qRHp,    g_qRH);
    cudaGetSymbolAddress((void**)&kTHp,    g_kTH);
    cudaGetSymbolAddress((void**)&scoresp, g_scores);
    cudaGetSymbolAddress((void**)&probsHp, g_probsH);
    cudaGetSymbolAddress((void**)&attnHp,  g_attnH);
    cudaGetSymbolAddress((void**)&hresp,   g_hres);
    cudaGetSymbolAddress((void**)&h2p,     g_h2);
    cudaGetSymbolAddress((void**)&h2up,    g_h2u);
    cudaGetSymbolAddress((void**)&h2bp,    g_h2b);
    cudaGetSymbolAddress((void**)&sgp,     g_sg);
    cudaGetSymbolAddress((void**)&sup,     g_su);
    cudaGetSymbolAddress((void**)&sharedp, g_shared);
    cudaGetSymbolAddress((void**)&actBp,   g_actB);
    cudaGetSymbolAddress((void**)&pairoutp,g_pairout);
    cudaGetSymbolAddress((void**)&gpeBp,   g_gpeB);
    cudaGetSymbolAddress((void**)&upeBp,   g_upeB);
    cudaGetSymbolAddress((void**)&dpeBp,   g_dpeB);
    cudaGetSymbolAddress((void**)&wqh,     g_WqH);
    cudaGetSymbolAddress((void**)&wkh,     g_WkH);
    cudaGetSymbolAddress((void**)&wvh,     g_WvH);
    cudaGetSymbolAddress((void**)&woh,     g_WoH);
    cudaGetSymbolAddress((void**)&shgr,    g_shgR);
    cudaGetSymbolAddress((void**)&shur,    g_shuR);
    cudaGetSymbolAddress((void**)&shdr,    g_shdR);

    const float inv_sqrt_hd = 0.08838834764831845f;

    // Exactly one side stream + six events (proven resource footprint).
    cudaStream_t s2;
    cudaStreamCreateWithFlags(&s2, cudaStreamNonBlocking);
    cudaEvent_t evFork, evH1, evV, evSide, evH2, evShared;
    cudaEventCreateWithFlags(&evFork,   cudaEventDisableTiming);
    cudaEventCreateWithFlags(&evH1,     cudaEventDisableTiming);
    cudaEventCreateWithFlags(&evV,      cudaEventDisableTiming);
    cudaEventCreateWithFlags(&evSide,   cudaEventDisableTiming);
    cudaEventCreateWithFlags(&evH2,     cudaEventDisableTiming);
    cudaEventCreateWithFlags(&evShared, cudaEventDisableTiming);

    cudaEventRecord(evFork, 0);
    cudaStreamWaitEvent(s2, evFork, 0);

    // s2: Wv/Wo conversion first
    conv_pair<<<dim3((H*NH*HD/4 + 255)/256, 2), 256, 0, s2>>>(
        (const float4*)Wv, (uint2*)wvh, (const float4*)Wo, (uint2*)woh);

    // main: Wq/Wk conversion + rms1 (fp16 out)
    conv_pair<<<dim3((H*NH*HD/4 + 255)/256, 2), 256>>>(
        (const float4*)Wq, (uint2*)wqh, (const float4*)Wk, (uint2*)wkh);
    rms_kernel<<<T, 256>>>(x, ln1, nullptr, nullptr, nullptr, h1Hp);
    cudaEventRecord(evH1, 0);

    // s2: Wv projection (fp16), transposes (evSide ASAP), shared-weight rounding
    cudaStreamWaitEvent(s2, evH1, 0);
    gemm_hf<<<dim3(H/64, T/128, 1), 128, 0, s2>>>(h1Hp, H, 0,
                                                  wvh, nullptr, nullptr, H, 0,
                                                  vHp, nullptr, nullptr, H, 0, 1,
                                                  nullptr, 1.f, H, 0);
    cudaEventRecord(evV, s2);   // also implies woh ready (s2 in-order)
    transpose_eb<<<dim3(EI/32, H), 256, 0, s2>>>(gpe, (unsigned*)gpeBp, H, EI);
    transpose_eb<<<dim3(EI/32, H), 256, 0, s2>>>(upe, (unsigned*)upeBp, H, EI);
    transpose_eb<<<dim3(H/32, EI), 256, 0, s2>>>(dpe, (unsigned*)dpeBp, EI, H);
    cudaEventRecord(evSide, s2);
    round_shared<<<dim3((H*SHF/4 + 255)/256, 3), 256, 0, s2>>>(
        (const float4*)sh_gate, (float4*)shgr, (const float4*)sh_up, (float4*)shur,
        (const float4*)sh_down, (float4*)shdr);

    // main: Q,K projections (fp16 fused z=2) + attention chain
    gemm_hf<<<dim3(H/64, T/128, 2), 128>>>(h1Hp, H, 0,
                                           wqh, wkh, nullptr, H, 0,
                                           qHp, kHp, nullptr, H, 0, 1,
                                           nullptr, 1.f, H, 0);
    rope_kernel<<<T, 256>>>();
    // scores: A=qR per head (sA=HD), B=kT per head (ldb=T, sB=HD*T), fp32 out, causal
    gemm_hf<<<dim3(T/64, T/128, NH), 128>>>(qRHp, H, HD,
                                            kTHp, nullptr, nullptr, T, (long)HD*T,
                                            scoresp, nullptr, nullptr, T, (long)T*T, 0,
                                            nullptr, inv_sqrt_hd, HD, 1);
    attn_softmax<<<dim3(T, NH), 256>>>();
    cudaStreamWaitEvent(0, evV, 0);   // v + woh ready
    // PV: A=probs per head (lda=T, sA=T*T), B=v (ldb=H, sB=HD), fp16 out, K capped
    gemm_hf<<<dim3(HD/64, T/128, NH), 128>>>(probsHp, T, (long)T*T,
                                             vHp, nullptr, nullptr, H, HD,
                                             attnHp, nullptr, nullptr, H, HD, 1,
                                             nullptr, 1.f, T, 2);
    // Wo: fp32 out + residual x
    gemm_hf<<<dim3(H/64, T/128, 1), 128>>>(attnHp, H, 0,
                                           woh, nullptr, nullptr, H, 0,
                                           hresp, nullptr, nullptr, H, 0, 0,
                                           x, 1.f, H, 0);

    // h2 (fp32-rounded + unrounded + bf16)
    rms_kernel<<<T, 256>>>(hresp, ln2, h2p, h2up, h2bp, nullptr);
    cudaEventRecord(evH2, 0);

    // s2: shared FFN (tf32) overlaps router + MoE on main
    cudaStreamWaitEvent(s2, evH2, 0);
    gemm_tc<<<dim3(SHF/64, T/64, 2), 128, 0, s2>>>(h2p, H, 0, shgr, shur, nullptr, SHF, 0, 0,
                                                   sgp, sup, nullptr, SHF, 0, nullptr, 0,
                                                   H, 1.f, 0, 0);
    silumul_kernel<<<(T*SHF/4 + 255)/256, 256, 0, s2>>>((float4*)sgp, (const float4*)sup, T*SHF/4);
    gemm_tc<<<dim3(H/64, T/64, 1), 128, 0, s2>>>(sgp, SHF, 0, shdr, nullptr, nullptr, H, 0, 0,
                                                 sharedp, nullptr, nullptr, H, 0, nullptr, 0,
                                                 SHF, 1.f, 0, 0);
    cudaEventRecord(evShared, s2);

    // main: router + MoE (bf16 LDSM, 128x128 tiles)
    zero_cnt_kernel<<<1, 64>>>();
    router_kernel<<<T, 256>>>(gate_w);
    prefix_kernel<<<1, 32>>>();
    scatter_kernel<<<(NPAIR + 255)/256, 256>>>();
    cudaStreamWaitEvent(0, evSide, 0);
    gemm_bf16_dual<<<dim3(EI/128, T/128, NEXP), 512>>>(
        h2bp, H, gpeBp, upeBp, (long)H*EI, EI, actBp, EI, H);
    gemm_bf16_one<<<dim3(H/128, T/128, NEXP), 256>>>(
        actBp, EI, dpeBp, (long)EI*H, H, pairoutp, H, EI);

    // join shared FFN, then combine
    cudaStreamWaitEvent(0, evShared, 0);
    combine_kernel<<<T, 320>>>(out);
}